// round 4
// baseline (speedup 1.0000x reference)
#include <cuda_runtime.h>
#include <cuda_bf16.h>
#include <math.h>
#include <stdint.h>

#define NV 24576
#define NC 98304
#define NE 294912
#define NL 49152              // 2*NV
#define INV_M (1.0f/12582912.0f)   // 1/(NC*128)

// ---------------- workspace layout (floats) ----------------
static constexpr size_t O_VARS   = 0;
static constexpr size_t O_CLS    = O_VARS  + (size_t)NV*128;
static constexpr size_t O_HV     = O_CLS   + (size_t)NC*128;   // NV x 256
static constexpr size_t O_HV2    = O_HV    + (size_t)NV*256;   // NV x 256
static constexpr size_t O_VQ     = O_HV2   + (size_t)NV*256;
static constexpr size_t O_HC     = O_VQ    + (size_t)NV*128;   // NC x 256
static constexpr size_t O_CQ     = O_HC    + (size_t)NC*256;
static constexpr size_t O_CGRAD  = O_CQ    + (size_t)NC*128;
static constexpr size_t O_LOSS   = O_CGRAD + (size_t)NC*128;
static constexpr size_t O_CDATA  = O_LOSS  + (size_t)NC*128;   // NC x 256
static constexpr size_t O_DLITS  = O_CDATA + (size_t)NC*256;   // NL x 128
static constexpr size_t O_VL     = O_DLITS + (size_t)NL*128;   // NL x 128
static constexpr size_t O_VOUT   = O_VL    + (size_t)NL*128;   // NV x 128
static constexpr size_t O_DEGW   = O_VOUT  + (size_t)NV*128;   // NL
static constexpr size_t O_VDEGW  = O_DEGW  + NL;               // NV
static constexpr size_t O_STAT   = O_VDEGW + NV;               // 128 sum, 128 ssq, 1 scale
static constexpr size_t O_WT     = O_STAT  + 260;              // bf16 split weights
static constexpr size_t WS_TOTAL = O_WT + 480000;

// weight offsets in HALVES within each hi/lo bf16 array ([N][KP] row-major)
static constexpr size_t WH_TOTAL = 477184;
static constexpr size_t OW_vq0 = 0;       // N=128, K=132, KP=136
static constexpr size_t OW_vq1 = 17408;   // 128,128,128
static constexpr size_t OW_cq0 = 33792;   // 128,132,136
static constexpr size_t OW_cq1 = 51200;   // 128,128,128
static constexpr size_t OW_cm0 = 67584;   // 256,384,384
static constexpr size_t OW_cm1 = 165888;  // 256,256,256
static constexpr size_t OW_ug0 = 231424;  // 256,512,512
static constexpr size_t OW_ug1 = 362496;  // 256,256,256
static constexpr size_t OW_ug2 = 428032;  // 128,256,256
static constexpr size_t OW_co0 = 460800;  // 128,128,128

__device__ float g_ws[WS_TOTAL];
__device__ int   g_deg[NL];

// ---------------- PTX helpers ----------------
__device__ __forceinline__ uint32_t smem_u32(const void* p){
    uint32_t a;
    asm("{ .reg .u64 t; cvta.to.shared.u64 t, %1; cvt.u32.u64 %0, t; }" : "=r"(a) : "l"(p));
    return a;
}
__device__ __forceinline__ void ldsm4(uint32_t* r, uint32_t addr){
    asm volatile("ldmatrix.sync.aligned.m8n8.x4.shared.b16 {%0,%1,%2,%3}, [%4];"
        : "=r"(r[0]), "=r"(r[1]), "=r"(r[2]), "=r"(r[3]) : "r"(addr));
}
__device__ __forceinline__ void mma_bf16(float* c, const uint32_t* a, const uint32_t* b){
    asm volatile("mma.sync.aligned.m16n8k16.row.col.f32.bf16.bf16.f32 "
        "{%0,%1,%2,%3}, {%4,%5,%6,%7}, {%8,%9}, {%0,%1,%2,%3};"
        : "+f"(c[0]), "+f"(c[1]), "+f"(c[2]), "+f"(c[3])
        : "r"(a[0]), "r"(a[1]), "r"(a[2]), "r"(a[3]), "r"(b[0]), "r"(b[1]));
}
__device__ __forceinline__ uint32_t pack_bf16x2(float lo, float hi){
    uint32_t r;
    asm("cvt.rn.bf16x2.f32 %0, %1, %2;" : "=r"(r) : "f"(hi), "f"(lo));
    return r;
}
__device__ __forceinline__ float sigm(float x){ return 1.f/(1.f+expf(-x)); }
__device__ __forceinline__ float softplusf(float x){ return fmaxf(x,0.f)+log1pf(expf(-fabsf(x))); }

// A-loader modes
#define M_PLAIN 0
#define M_CAT4  1
#define M_CMIN  2
#define M_UNIT  3

struct GArgs {
    const float* p0; const float* p1; const float* p2;
    const float* p3; const float* p4; const float* p5;
};

// ---------------- bf16-split MMA GEMM with fused loaders/epilogues ----------------
template<int MODE, int EPI>
__global__ void __launch_bounds__(256, 1)
k_mma(GArgs ga, const __nv_bfloat16* __restrict__ Bhg,
      const __nv_bfloat16* __restrict__ Blg, const float* __restrict__ bias,
      float* __restrict__ C, int K, int KP, int Ntot, int relu,
      float* __restrict__ out, int round,
      const float* __restrict__ w1, const float* __restrict__ b1)
{
    extern __shared__ __align__(16) char smem[];
    const uint32_t sbase = smem_u32(smem);
    const int t = threadIdx.x;
    const int lane = t & 31, wid = t >> 5;
    const int warp_m = wid & 1, warp_n = wid >> 1;
    const int bm = blockIdx.y * 128;
    const int bn = blockIdx.x * 128;

    constexpr int LDH = 40;
    constexpr int AH_OFF = 0;
    constexpr int AL_OFF = 128*LDH;
    constexpr int BH_OFF = 2*128*LDH;
    constexpr int BL_OFF = 3*128*LDH;
    constexpr int STAGE_B = 4*128*LDH*2;

    float acc[4][4][4];
    #pragma unroll
    for (int i=0;i<4;i++)
        #pragma unroll
        for(int j=0;j<4;j++)
            #pragma unroll
            for(int q=0;q<4;q++) acc[i][j][q]=0.f;

    const int nch = (K + 31) >> 5;
    float4 aReg[4];
    uint4  bhReg[2], blReg[2];

    auto loadA = [&](int c){
        const int k0 = c << 5;
        #pragma unroll
        for (int i = 0; i < 4; i++) {
            int idx = t + i*256;
            int row = idx >> 3, col4 = (idx & 7) << 2;
            int gk = k0 + col4;
            int r = bm + row;
            float4 v = make_float4(0.f,0.f,0.f,0.f);
            if (MODE == M_PLAIN) {
                if (gk < K) v = *reinterpret_cast<const float4*>(&ga.p0[(size_t)r*K + gk]);
            } else if (MODE == M_CAT4) {
                if (gk < 128)      v = *reinterpret_cast<const float4*>(&ga.p0[(size_t)r*128 + gk]);
                else if (gk == 128) v = *reinterpret_cast<const float4*>(&ga.p1[(size_t)r*4]);
            } else if (MODE == M_CMIN) {
                int seg = gk >> 7, cc = gk & 127;
                if (seg == 0)      v = *reinterpret_cast<const float4*>(&ga.p0[(size_t)r*128 + cc]);
                else if (seg == 1) {
                    v = *reinterpret_cast<const float4*>(&ga.p1[(size_t)r*128 + cc]);
                    v.x*=4.f; v.y*=4.f; v.z*=4.f; v.w*=4.f;
                } else             v = *reinterpret_cast<const float4*>(&ga.p2[(size_t)r*128 + cc]);
            } else { // M_UNIT: p0=VQ p1=DLITS p2=VARS p3=VL p4=DEGW p5=VDEGW
                int seg = gk >> 7, cc = gk & 127;
                if (seg == 0) {
                    float4 vq = *reinterpret_cast<const float4*>(&ga.p0[(size_t)r*128 + cc]);
                    float4 dp = *reinterpret_cast<const float4*>(&ga.p1[(size_t)r*128 + cc]);
                    float4 dn = *reinterpret_cast<const float4*>(&ga.p1[(size_t)(r+NV)*128 + cc]);
                    float w = ga.p5[r];
                    float sp;
                    sp = sigm(vq.x); v.x = -INV_M*(dp.x*sp - dn.x*(1.f-sp))*w;
                    sp = sigm(vq.y); v.y = -INV_M*(dp.y*sp - dn.y*(1.f-sp))*w;
                    sp = sigm(vq.z); v.z = -INV_M*(dp.z*sp - dn.z*(1.f-sp))*w;
                    sp = sigm(vq.w); v.w = -INV_M*(dp.w*sp - dn.w*(1.f-sp))*w;
                } else if (seg == 1) {
                    v = *reinterpret_cast<const float4*>(&ga.p2[(size_t)r*128 + cc]);
                } else if (seg == 2) {
                    v = *reinterpret_cast<const float4*>(&ga.p3[(size_t)r*128 + cc]);
                    float w = ga.p4[r];
                    v.x*=w; v.y*=w; v.z*=w; v.w*=w;
                } else {
                    v = *reinterpret_cast<const float4*>(&ga.p3[(size_t)(r+NV)*128 + cc]);
                    float w = ga.p4[r+NV];
                    v.x*=w; v.y*=w; v.z*=w; v.w*=w;
                }
            }
            aReg[i] = v;
        }
    };
    auto loadB = [&](int c){
        const int k0 = c << 5;
        #pragma unroll
        for (int i = 0; i < 2; i++) {
            int idx = t + i*256;
            int row = idx >> 2, q = idx & 3;
            int gk = k0 + q*8;
            if (gk + 8 <= KP) {
                size_t off = (size_t)(bn+row)*KP + gk;
                bhReg[i] = *reinterpret_cast<const uint4*>(&Bhg[off]);
                blReg[i] = *reinterpret_cast<const uint4*>(&Blg[off]);
            } else {
                bhReg[i] = make_uint4(0,0,0,0);
                blReg[i] = make_uint4(0,0,0,0);
            }
        }
    };
    auto storeStage = [&](int buf){
        char* sc = smem + buf*STAGE_B;
        #pragma unroll
        for (int i = 0; i < 4; i++) {
            int idx = t + i*256;
            int row = idx >> 3, col4 = (idx & 7) << 2;
            uint32_t h0 = pack_bf16x2(aReg[i].x, aReg[i].y);
            uint32_t h1 = pack_bf16x2(aReg[i].z, aReg[i].w);
            float hx = __uint_as_float(h0 << 16);
            float hy = __uint_as_float(h0 & 0xffff0000u);
            float hz = __uint_as_float(h1 << 16);
            float hw = __uint_as_float(h1 & 0xffff0000u);
            uint32_t l0 = pack_bf16x2(aReg[i].x - hx, aReg[i].y - hy);
            uint32_t l1 = pack_bf16x2(aReg[i].z - hz, aReg[i].w - hw);
            int boff = (row*LDH + col4)*2;
            *reinterpret_cast<uint2*>(sc + AH_OFF*2 + boff) = make_uint2(h0,h1);
            *reinterpret_cast<uint2*>(sc + AL_OFF*2 + boff) = make_uint2(l0,l1);
        }
        #pragma unroll
        for (int i = 0; i < 2; i++) {
            int idx = t + i*256;
            int row = idx >> 2, q = idx & 3;
            int boff = (row*LDH + q*8)*2;
            *reinterpret_cast<uint4*>(sc + BH_OFF*2 + boff) = bhReg[i];
            *reinterpret_cast<uint4*>(sc + BL_OFF*2 + boff) = blReg[i];
        }
    };
    auto compute = [&](int buf){
        const uint32_t sb = sbase + buf*STAGE_B;
        const int grp = lane >> 3, r = lane & 7;
        #pragma unroll
        for (int ks = 0; ks < 32; ks += 16) {
            uint32_t aH[4][4], aL[4][4], bH[4][2], bL[4][2];
            #pragma unroll
            for (int mt = 0; mt < 4; mt++) {
                int arow = warp_m*64 + mt*16 + (grp & 1)*8 + r;
                int acol = ks + (grp >> 1)*8;
                uint32_t adr = sb + (uint32_t)(arow*LDH + acol)*2;
                ldsm4(aH[mt], adr + AH_OFF*2);
                ldsm4(aL[mt], adr + AL_OFF*2);
            }
            #pragma unroll
            for (int p = 0; p < 2; p++) {
                int brow = warp_n*32 + p*16 + (grp >> 1)*8 + r;
                int bcol = ks + (grp & 1)*8;
                uint32_t adr = sb + (uint32_t)(brow*LDH + bcol)*2;
                uint32_t tmp[4];
                ldsm4(tmp, adr + BH_OFF*2);
                bH[2*p][0]=tmp[0]; bH[2*p][1]=tmp[1]; bH[2*p+1][0]=tmp[2]; bH[2*p+1][1]=tmp[3];
                ldsm4(tmp, adr + BL_OFF*2);
                bL[2*p][0]=tmp[0]; bL[2*p][1]=tmp[1]; bL[2*p+1][0]=tmp[2]; bL[2*p+1][1]=tmp[3];
            }
            #pragma unroll
            for (int mt = 0; mt < 4; mt++)
                #pragma unroll
                for (int nt = 0; nt < 4; nt++) {
                    mma_bf16(acc[mt][nt], aH[mt], bH[nt]);
                    mma_bf16(acc[mt][nt], aH[mt], bL[nt]);
                    mma_bf16(acc[mt][nt], aL[mt], bH[nt]);
                }
        }
    };

    loadA(0); loadB(0);
    storeStage(0);
    __syncthreads();
    for (int c = 0; c < nch; c++) {
        if (c+1 < nch) { loadA(c+1); loadB(c+1); }
        compute(c & 1);
        __syncthreads();
        if (c+1 < nch) { storeStage((c+1)&1); __syncthreads(); }
    }

    if (EPI == 0) {
        #pragma unroll
        for (int mt = 0; mt < 4; mt++) {
            int row0 = bm + warp_m*64 + mt*16 + (lane >> 2);
            #pragma unroll
            for (int nt = 0; nt < 4; nt++) {
                int col = bn + warp_n*32 + nt*8 + (lane & 3)*2;
                float2 bv = *reinterpret_cast<const float2*>(&bias[col]);
                float v0 = acc[mt][nt][0] + bv.x, v1 = acc[mt][nt][1] + bv.y;
                float v2 = acc[mt][nt][2] + bv.x, v3 = acc[mt][nt][3] + bv.y;
                if (relu) { v0=fmaxf(v0,0.f); v1=fmaxf(v1,0.f); v2=fmaxf(v2,0.f); v3=fmaxf(v3,0.f); }
                *reinterpret_cast<float2*>(&C[(size_t)row0*Ntot + col])     = make_float2(v0,v1);
                *reinterpret_cast<float2*>(&C[(size_t)(row0+8)*Ntot + col]) = make_float2(v2,v3);
            }
        }
    } else {
        // fused logits head: x[row] = relu(H[row]) . w1 + b1 -> sigmoid/softplus
        float* red = reinterpret_cast<float*>(smem);
        if (t < 128) red[t] = 0.f;
        __syncthreads();
        #pragma unroll
        for (int mt = 0; mt < 4; mt++) {
            int rl = warp_m*64 + mt*16 + (lane >> 2);
            float p0 = 0.f, p1 = 0.f;
            #pragma unroll
            for (int nt = 0; nt < 4; nt++) {
                int col = warp_n*32 + nt*8 + (lane & 3)*2;
                float2 bv = *reinterpret_cast<const float2*>(&bias[col]);
                float wa = __ldg(&w1[col]), wb = __ldg(&w1[col+1]);
                float v0 = fmaxf(acc[mt][nt][0] + bv.x, 0.f);
                float v1 = fmaxf(acc[mt][nt][1] + bv.y, 0.f);
                float v2 = fmaxf(acc[mt][nt][2] + bv.x, 0.f);
                float v3 = fmaxf(acc[mt][nt][3] + bv.y, 0.f);
                p0 += v0*wa + v1*wb;
                p1 += v2*wa + v3*wb;
            }
            atomicAdd(&red[rl], p0);
            atomicAdd(&red[rl+8], p1);
        }
        __syncthreads();
        if (t < 128) {
            float x = red[t] + __ldg(&b1[0]);
            int row = bm + t;
            out[(size_t)round*NC + row] = sigm(x);
            out[(size_t)4*NC + (size_t)round*NC + row] = softplusf(x);
        }
    }
}

// weight transpose + bf16 split: W[K,N] -> hi/lo [N,KP] bf16 (pad zero-filled)
__global__ void k_wsplit(const float* __restrict__ W, __nv_bfloat16* __restrict__ hi,
                         __nv_bfloat16* __restrict__ lo, int K, int N, int KP){
    int idx = blockIdx.x*blockDim.x + threadIdx.x;
    if (idx >= N*KP) return;
    int n = idx / KP, k = idx % KP;
    float v = (k < K) ? W[(size_t)k*N + n] : 0.f;
    __nv_bfloat16 h = __float2bfloat16(v);
    hi[idx] = h;
    lo[idx] = __float2bfloat16(v - __bfloat162float(h));
}

// ---------------- misc kernels ----------------
__global__ void k_zero(float* p, size_t n){
    size_t i = (size_t)blockIdx.x*blockDim.x + threadIdx.x;
    if (i < n) p[i] = 0.f;
}
__global__ void k_fill1(float* p, size_t n){
    size_t i = (size_t)blockIdx.x*blockDim.x + threadIdx.x;
    if (i < n) p[i] = 1.f;
}
__global__ void k_zero_int(int* p, int n){
    int i = blockIdx.x*blockDim.x + threadIdx.x;
    if (i < n) p[i] = 0;
}
__global__ void k_count(const int* __restrict__ lit){
    int e = blockIdx.x*blockDim.x + threadIdx.x;
    if (e < NE) atomicAdd(&g_deg[lit[e]], 1);
}
__global__ void k_weights(){
    int l = blockIdx.x*blockDim.x + threadIdx.x;
    if (l < NL) g_ws[O_DEGW + l] = rsqrtf(fmaxf((float)g_deg[l], 1.f));
    if (l < NV) g_ws[O_VDEGW + l] = 4.f*rsqrtf(fmaxf((float)(g_deg[l] + g_deg[l+NV]), 1.f));
}

// fused: csum (sorted-clause gather) + loss + cgrad
__global__ void k_csum_loss(const int* __restrict__ lit, const int* __restrict__ cls){
    const int c = blockIdx.x, f = threadIdx.x;
    __shared__ int se[2];
    if (f < 2) {
        int key = c + f;
        int lo = 0, hi = NE;
        while (lo < hi) { int mid = (lo+hi) >> 1; if (cls[mid] < key) lo = mid+1; else hi = mid; }
        se[f] = lo;
    }
    __syncthreads();
    float csum = 0.f;
    for (int e = se[0]; e < se[1]; e++) {
        int l = lit[e];
        float z = (l < NV) ? g_ws[O_VQ + (size_t)l*128 + f]
                           : -g_ws[O_VQ + (size_t)(l-NV)*128 + f];
        csum += softplusf(z);
    }
    size_t i = (size_t)c*128 + f;
    float s = sigm(g_ws[O_CQ + i]);
    float l = expf(-csum) * s;
    g_ws[O_LOSS + i]  = l;
    g_ws[O_CGRAD + i] = l * (1.f - s) * INV_M;
}

// dst[sidx[e]] += src[gidx[e]] (src row stride given; dst stride 128)
__global__ void k_scatter(const float* __restrict__ src, int sstride,
                          const int* __restrict__ gidx, const int* __restrict__ sidx,
                          float* __restrict__ dst){
    int e = blockIdx.x, f = threadIdx.x;
    atomicAdd(&dst[(size_t)sidx[e]*128 + f], src[(size_t)gidx[e]*sstride + f]);
}

// ---------------- pair_norm ----------------
__global__ void k_pn_stats(const float* __restrict__ x, int stride, int off, int n){
    int f = threadIdx.x;
    float s = 0.f, q = 0.f;
    for (int r = blockIdx.x; r < n; r += gridDim.x) {
        float v = x[(size_t)r*stride + off + f];
        s += v; q += v*v;
    }
    atomicAdd(&g_ws[O_STAT + f], s);
    atomicAdd(&g_ws[O_STAT + 128 + f], q);
}
__global__ void k_pn_scale(float n){
    int f = threadIdx.x;
    float mean = g_ws[O_STAT + f] / n;
    float var  = g_ws[O_STAT + 128 + f] / n - mean*mean;
    __shared__ float sh[128];
    sh[f] = var; __syncthreads();
    for (int s = 64; s > 0; s >>= 1) { if (f < s) sh[f] += sh[f+s]; __syncthreads(); }
    g_ws[O_STAT + f] = mean;
    if (f == 0) g_ws[O_STAT + 256] = rsqrtf(sh[0]*(1.f/128.f) + 1e-6f);
}
__global__ void k_pn_apply(const float* __restrict__ x, int stride, int off,
                           float* __restrict__ dst){
    int r = blockIdx.x, f = threadIdx.x;
    float scale = g_ws[O_STAT + 256];
    float v = (x[(size_t)r*stride + off + f] - g_ws[O_STAT + f]) * scale;
    size_t i = (size_t)r*128 + f;
    dst[i] = v*0.25f + 0.1f*dst[i];
}

// ---------------- host ----------------
static constexpr int GEMM_SMEM = 81920;

template<int MODE, int EPI>
static void mmgemm(GArgs ga, const __nv_bfloat16* Bh, const __nv_bfloat16* Bl,
                   const float* bias, float* C, int M, int K, int KP, int Ntot, int relu,
                   float* out = nullptr, int round = 0,
                   const float* w1 = nullptr, const float* b1 = nullptr){
    cudaFuncSetAttribute(k_mma<MODE,EPI>, cudaFuncAttributeMaxDynamicSharedMemorySize, GEMM_SMEM);
    dim3 grid(Ntot/128, M/128);
    k_mma<MODE,EPI><<<grid, 256, GEMM_SMEM>>>(ga, Bh, Bl, bias, C, K, KP, Ntot, relu,
                                              out, round, w1, b1);
}

extern "C" void kernel_launch(void* const* d_in, const int* in_sizes, int n_in,
                              void* d_out, int out_size)
{
    (void)in_sizes; (void)n_in; (void)out_size;
    const int*   edge_lit    = (const int*)d_in[0];
    const int*   edge_clause = (const int*)d_in[1];
    const float* noise_v = (const float*)d_in[2];
    const float* noise_c = (const float*)d_in[3];
    const float* vq_w0 = (const float*)d_in[4];  const float* vq_b0 = (const float*)d_in[5];
    const float* vq_w1 = (const float*)d_in[6];  const float* vq_b1 = (const float*)d_in[7];
    const float* cq_w0 = (const float*)d_in[8];  const float* cq_b0 = (const float*)d_in[9];
    const float* cq_w1 = (const float*)d_in[10]; const float* cq_b1 = (const float*)d_in[11];
    const float* cm_w0 = (const float*)d_in[12]; const float* cm_b0 = (const float*)d_in[13];
    const float* cm_w1 = (const float*)d_in[14]; const float* cm_b1 = (const float*)d_in[15];
    const float* ug_w0 = (const float*)d_in[16]; const float* ug_b0 = (const float*)d_in[17];
    const float* ug_w1 = (const float*)d_in[18]; const float* ug_b1 = (const float*)d_in[19];
    const float* ug_w2 = (const float*)d_in[20]; const float* ug_b2 = (const float*)d_in[21];
    const float* co_w0 = (const float*)d_in[22]; const float* co_b0 = (const float*)d_in[23];
    const float* co_w1 = (const float*)d_in[24]; const float* co_b1 = (const float*)d_in[25];
    float* out = (float*)d_out;

    float* ws; cudaGetSymbolAddress((void**)&ws, g_ws);
    int* deg;  cudaGetSymbolAddress((void**)&deg, g_deg);
    __nv_bfloat16* wh = reinterpret_cast<__nv_bfloat16*>(ws + O_WT);
    __nv_bfloat16* wl = wh + WH_TOTAL;

    // ---- setup ----
    k_zero_int<<<(NL+255)/256, 256>>>(deg, NL);
    k_count<<<(NE+255)/256, 256>>>(edge_lit);
    k_weights<<<(NL+255)/256, 256>>>();
    {
        size_t n = (size_t)NV*128;
        k_fill1<<<(unsigned)((n+255)/256), 256>>>(ws + O_VARS, n);
        n = (size_t)NC*128;
        k_fill1<<<(unsigned)((n+255)/256), 256>>>(ws + O_CLS, n);
    }
    #define WSPLIT(src, off, K, N, KP) \
        k_wsplit<<<((N)*(KP)+255)/256, 256>>>(src, wh + (off), wl + (off), K, N, KP)
    WSPLIT(vq_w0, OW_vq0, 132, 128, 136);
    WSPLIT(vq_w1, OW_vq1, 128, 128, 128);
    WSPLIT(cq_w0, OW_cq0, 132, 128, 136);
    WSPLIT(cq_w1, OW_cq1, 128, 128, 128);
    WSPLIT(cm_w0, OW_cm0, 384, 256, 384);
    WSPLIT(cm_w1, OW_cm1, 256, 256, 256);
    WSPLIT(ug_w0, OW_ug0, 512, 256, 512);
    WSPLIT(ug_w1, OW_ug1, 256, 256, 256);
    WSPLIT(ug_w2, OW_ug2, 256, 128, 256);
    WSPLIT(co_w0, OW_co0, 128, 128, 128);
    #undef WSPLIT

    for (int r = 0; r < 4; r++) {
        const float* nv_r = noise_v + (size_t)r*NV*4;
        const float* nc_r = noise_c + (size_t)r*NC*4;
        GArgs ga{};

        // vq = mlp2([vars|noise_v]); cq = mlp2([cls|noise_c])   (concat fused)
        ga = {ws+O_VARS, nv_r, 0, 0, 0, 0};
        mmgemm<M_CAT4,0>(ga, wh+OW_vq0, wl+OW_vq0, vq_b0, ws+O_HV, NV, 132, 136, 128, 1);
        ga = {ws+O_HV, 0, 0, 0, 0, 0};
        mmgemm<M_PLAIN,0>(ga, wh+OW_vq1, wl+OW_vq1, vq_b1, ws+O_VQ, NV, 128, 128, 128, 0);
        ga = {ws+O_CLS, nc_r, 0, 0, 0, 0};
        mmgemm<M_CAT4,0>(ga, wh+OW_cq0, wl+OW_cq0, cq_b0, ws+O_HC, NC, 132, 136, 128, 1);
        ga = {ws+O_HC, 0, 0, 0, 0, 0};
        mmgemm<M_PLAIN,0>(ga, wh+OW_cq1, wl+OW_cq1, cq_b1, ws+O_CQ, NC, 128, 128, 128, 0);

        // csum gather (sorted edge_clause) + loss + cgrad, fused, no atomics
        k_csum_loss<<<NC, 128>>>(edge_lit, edge_clause);

        // dlits = segsum(loss[edge_clause] by edge_lit)
        {
            size_t n = (size_t)NL*128;
            k_zero<<<(unsigned)((n+255)/256), 256>>>(ws+O_DLITS, n);
        }
        k_scatter<<<NE, 128>>>(ws+O_LOSS, 128, edge_clause, edge_lit, ws+O_DLITS);

        // clause message MLP (CMIN build fused into A-loader)
        ga = {ws+O_CLS, ws+O_LOSS, ws+O_CGRAD, 0, 0, 0};
        mmgemm<M_CMIN,0>(ga, wh+OW_cm0, wl+OW_cm0, cm_b0, ws+O_HC, NC, 384, 384, 256, 1);
        ga = {ws+O_HC, 0, 0, 0, 0, 0};
        mmgemm<M_PLAIN,0>(ga, wh+OW_cm1, wl+OW_cm1, cm_b1, ws+O_CDATA, NC, 256, 256, 256, 0);

        // variables_loss scatter
        {
            size_t n = (size_t)NL*128;
            k_zero<<<(unsigned)((n+255)/256), 256>>>(ws+O_VL, n);
        }
        k_scatter<<<NE, 128>>>(ws+O_CDATA, 256, edge_clause, edge_lit, ws+O_VL);

        // clauses = pair_norm(cdata[:,128:])*0.25 + 0.1*clauses
        k_zero<<<2, 256>>>(ws+O_STAT, 257);
        k_pn_stats<<<512, 128>>>(ws+O_CDATA, 256, 128, NC);
        k_pn_scale<<<1, 128>>>((float)NC);
        k_pn_apply<<<NC, 128>>>(ws+O_CDATA, 256, 128, ws+O_CLS);

        // variable update MLP3 (UNIT build fused into A-loader)
        ga = {ws+O_VQ, ws+O_DLITS, ws+O_VARS, ws+O_VL, ws+O_DEGW, ws+O_VDEGW};
        mmgemm<M_UNIT,0>(ga, wh+OW_ug0, wl+OW_ug0, ug_b0, ws+O_HV, NV, 512, 512, 256, 1);
        ga = {ws+O_HV, 0, 0, 0, 0, 0};
        mmgemm<M_PLAIN,0>(ga, wh+OW_ug1, wl+OW_ug1, ug_b1, ws+O_HV2, NV, 256, 256, 256, 1);
        ga = {ws+O_HV2, 0, 0, 0, 0, 0};
        mmgemm<M_PLAIN,0>(ga, wh+OW_ug2, wl+OW_ug2, ug_b2, ws+O_VOUT, NV, 256, 256, 128, 0);

        k_zero<<<2, 256>>>(ws+O_STAT, 257);
        k_pn_stats<<<512, 128>>>(ws+O_VOUT, 128, 0, NV);
        k_pn_scale<<<1, 128>>>((float)NV);
        k_pn_apply<<<NV, 128>>>(ws+O_VOUT, 128, 0, ws+O_VARS);

        // output head: co0 GEMM with fused logits epilogue (H never stored)
        ga = {ws+O_CLS, 0, 0, 0, 0, 0};
        mmgemm<M_PLAIN,1>(ga, wh+OW_co0, wl+OW_co0, co_b0, nullptr, NC, 128, 128, 128, 1,
                          out, r, co_w1, co_b1);
    }
}

// round 6
// speedup vs baseline: 1.0080x; 1.0080x over previous
#include <cuda_runtime.h>
#include <cuda_bf16.h>
#include <math.h>
#include <stdint.h>

#define NV 24576
#define NC 98304
#define NE 294912
#define NL 49152              // 2*NV
#define INV_M (1.0f/12582912.0f)   // 1/(NC*128)

// ---------------- workspace layout (floats) ----------------
static constexpr size_t O_VARS   = 0;
static constexpr size_t O_CLS    = O_VARS  + (size_t)NV*128;
static constexpr size_t O_HV     = O_CLS   + (size_t)NC*128;   // NV x 256
static constexpr size_t O_HV2    = O_HV    + (size_t)NV*256;   // NV x 256
static constexpr size_t O_VQ     = O_HV2   + (size_t)NV*256;
static constexpr size_t O_HC     = O_VQ    + (size_t)NV*128;   // NC x 256
static constexpr size_t O_CQ     = O_HC    + (size_t)NC*256;
static constexpr size_t O_CGRAD  = O_CQ    + (size_t)NC*128;
static constexpr size_t O_LOSS   = O_CGRAD + (size_t)NC*128;
static constexpr size_t O_CDATA  = O_LOSS  + (size_t)NC*128;   // NC x 256
static constexpr size_t O_DLITS  = O_CDATA + (size_t)NC*256;   // NL x 128
static constexpr size_t O_VL     = O_DLITS + (size_t)NL*128;   // NL x 128
static constexpr size_t O_VOUT   = O_VL    + (size_t)NL*128;   // NV x 128
static constexpr size_t O_DEGW   = O_VOUT  + (size_t)NV*128;   // NL
static constexpr size_t O_VDEGW  = O_DEGW  + NL;               // NV
static constexpr size_t O_STAT   = O_VDEGW + NV;               // 128 sum, 128 ssq, 1 scale
static constexpr size_t O_WT     = O_STAT  + 260;              // bf16 split weights
static constexpr size_t WS_TOTAL = O_WT + 480000;

// weight offsets in HALVES within each hi/lo bf16 array ([N][KP] row-major)
static constexpr size_t WH_TOTAL = 477184;
static constexpr size_t OW_vq0 = 0;
static constexpr size_t OW_vq1 = 17408;
static constexpr size_t OW_cq0 = 33792;
static constexpr size_t OW_cq1 = 51200;
static constexpr size_t OW_cm0 = 67584;
static constexpr size_t OW_cm1 = 165888;
static constexpr size_t OW_ug0 = 231424;
static constexpr size_t OW_ug1 = 362496;
static constexpr size_t OW_ug2 = 428032;
static constexpr size_t OW_co0 = 460800;
static constexpr int    OW_END = 477184;

__device__ float g_ws[WS_TOTAL];
__device__ int   g_deg[NL];

// ---------------- PTX helpers ----------------
__device__ __forceinline__ uint32_t smem_u32(const void* p){
    uint32_t a;
    asm("{ .reg .u64 t; cvta.to.shared.u64 t, %1; cvt.u32.u64 %0, t; }" : "=r"(a) : "l"(p));
    return a;
}
__device__ __forceinline__ void ldsm4(uint32_t* r, uint32_t addr){
    asm volatile("ldmatrix.sync.aligned.m8n8.x4.shared.b16 {%0,%1,%2,%3}, [%4];"
        : "=r"(r[0]), "=r"(r[1]), "=r"(r[2]), "=r"(r[3]) : "r"(addr));
}
__device__ __forceinline__ void mma_bf16(float* c, const uint32_t* a, const uint32_t* b){
    asm volatile("mma.sync.aligned.m16n8k16.row.col.f32.bf16.bf16.f32 "
        "{%0,%1,%2,%3}, {%4,%5,%6,%7}, {%8,%9}, {%0,%1,%2,%3};"
        : "+f"(c[0]), "+f"(c[1]), "+f"(c[2]), "+f"(c[3])
        : "r"(a[0]), "r"(a[1]), "r"(a[2]), "r"(a[3]), "r"(b[0]), "r"(b[1]));
}
__device__ __forceinline__ uint32_t pack_bf16x2(float lo, float hi){
    uint32_t r;
    asm("cvt.rn.bf16x2.f32 %0, %1, %2;" : "=r"(r) : "f"(hi), "f"(lo));
    return r;
}
__device__ __forceinline__ void cp16(uint32_t dst, const void* src, bool pred){
    int sz = pred ? 16 : 0;
    asm volatile("cp.async.cg.shared.global [%0], [%1], 16, %2;"
                 :: "r"(dst), "l"(src), "r"(sz));
}
#define CP_COMMIT() asm volatile("cp.async.commit_group;" ::: "memory")
#define CP_WAIT1()  asm volatile("cp.async.wait_group 1;" ::: "memory")

__device__ __forceinline__ float sigm(float x){ return 1.f/(1.f+expf(-x)); }
__device__ __forceinline__ float softplusf(float x){ return fmaxf(x,0.f)+log1pf(expf(-fabsf(x))); }

// A-loader modes
#define M_PLAIN 0
#define M_CAT4  1
#define M_CMIN  2
#define M_UNIT  3

struct GArgs {
    const float* p0; const float* p1; const float* p2;
    const float* p3; const float* p4; const float* p5;
};

// ---------------- bf16-split MMA GEMM, cp.async pipelined ----------------
// smem: A 2-stage (hi/lo) [0,40960), B 3-buf (hi/lo) [40960,102400)
static constexpr int GEMM_SMEM = 102400;

template<int MODE, int EPI>
__global__ void __launch_bounds__(256, 1)
k_mma(GArgs ga, const __nv_bfloat16* __restrict__ Bhg,
      const __nv_bfloat16* __restrict__ Blg, const float* __restrict__ bias,
      float* __restrict__ C, int K, int KP, int Ntot, int relu,
      float* __restrict__ out, int round,
      const float* __restrict__ w1, const float* __restrict__ b1)
{
    extern __shared__ __align__(16) char smem[];
    const uint32_t sbase = smem_u32(smem);
    const int t = threadIdx.x;
    const int lane = t & 31, wid = t >> 5;
    const int warp_m = wid & 1, warp_n = wid >> 1;
    const int bm = blockIdx.y * 128;
    const int bn = blockIdx.x * 128;

    constexpr int LDH  = 40;
    constexpr int HALF = 10240;     // one 128x32 bf16 plane (with pad)
    constexpr int A0   = 0;         // A stage s: hi at s*2*HALF, lo +HALF
    constexpr int B0   = 40960;     // B buf b:  hi at B0+b*2*HALF, lo +HALF

    float acc[4][4][4];
    #pragma unroll
    for (int i=0;i<4;i++)
        #pragma unroll
        for(int j=0;j<4;j++)
            #pragma unroll
            for(int q=0;q<4;q++) acc[i][j][q]=0.f;

    const int nch = (K + 31) >> 5;
    float4 aReg[4];

    auto loadA = [&](int c){
        const int k0 = c << 5;
        #pragma unroll
        for (int i = 0; i < 4; i++) {
            int idx = t + i*256;
            int row = idx >> 3, col4 = (idx & 7) << 2;
            int gk = k0 + col4;
            int r = bm + row;
            float4 v = make_float4(0.f,0.f,0.f,0.f);
            if (MODE == M_PLAIN) {
                if (gk < K) v = *reinterpret_cast<const float4*>(&ga.p0[(size_t)r*K + gk]);
            } else if (MODE == M_CAT4) {
                if (gk < 128)       v = *reinterpret_cast<const float4*>(&ga.p0[(size_t)r*128 + gk]);
                else if (gk == 128) v = *reinterpret_cast<const float4*>(&ga.p1[(size_t)r*4]);
            } else if (MODE == M_CMIN) {
                int seg = gk >> 7, cc = gk & 127;
                if (seg == 0)      v = *reinterpret_cast<const float4*>(&ga.p0[(size_t)r*128 + cc]);
                else if (seg == 1) {
                    v = *reinterpret_cast<const float4*>(&ga.p1[(size_t)r*128 + cc]);
                    v.x*=4.f; v.y*=4.f; v.z*=4.f; v.w*=4.f;
                } else             v = *reinterpret_cast<const float4*>(&ga.p2[(size_t)r*128 + cc]);
            } else { // M_UNIT
                int seg = gk >> 7, cc = gk & 127;
                if (seg == 0) {
                    float4 vq = *reinterpret_cast<const float4*>(&ga.p0[(size_t)r*128 + cc]);
                    float4 dp = *reinterpret_cast<const float4*>(&ga.p1[(size_t)r*128 + cc]);
                    float4 dn = *reinterpret_cast<const float4*>(&ga.p1[(size_t)(r+NV)*128 + cc]);
                    float w = ga.p5[r];
                    float sp;
                    sp = sigm(vq.x); v.x = -INV_M*(dp.x*sp - dn.x*(1.f-sp))*w;
                    sp = sigm(vq.y); v.y = -INV_M*(dp.y*sp - dn.y*(1.f-sp))*w;
                    sp = sigm(vq.z); v.z = -INV_M*(dp.z*sp - dn.z*(1.f-sp))*w;
                    sp = sigm(vq.w); v.w = -INV_M*(dp.w*sp - dn.w*(1.f-sp))*w;
                } else if (seg == 1) {
                    v = *reinterpret_cast<const float4*>(&ga.p2[(size_t)r*128 + cc]);
                } else if (seg == 2) {
                    v = *reinterpret_cast<const float4*>(&ga.p3[(size_t)r*128 + cc]);
                    float w = ga.p4[r];
                    v.x*=w; v.y*=w; v.z*=w; v.w*=w;
                } else {
                    v = *reinterpret_cast<const float4*>(&ga.p3[(size_t)(r+NV)*128 + cc]);
                    float w = ga.p4[r+NV];
                    v.x*=w; v.y*=w; v.z*=w; v.w*=w;
                }
            }
            aReg[i] = v;
        }
    };
    auto cpB = [&](int c){
        const int k0 = c << 5;
        const uint32_t bb = sbase + B0 + (uint32_t)(c % 3)*(2*HALF);
        #pragma unroll
        for (int i = 0; i < 2; i++) {
            int idx = t + i*256;
            int row = idx >> 2, q = idx & 3;
            int gk = k0 + q*8;
            bool ok = (gk + 8 <= KP);
            size_t off = ok ? ((size_t)(bn+row)*KP + gk) : 0;
            uint32_t d = bb + (uint32_t)(row*LDH + q*8)*2;
            cp16(d,        Bhg + off, ok);
            cp16(d + HALF, Blg + off, ok);
        }
    };
    auto storeA = [&](int s){
        char* sc = smem + A0 + s*(2*HALF);
        #pragma unroll
        for (int i = 0; i < 4; i++) {
            int idx = t + i*256;
            int row = idx >> 3, col4 = (idx & 7) << 2;
            uint32_t h0 = pack_bf16x2(aReg[i].x, aReg[i].y);
            uint32_t h1 = pack_bf16x2(aReg[i].z, aReg[i].w);
            float hx = __uint_as_float(h0 << 16);
            float hy = __uint_as_float(h0 & 0xffff0000u);
            float hz = __uint_as_float(h1 << 16);
            float hw = __uint_as_float(h1 & 0xffff0000u);
            uint32_t l0 = pack_bf16x2(aReg[i].x - hx, aReg[i].y - hy);
            uint32_t l1 = pack_bf16x2(aReg[i].z - hz, aReg[i].w - hw);
            int boff = (row*LDH + col4)*2;
            *reinterpret_cast<uint2*>(sc + boff)        = make_uint2(h0,h1);
            *reinterpret_cast<uint2*>(sc + HALF + boff) = make_uint2(l0,l1);
        }
    };
    auto compute = [&](int c){
        const uint32_t sa = sbase + A0 + (uint32_t)(c & 1)*(2*HALF);
        const uint32_t sb = sbase + B0 + (uint32_t)(c % 3)*(2*HALF);
        const int grp = lane >> 3, r = lane & 7;
        #pragma unroll
        for (int ks = 0; ks < 32; ks += 16) {
            uint32_t aH[4][4], aL[4][4], bH[4][2], bL[4][2];
            #pragma unroll
            for (int mt = 0; mt < 4; mt++) {
                int arow = warp_m*64 + mt*16 + (grp & 1)*8 + r;
                int acol = ks + (grp >> 1)*8;
                uint32_t adr = sa + (uint32_t)(arow*LDH + acol)*2;
                ldsm4(aH[mt], adr);
                ldsm4(aL[mt], adr + HALF);
            }
            #pragma unroll
            for (int p = 0; p < 2; p++) {
                int brow = warp_n*32 + p*16 + (grp >> 1)*8 + r;
                int bcol = ks + (grp & 1)*8;
                uint32_t adr = sb + (uint32_t)(brow*LDH + bcol)*2;
                uint32_t tmp[4];
                ldsm4(tmp, adr);
                bH[2*p][0]=tmp[0]; bH[2*p][1]=tmp[1]; bH[2*p+1][0]=tmp[2]; bH[2*p+1][1]=tmp[3];
                ldsm4(tmp, adr + HALF);
                bL[2*p][0]=tmp[0]; bL[2*p][1]=tmp[1]; bL[2*p+1][0]=tmp[2]; bL[2*p+1][1]=tmp[3];
            }
            #pragma unroll
            for (int mt = 0; mt < 4; mt++)
                #pragma unroll
                for (int nt = 0; nt < 4; nt++) {
                    mma_bf16(acc[mt][nt], aH[mt], bH[nt]);
                    mma_bf16(acc[mt][nt], aH[mt], bL[nt]);
                    mma_bf16(acc[mt][nt], aL[mt], bH[nt]);
                }
        }
    };

    // prologue: A(0) via regs, B(0)/B(1) via cp.async
    loadA(0);
    cpB(0);
    CP_COMMIT();
    storeA(0);
    if (nch > 1) { loadA(1); cpB(1); }
    CP_COMMIT();
    CP_WAIT1();
    __syncthreads();

    for (int c = 0; c < nch; c++) {
        compute(c);
        if (c+1 < nch) storeA((c+1) & 1);
        if (c+2 < nch) cpB(c+2);
        CP_COMMIT();
        if (c+2 < nch) loadA(c+2);
        CP_WAIT1();
        __syncthreads();
    }

    if (EPI == 0) {
        #pragma unroll
        for (int mt = 0; mt < 4; mt++) {
            int row0 = bm + warp_m*64 + mt*16 + (lane >> 2);
            #pragma unroll
            for (int nt = 0; nt < 4; nt++) {
                int col = bn + warp_n*32 + nt*8 + (lane & 3)*2;
                float2 bv = *reinterpret_cast<const float2*>(&bias[col]);
                float v0 = acc[mt][nt][0] + bv.x, v1 = acc[mt][nt][1] + bv.y;
                float v2 = acc[mt][nt][2] + bv.x, v3 = acc[mt][nt][3] + bv.y;
                if (relu) { v0=fmaxf(v0,0.f); v1=fmaxf(v1,0.f); v2=fmaxf(v2,0.f); v3=fmaxf(v3,0.f); }
                *reinterpret_cast<float2*>(&C[(size_t)row0*Ntot + col])     = make_float2(v0,v1);
                *reinterpret_cast<float2*>(&C[(size_t)(row0+8)*Ntot + col]) = make_float2(v2,v3);
            }
        }
    } else {
        float* red = reinterpret_cast<float*>(smem);
        if (t < 128) red[t] = 0.f;
        __syncthreads();
        #pragma unroll
        for (int mt = 0; mt < 4; mt++) {
            int rl = warp_m*64 + mt*16 + (lane >> 2);
            float p0 = 0.f, p1 = 0.f;
            #pragma unroll
            for (int nt = 0; nt < 4; nt++) {
                int col = warp_n*32 + nt*8 + (lane & 3)*2;
                float2 bv = *reinterpret_cast<const float2*>(&bias[col]);
                float wa = __ldg(&w1[col]), wb = __ldg(&w1[col+1]);
                float v0 = fmaxf(acc[mt][nt][0] + bv.x, 0.f);
                float v1 = fmaxf(acc[mt][nt][1] + bv.y, 0.f);
                float v2 = fmaxf(acc[mt][nt][2] + bv.x, 0.f);
                float v3 = fmaxf(acc[mt][nt][3] + bv.y, 0.f);
                p0 += v0*wa + v1*wb;
                p1 += v2*wa + v3*wb;
            }
            atomicAdd(&red[rl], p0);
            atomicAdd(&red[rl+8], p1);
        }
        __syncthreads();
        if (t < 128) {
            float x = red[t] + __ldg(&b1[0]);
            int row = bm + t;
            out[(size_t)round*NC + row] = sigm(x);
            out[(size_t)4*NC + (size_t)round*NC + row] = softplusf(x);
        }
    }
}

// ---------------- setup kernels (5 launches so ncu -s 5 lands on k_mma) ----------------
__global__ void k_fill_init(float* p, size_t n){
    size_t i = (size_t)blockIdx.x*blockDim.x + threadIdx.x;
    if (i < n) p[i] = 1.f;
}
__global__ void k_zero_int(int* p, int n){
    int i = blockIdx.x*blockDim.x + threadIdx.x;
    if (i < n) p[i] = 0;
}
__global__ void k_count(const int* __restrict__ lit){
    int e = blockIdx.x*blockDim.x + threadIdx.x;
    if (e < NE) atomicAdd(&g_deg[lit[e]], 1);
}
__global__ void k_weights(){
    int l = blockIdx.x*blockDim.x + threadIdx.x;
    if (l < NL) g_ws[O_DEGW + l] = rsqrtf(fmaxf((float)g_deg[l], 1.f));
    if (l < NV) g_ws[O_VDEGW + l] = 4.f*rsqrtf(fmaxf((float)(g_deg[l] + g_deg[l+NV]), 1.f));
}

struct WSrc { const float* w[10]; };
__global__ void k_wsplit_all(WSrc ws, __nv_bfloat16* __restrict__ hi,
                             __nv_bfloat16* __restrict__ lo){
    const int offs[11] = {0, 17408, 33792, 51200, 67584, 165888, 231424,
                          362496, 428032, 460800, 477184};
    const int Ks[10]  = {132,128,132,128,384,256,512,256,256,128};
    const int KPs[10] = {136,128,136,128,384,256,512,256,256,128};
    const int Ns[10]  = {128,128,128,128,256,256,256,256,128,128};
    int idx = blockIdx.x*blockDim.x + threadIdx.x;
    if (idx >= offs[10]) return;
    int seg = 0;
    #pragma unroll
    for (int s = 1; s < 10; s++) if (idx >= offs[s]) seg = s;
    int local = idx - offs[seg];
    int K = Ks[seg], KP = KPs[seg], N = Ns[seg];
    int n = local / KP, k = local % KP;
    float v = (k < K) ? ws.w[seg][(size_t)k*N + n] : 0.f;
    __nv_bfloat16 h = __float2bfloat16(v);
    hi[idx] = h;
    lo[idx] = __float2bfloat16(v - __bfloat162float(h));
}

// ---------------- misc kernels ----------------
__global__ void k_zero(float* p, size_t n){
    size_t i = (size_t)blockIdx.x*blockDim.x + threadIdx.x;
    if (i < n) p[i] = 0.f;
}
// fused: csum (sorted-clause gather) + loss + cgrad
__global__ void k_csum_loss(const int* __restrict__ lit, const int* __restrict__ cls){
    const int c = blockIdx.x, f = threadIdx.x;
    __shared__ int se[2];
    if (f < 2) {
        int key = c + f;
        int lo = 0, hi = NE;
        while (lo < hi) { int mid = (lo+hi) >> 1; if (cls[mid] < key) lo = mid+1; else hi = mid; }
        se[f] = lo;
    }
    __syncthreads();
    float csum = 0.f;
    for (int e = se[0]; e < se[1]; e++) {
        int l = lit[e];
        float z = (l < NV) ? g_ws[O_VQ + (size_t)l*128 + f]
                           : -g_ws[O_VQ + (size_t)(l-NV)*128 + f];
        csum += softplusf(z);
    }
    size_t i = (size_t)c*128 + f;
    float s = sigm(g_ws[O_CQ + i]);
    float l = expf(-csum) * s;
    g_ws[O_LOSS + i]  = l;
    g_ws[O_CGRAD + i] = l * (1.f - s) * INV_M;
}
__global__ void k_scatter(const float* __restrict__ src, int sstride,
                          const int* __restrict__ gidx, const int* __restrict__ sidx,
                          float* __restrict__ dst){
    int e = blockIdx.x, f = threadIdx.x;
    atomicAdd(&dst[(size_t)sidx[e]*128 + f], src[(size_t)gidx[e]*sstride + f]);
}
__global__ void k_pn_stats(const float* __restrict__ x, int stride, int off, int n){
    int f = threadIdx.x;
    float s = 0.f, q = 0.f;
    for (int r = blockIdx.x; r < n; r += gridDim.x) {
        float v = x[(size_t)r*stride + off + f];
        s += v; q += v*v;
    }
    atomicAdd(&g_ws[O_STAT + f], s);
    atomicAdd(&g_ws[O_STAT + 128 + f], q);
}
__global__ void k_pn_scale(float n){
    int f = threadIdx.x;
    float mean = g_ws[O_STAT + f] / n;
    float var  = g_ws[O_STAT + 128 + f] / n - mean*mean;
    __shared__ float sh[128];
    sh[f] = var; __syncthreads();
    for (int s = 64; s > 0; s >>= 1) { if (f < s) sh[f] += sh[f+s]; __syncthreads(); }
    g_ws[O_STAT + f] = mean;
    if (f == 0) g_ws[O_STAT + 256] = rsqrtf(sh[0]*(1.f/128.f) + 1e-6f);
}
__global__ void k_pn_apply(const float* __restrict__ x, int stride, int off,
                           float* __restrict__ dst){
    int r = blockIdx.x, f = threadIdx.x;
    float scale = g_ws[O_STAT + 256];
    float v = (x[(size_t)r*stride + off + f] - g_ws[O_STAT + f]) * scale;
    size_t i = (size_t)r*128 + f;
    dst[i] = v*0.25f + 0.1f*dst[i];
}

// ---------------- host ----------------
template<int MODE, int EPI>
static void mmgemm(GArgs ga, const __nv_bfloat16* Bh, const __nv_bfloat16* Bl,
                   const float* bias, float* C, int M, int K, int KP, int Ntot, int relu,
                   float* out = nullptr, int round = 0,
                   const float* w1 = nullptr, const float* b1 = nullptr){
    cudaFuncSetAttribute(k_mma<MODE,EPI>, cudaFuncAttributeMaxDynamicSharedMemorySize, GEMM_SMEM);
    dim3 grid(Ntot/128, M/128);
    k_mma<MODE,EPI><<<grid, 256, GEMM_SMEM>>>(ga, Bh, Bl, bias, C, K, KP, Ntot, relu,
                                              out, round, w1, b1);
}

extern "C" void kernel_launch(void* const* d_in, const int* in_sizes, int n_in,
                              void* d_out, int out_size)
{
    (void)in_sizes; (void)n_in; (void)out_size;
    const int*   edge_lit    = (const int*)d_in[0];
    const int*   edge_clause = (const int*)d_in[1];
    const float* noise_v = (const float*)d_in[2];
    const float* noise_c = (const float*)d_in[3];
    const float* vq_w0 = (const float*)d_in[4];  const float* vq_b0 = (const float*)d_in[5];
    const float* vq_w1 = (const float*)d_in[6];  const float* vq_b1 = (const float*)d_in[7];
    const float* cq_w0 = (const float*)d_in[8];  const float* cq_b0 = (const float*)d_in[9];
    const float* cq_w1 = (const float*)d_in[10]; const float* cq_b1 = (const float*)d_in[11];
    const float* cm_w0 = (const float*)d_in[12]; const float* cm_b0 = (const float*)d_in[13];
    const float* cm_w1 = (const float*)d_in[14]; const float* cm_b1 = (const float*)d_in[15];
    const float* ug_w0 = (const float*)d_in[16]; const float* ug_b0 = (const float*)d_in[17];
    const float* ug_w1 = (const float*)d_in[18]; const float* ug_b1 = (const float*)d_in[19];
    const float* ug_w2 = (const float*)d_in[20]; const float* ug_b2 = (const float*)d_in[21];
    const float* co_w0 = (const float*)d_in[22]; const float* co_b0 = (const float*)d_in[23];
    const float* co_w1 = (const float*)d_in[24]; const float* co_b1 = (const float*)d_in[25];
    float* out = (float*)d_out;

    float* ws; cudaGetSymbolAddress((void**)&ws, g_ws);
    int* deg;  cudaGetSymbolAddress((void**)&deg, g_deg);
    __nv_bfloat16* wh = reinterpret_cast<__nv_bfloat16*>(ws + O_WT);
    __nv_bfloat16* wl = wh + WH_TOTAL;

    // ---- setup: exactly 5 launches, so launch #6 (first k_mma) is ncu's target ----
    {
        size_t n = (size_t)(NV+NC)*128;   // VARS and CLS are contiguous
        k_fill_init<<<(unsigned)((n+255)/256), 256>>>(ws + O_VARS, n);
    }
    k_zero_int<<<(NL+255)/256, 256>>>(deg, NL);
    k_count<<<(NE+255)/256, 256>>>(edge_lit);
    k_weights<<<(NL+255)/256, 256>>>();
    {
        WSrc s;
        s.w[0]=vq_w0; s.w[1]=vq_w1; s.w[2]=cq_w0; s.w[3]=cq_w1; s.w[4]=cm_w0;
        s.w[5]=cm_w1; s.w[6]=ug_w0; s.w[7]=ug_w1; s.w[8]=ug_w2; s.w[9]=co_w0;
        k_wsplit_all<<<(OW_END+255)/256, 256>>>(s, wh, wl);
    }

    for (int r = 0; r < 4; r++) {
        const float* nv_r = noise_v + (size_t)r*NV*4;
        const float* nc_r = noise_c + (size_t)r*NC*4;
        GArgs ga{};

        ga = {ws+O_VARS, nv_r, 0, 0, 0, 0};
        mmgemm<M_CAT4,0>(ga, wh+OW_vq0, wl+OW_vq0, vq_b0, ws+O_HV, NV, 132, 136, 128, 1);
        ga = {ws+O_HV, 0, 0, 0, 0, 0};
        mmgemm<M_PLAIN,0>(ga, wh+OW_vq1, wl+OW_vq1, vq_b1, ws+O_VQ, NV, 128, 128, 128, 0);
        ga = {ws+O_CLS, nc_r, 0, 0, 0, 0};
        mmgemm<M_CAT4,0>(ga, wh+OW_cq0, wl+OW_cq0, cq_b0, ws+O_HC, NC, 132, 136, 128, 1);
        ga = {ws+O_HC, 0, 0, 0, 0, 0};
        mmgemm<M_PLAIN,0>(ga, wh+OW_cq1, wl+OW_cq1, cq_b1, ws+O_CQ, NC, 128, 128, 128, 0);

        k_csum_loss<<<NC, 128>>>(edge_lit, edge_clause);

        {
            size_t n = (size_t)NL*128;
            k_zero<<<(unsigned)((n+255)/256), 256>>>(ws+O_DLITS, n);
        }
        k_scatter<<<NE, 128>>>(ws+O_LOSS, 128, edge_clause, edge_lit, ws+O_DLITS);

        ga = {ws+O_CLS, ws+O_LOSS, ws+O_CGRAD, 0, 0, 0};
        mmgemm<M_CMIN,0>(ga, wh+OW_cm0, wl+OW_cm0, cm_b0, ws+O_HC, NC, 384, 384, 256, 1);
        ga = {ws+O_HC, 0, 0, 0, 0, 0};
        mmgemm<M_PLAIN,0>(ga, wh+OW_cm1, wl+OW_cm1, cm_b1, ws+O_CDATA, NC, 256, 256, 256, 0);

        {
            size_t n = (size_t)NL*128;
            k_zero<<<(unsigned)((n+255)/256), 256>>>(ws+O_VL, n);
        }
        k_scatter<<<NE, 128>>>(ws+O_CDATA, 256, edge_clause, edge_lit, ws+O_VL);

        k_zero<<<2, 256>>>(ws+O_STAT, 257);
        k_pn_stats<<<512, 128>>>(ws+O_CDATA, 256, 128, NC);
        k_pn_scale<<<1, 128>>>((float)NC);
        k_pn_apply<<<NC, 128>>>(ws+O_CDATA, 256, 128, ws+O_CLS);

        ga = {ws+O_VQ, ws+O_DLITS, ws+O_VARS, ws+O_VL, ws+O_DEGW, ws+O_VDEGW};
        mmgemm<M_UNIT,0>(ga, wh+OW_ug0, wl+OW_ug0, ug_b0, ws+O_HV, NV, 512, 512, 256, 1);
        ga = {ws+O_HV, 0, 0, 0, 0, 0};
        mmgemm<M_PLAIN,0>(ga, wh+OW_ug1, wl+OW_ug1, ug_b1, ws+O_HV2, NV, 256, 256, 256, 1);
        ga = {ws+O_HV2, 0, 0, 0, 0, 0};
        mmgemm<M_PLAIN,0>(ga, wh+OW_ug2, wl+OW_ug2, ug_b2, ws+O_VOUT, NV, 256, 256, 128, 0);

        k_zero<<<2, 256>>>(ws+O_STAT, 257);
        k_pn_stats<<<512, 128>>>(ws+O_VOUT, 128, 0, NV);
        k_pn_scale<<<1, 128>>>((float)NV);
        k_pn_apply<<<NV, 128>>>(ws+O_VOUT, 128, 0, ws+O_VARS);

        ga = {ws+O_CLS, 0, 0, 0, 0, 0};
        mmgemm<M_PLAIN,1>(ga, wh+OW_co0, wl+OW_co0, co_b0, nullptr, NC, 128, 128, 128, 1,
                          out, r, co_w1, co_b1);
    }
}

// round 7
// speedup vs baseline: 1.1945x; 1.1850x over previous
#include <cuda_runtime.h>
#include <cuda_bf16.h>
#include <math.h>
#include <stdint.h>

#define NV 24576
#define NC 98304
#define NE 294912
#define NL 49152              // 2*NV
#define INV_M (1.0f/12582912.0f)   // 1/(NC*128)
#define CSR_W 40

// ---------------- workspace layout (floats) ----------------
static constexpr size_t O_VARS   = 0;
static constexpr size_t O_CLS    = O_VARS  + (size_t)NV*128;
static constexpr size_t O_HV     = O_CLS   + (size_t)NC*128;   // NV x 256
static constexpr size_t O_HV2    = O_HV    + (size_t)NV*256;   // NV x 256
static constexpr size_t O_VQ     = O_HV2   + (size_t)NV*256;
static constexpr size_t O_HC     = O_VQ    + (size_t)NV*128;   // NC x 256
static constexpr size_t O_CQ     = O_HC    + (size_t)NC*256;
static constexpr size_t O_CGRAD  = O_CQ    + (size_t)NC*128;
static constexpr size_t O_LOSS   = O_CGRAD + (size_t)NC*128;
static constexpr size_t O_CDATA  = O_LOSS  + (size_t)NC*128;   // NC x 256
static constexpr size_t O_DLITS  = O_CDATA + (size_t)NC*256;   // NL x 128
static constexpr size_t O_VL     = O_DLITS + (size_t)NL*128;   // NL x 128
static constexpr size_t O_VOUT   = O_VL    + (size_t)NL*128;   // NV x 128
static constexpr size_t O_DEGW   = O_VOUT  + (size_t)NV*128;   // NL
static constexpr size_t O_VDEGW  = O_DEGW  + NL;               // NV
static constexpr size_t O_STAT   = O_VDEGW + NV;               // 128 sum, 128 ssq, 1 scale
static constexpr size_t O_WT     = O_STAT  + 260;              // bf16 split weights
static constexpr size_t WS_TOTAL = O_WT + 480000;

// weight offsets in HALVES within each hi/lo bf16 array ([N][KP] row-major)
static constexpr size_t WH_TOTAL = 477184;
static constexpr size_t OW_vq0 = 0;
static constexpr size_t OW_vq1 = 17408;
static constexpr size_t OW_cq0 = 33792;
static constexpr size_t OW_cq1 = 51200;
static constexpr size_t OW_cm0 = 67584;
static constexpr size_t OW_cm1 = 165888;
static constexpr size_t OW_ug0 = 231424;
static constexpr size_t OW_ug1 = 362496;
static constexpr size_t OW_ug2 = 428032;
static constexpr size_t OW_co0 = 460800;
static constexpr int    OW_END = 477184;

__device__ float g_ws[WS_TOTAL];
__device__ int   g_deg[NL];
__device__ int   g_csr[(size_t)NL * CSR_W];

// ---------------- PTX helpers ----------------
__device__ __forceinline__ uint32_t smem_u32(const void* p){
    uint32_t a;
    asm("{ .reg .u64 t; cvta.to.shared.u64 t, %1; cvt.u32.u64 %0, t; }" : "=r"(a) : "l"(p));
    return a;
}
__device__ __forceinline__ void ldsm4(uint32_t* r, uint32_t addr){
    asm volatile("ldmatrix.sync.aligned.m8n8.x4.shared.b16 {%0,%1,%2,%3}, [%4];"
        : "=r"(r[0]), "=r"(r[1]), "=r"(r[2]), "=r"(r[3]) : "r"(addr));
}
__device__ __forceinline__ void mma_bf16(float* c, const uint32_t* a, const uint32_t* b){
    asm volatile("mma.sync.aligned.m16n8k16.row.col.f32.bf16.bf16.f32 "
        "{%0,%1,%2,%3}, {%4,%5,%6,%7}, {%8,%9}, {%0,%1,%2,%3};"
        : "+f"(c[0]), "+f"(c[1]), "+f"(c[2]), "+f"(c[3])
        : "r"(a[0]), "r"(a[1]), "r"(a[2]), "r"(a[3]), "r"(b[0]), "r"(b[1]));
}
__device__ __forceinline__ uint32_t pack_bf16x2(float lo, float hi){
    uint32_t r;
    asm("cvt.rn.bf16x2.f32 %0, %1, %2;" : "=r"(r) : "f"(hi), "f"(lo));
    return r;
}
__device__ __forceinline__ void cp16(uint32_t dst, const void* src, bool pred){
    int sz = pred ? 16 : 0;
    asm volatile("cp.async.cg.shared.global [%0], [%1], 16, %2;"
                 :: "r"(dst), "l"(src), "r"(sz));
}
#define CP_COMMIT() asm volatile("cp.async.commit_group;" ::: "memory")
#define CP_WAIT1()  asm volatile("cp.async.wait_group 1;" ::: "memory")

__device__ __forceinline__ float sigm(float x){ return 1.f/(1.f+expf(-x)); }
__device__ __forceinline__ float softplusf(float x){ return fmaxf(x,0.f)+log1pf(expf(-fabsf(x))); }

// A-loader modes
#define M_PLAIN 0
#define M_CAT4  1
#define M_CMIN  2
#define M_UNIT  3

struct GArgs {
    const float* p0; const float* p1; const float* p2;
    const float* p3; const float* p4; const float* p5;
};

// ---------------- bf16-split MMA GEMM, cp.async pipelined ----------------
static constexpr int GEMM_SMEM = 102400;

template<int MODE, int EPI>
__global__ void __launch_bounds__(256, 1)
k_mma(GArgs ga, const __nv_bfloat16* __restrict__ Bhg,
      const __nv_bfloat16* __restrict__ Blg, const float* __restrict__ bias,
      float* __restrict__ C, int K, int KP, int Ntot, int relu,
      float* __restrict__ out, int round,
      const float* __restrict__ w1, const float* __restrict__ b1)
{
    extern __shared__ __align__(16) char smem[];
    const uint32_t sbase = smem_u32(smem);
    const int t = threadIdx.x;
    const int lane = t & 31, wid = t >> 5;
    const int warp_m = wid & 1, warp_n = wid >> 1;
    const int bm = blockIdx.y * 128;
    const int bn = blockIdx.x * 128;

    constexpr int LDH  = 40;
    constexpr int HALF = 10240;     // one 128x32 bf16 plane (with pad)
    constexpr int A0   = 0;         // A stage s: hi at s*2*HALF, lo +HALF
    constexpr int B0   = 40960;     // B buf b:  hi at B0+b*2*HALF, lo +HALF

    float acc[4][4][4];
    #pragma unroll
    for (int i=0;i<4;i++)
        #pragma unroll
        for(int j=0;j<4;j++)
            #pragma unroll
            for(int q=0;q<4;q++) acc[i][j][q]=0.f;

    const int nch = (K + 31) >> 5;
    float4 aReg[4];

    auto loadA = [&](int c){
        const int k0 = c << 5;
        #pragma unroll
        for (int i = 0; i < 4; i++) {
            int idx = t + i*256;
            int row = idx >> 3, col4 = (idx & 7) << 2;
            int gk = k0 + col4;
            int r = bm + row;
            float4 v = make_float4(0.f,0.f,0.f,0.f);
            if (MODE == M_PLAIN) {
                if (gk < K) v = *reinterpret_cast<const float4*>(&ga.p0[(size_t)r*K + gk]);
            } else if (MODE == M_CAT4) {
                if (gk < 128)       v = *reinterpret_cast<const float4*>(&ga.p0[(size_t)r*128 + gk]);
                else if (gk == 128) v = *reinterpret_cast<const float4*>(&ga.p1[(size_t)r*4]);
            } else if (MODE == M_CMIN) {
                int seg = gk >> 7, cc = gk & 127;
                if (seg == 0)      v = *reinterpret_cast<const float4*>(&ga.p0[(size_t)r*128 + cc]);
                else if (seg == 1) {
                    v = *reinterpret_cast<const float4*>(&ga.p1[(size_t)r*128 + cc]);
                    v.x*=4.f; v.y*=4.f; v.z*=4.f; v.w*=4.f;
                } else             v = *reinterpret_cast<const float4*>(&ga.p2[(size_t)r*128 + cc]);
            } else { // M_UNIT
                int seg = gk >> 7, cc = gk & 127;
                if (seg == 0) {
                    float4 vq = *reinterpret_cast<const float4*>(&ga.p0[(size_t)r*128 + cc]);
                    float4 dp = *reinterpret_cast<const float4*>(&ga.p1[(size_t)r*128 + cc]);
                    float4 dn = *reinterpret_cast<const float4*>(&ga.p1[(size_t)(r+NV)*128 + cc]);
                    float w = ga.p5[r];
                    float sp;
                    sp = sigm(vq.x); v.x = -INV_M*(dp.x*sp - dn.x*(1.f-sp))*w;
                    sp = sigm(vq.y); v.y = -INV_M*(dp.y*sp - dn.y*(1.f-sp))*w;
                    sp = sigm(vq.z); v.z = -INV_M*(dp.z*sp - dn.z*(1.f-sp))*w;
                    sp = sigm(vq.w); v.w = -INV_M*(dp.w*sp - dn.w*(1.f-sp))*w;
                } else if (seg == 1) {
                    v = *reinterpret_cast<const float4*>(&ga.p2[(size_t)r*128 + cc]);
                } else if (seg == 2) {
                    v = *reinterpret_cast<const float4*>(&ga.p3[(size_t)r*128 + cc]);
                    float w = ga.p4[r];
                    v.x*=w; v.y*=w; v.z*=w; v.w*=w;
                } else {
                    v = *reinterpret_cast<const float4*>(&ga.p3[(size_t)(r+NV)*128 + cc]);
                    float w = ga.p4[r+NV];
                    v.x*=w; v.y*=w; v.z*=w; v.w*=w;
                }
            }
            aReg[i] = v;
        }
    };
    auto cpB = [&](int c){
        const int k0 = c << 5;
        const uint32_t bb = sbase + B0 + (uint32_t)(c % 3)*(2*HALF);
        #pragma unroll
        for (int i = 0; i < 2; i++) {
            int idx = t + i*256;
            int row = idx >> 2, q = idx & 3;
            int gk = k0 + q*8;
            bool ok = (gk + 8 <= KP);
            size_t off = ok ? ((size_t)(bn+row)*KP + gk) : 0;
            uint32_t d = bb + (uint32_t)(row*LDH + q*8)*2;
            cp16(d,        Bhg + off, ok);
            cp16(d + HALF, Blg + off, ok);
        }
    };
    auto storeA = [&](int s){
        char* sc = smem + A0 + s*(2*HALF);
        #pragma unroll
        for (int i = 0; i < 4; i++) {
            int idx = t + i*256;
            int row = idx >> 3, col4 = (idx & 7) << 2;
            uint32_t h0 = pack_bf16x2(aReg[i].x, aReg[i].y);
            uint32_t h1 = pack_bf16x2(aReg[i].z, aReg[i].w);
            float hx = __uint_as_float(h0 << 16);
            float hy = __uint_as_float(h0 & 0xffff0000u);
            float hz = __uint_as_float(h1 << 16);
            float hw = __uint_as_float(h1 & 0xffff0000u);
            uint32_t l0 = pack_bf16x2(aReg[i].x - hx, aReg[i].y - hy);
            uint32_t l1 = pack_bf16x2(aReg[i].z - hz, aReg[i].w - hw);
            int boff = (row*LDH + col4)*2;
            *reinterpret_cast<uint2*>(sc + boff)        = make_uint2(h0,h1);
            *reinterpret_cast<uint2*>(sc + HALF + boff) = make_uint2(l0,l1);
        }
    };
    auto compute = [&](int c){
        const uint32_t sa = sbase + A0 + (uint32_t)(c & 1)*(2*HALF);
        const uint32_t sb = sbase + B0 + (uint32_t)(c % 3)*(2*HALF);
        const int grp = lane >> 3, r = lane & 7;
        #pragma unroll
        for (int ks = 0; ks < 32; ks += 16) {
            uint32_t aH[4][4], aL[4][4], bH[4][2], bL[4][2];
            #pragma unroll
            for (int mt = 0; mt < 4; mt++) {
                int arow = warp_m*64 + mt*16 + (grp & 1)*8 + r;
                int acol = ks + (grp >> 1)*8;
                uint32_t adr = sa + (uint32_t)(arow*LDH + acol)*2;
                ldsm4(aH[mt], adr);
                ldsm4(aL[mt], adr + HALF);
            }
            #pragma unroll
            for (int p = 0; p < 2; p++) {
                int brow = warp_n*32 + p*16 + (grp >> 1)*8 + r;
                int bcol = ks + (grp & 1)*8;
                uint32_t adr = sb + (uint32_t)(brow*LDH + bcol)*2;
                uint32_t tmp[4];
                ldsm4(tmp, adr);
                bH[2*p][0]=tmp[0]; bH[2*p][1]=tmp[1]; bH[2*p+1][0]=tmp[2]; bH[2*p+1][1]=tmp[3];
                ldsm4(tmp, adr + HALF);
                bL[2*p][0]=tmp[0]; bL[2*p][1]=tmp[1]; bL[2*p+1][0]=tmp[2]; bL[2*p+1][1]=tmp[3];
            }
            #pragma unroll
            for (int mt = 0; mt < 4; mt++)
                #pragma unroll
                for (int nt = 0; nt < 4; nt++) {
                    mma_bf16(acc[mt][nt], aH[mt], bH[nt]);
                    mma_bf16(acc[mt][nt], aH[mt], bL[nt]);
                    mma_bf16(acc[mt][nt], aL[mt], bH[nt]);
                }
        }
    };

    loadA(0);
    cpB(0);
    CP_COMMIT();
    storeA(0);
    if (nch > 1) { loadA(1); cpB(1); }
    CP_COMMIT();
    CP_WAIT1();
    __syncthreads();

    for (int c = 0; c < nch; c++) {
        compute(c);
        if (c+1 < nch) storeA((c+1) & 1);
        if (c+2 < nch) cpB(c+2);
        CP_COMMIT();
        if (c+2 < nch) loadA(c+2);
        CP_WAIT1();
        __syncthreads();
    }

    if (EPI == 0) {
        #pragma unroll
        for (int mt = 0; mt < 4; mt++) {
            int row0 = bm + warp_m*64 + mt*16 + (lane >> 2);
            #pragma unroll
            for (int nt = 0; nt < 4; nt++) {
                int col = bn + warp_n*32 + nt*8 + (lane & 3)*2;
                float2 bv = *reinterpret_cast<const float2*>(&bias[col]);
                float v0 = acc[mt][nt][0] + bv.x, v1 = acc[mt][nt][1] + bv.y;
                float v2 = acc[mt][nt][2] + bv.x, v3 = acc[mt][nt][3] + bv.y;
                if (relu) { v0=fmaxf(v0,0.f); v1=fmaxf(v1,0.f); v2=fmaxf(v2,0.f); v3=fmaxf(v3,0.f); }
                *reinterpret_cast<float2*>(&C[(size_t)row0*Ntot + col])     = make_float2(v0,v1);
                *reinterpret_cast<float2*>(&C[(size_t)(row0+8)*Ntot + col]) = make_float2(v2,v3);
            }
        }
    } else {
        float* red = reinterpret_cast<float*>(smem);
        if (t < 128) red[t] = 0.f;
        __syncthreads();
        #pragma unroll
        for (int mt = 0; mt < 4; mt++) {
            int rl = warp_m*64 + mt*16 + (lane >> 2);
            float p0 = 0.f, p1 = 0.f;
            #pragma unroll
            for (int nt = 0; nt < 4; nt++) {
                int col = warp_n*32 + nt*8 + (lane & 3)*2;
                float2 bv = *reinterpret_cast<const float2*>(&bias[col]);
                float wa = __ldg(&w1[col]), wb = __ldg(&w1[col+1]);
                float v0 = fmaxf(acc[mt][nt][0] + bv.x, 0.f);
                float v1 = fmaxf(acc[mt][nt][1] + bv.y, 0.f);
                float v2 = fmaxf(acc[mt][nt][2] + bv.x, 0.f);
                float v3 = fmaxf(acc[mt][nt][3] + bv.y, 0.f);
                p0 += v0*wa + v1*wb;
                p1 += v2*wa + v3*wb;
            }
            atomicAdd(&red[rl], p0);
            atomicAdd(&red[rl+8], p1);
        }
        __syncthreads();
        if (t < 128) {
            float x = red[t] + __ldg(&b1[0]);
            int row = bm + t;
            out[(size_t)round*NC + row] = sigm(x);
            out[(size_t)4*NC + (size_t)round*NC + row] = softplusf(x);
        }
    }
}

// ---------------- setup kernels (exactly 3 launches; launch #4 = first k_mma) ----------------
// 1: fill VARS/CLS with ones + zero deg
__global__ void k_init(float* p, size_t nfill){
    size_t i = (size_t)blockIdx.x*blockDim.x + threadIdx.x;
    if (i < nfill) p[i] = 1.f;
    if (i < NL) g_deg[i] = 0;
}
// 2: count degrees AND fill fixed-slot CSR (csr[l*CSR_W+pos] = clause of edge)
__global__ void k_count_csr(const int* __restrict__ lit, const int* __restrict__ cls){
    int e = blockIdx.x*blockDim.x + threadIdx.x;
    if (e >= NE) return;
    int l = lit[e];
    int pos = atomicAdd(&g_deg[l], 1);
    if (pos < CSR_W) g_csr[(size_t)l*CSR_W + pos] = cls[e];
}
// 3: degree weights + weight transpose/split, one grid
struct WSrc { const float* w[10]; };
__global__ void k_weights_wsplit(WSrc ws, __nv_bfloat16* __restrict__ hi,
                                 __nv_bfloat16* __restrict__ lo){
    const int offs[11] = {0, 17408, 33792, 51200, 67584, 165888, 231424,
                          362496, 428032, 460800, 477184};
    const int Ks[10]  = {132,128,132,128,384,256,512,256,256,128};
    const int KPs[10] = {136,128,136,128,384,256,512,256,256,128};
    const int Ns[10]  = {128,128,128,128,256,256,256,256,128,128};
    int idx = blockIdx.x*blockDim.x + threadIdx.x;
    if (idx < NL) g_ws[O_DEGW + idx] = rsqrtf(fmaxf((float)g_deg[idx], 1.f));
    if (idx < NV) g_ws[O_VDEGW + idx] = 4.f*rsqrtf(fmaxf((float)(g_deg[idx] + g_deg[idx+NV]), 1.f));
    if (idx >= offs[10]) return;
    int seg = 0;
    #pragma unroll
    for (int s = 1; s < 10; s++) if (idx >= offs[s]) seg = s;
    int local = idx - offs[seg];
    int K = Ks[seg], KP = KPs[seg], N = Ns[seg];
    int n = local / KP, k = local % KP;
    float v = (k < K) ? ws.w[seg][(size_t)k*N + n] : 0.f;
    __nv_bfloat16 h = __float2bfloat16(v);
    hi[idx] = h;
    lo[idx] = __float2bfloat16(v - __bfloat162float(h));
}

// ---------------- misc kernels ----------------
__global__ void k_zero(float* p, size_t n){
    size_t i = (size_t)blockIdx.x*blockDim.x + threadIdx.x;
    if (i < n) p[i] = 0.f;
}
// fused: csum (sorted-clause gather) + loss + cgrad
__global__ void k_csum_loss(const int* __restrict__ lit, const int* __restrict__ cls){
    const int c = blockIdx.x, f = threadIdx.x;
    __shared__ int se[2];
    if (f < 2) {
        int key = c + f;
        int lo = 0, hi = NE;
        while (lo < hi) { int mid = (lo+hi) >> 1; if (cls[mid] < key) lo = mid+1; else hi = mid; }
        se[f] = lo;
    }
    __syncthreads();
    float csum = 0.f;
    for (int e = se[0]; e < se[1]; e++) {
        int l = lit[e];
        float z = (l < NV) ? g_ws[O_VQ + (size_t)l*128 + f]
                           : -g_ws[O_VQ + (size_t)(l-NV)*128 + f];
        csum += softplusf(z);
    }
    size_t i = (size_t)c*128 + f;
    float s = sigm(g_ws[O_CQ + i]);
    float l = expf(-csum) * s;
    g_ws[O_LOSS + i]  = l;
    g_ws[O_CGRAD + i] = l * (1.f - s) * INV_M;
}
// per-literal gather via CSR: dst[l] = sum over clauses of src rows (no atomics)
__global__ void k_gather(const float* __restrict__ src, int sstride,
                         float* __restrict__ dst){
    const int l = blockIdx.x, f = threadIdx.x;
    int d = g_deg[l];
    if (d > CSR_W) d = CSR_W;
    float s = 0.f;
    for (int j = 0; j < d; j++) {
        int c = g_csr[(size_t)l*CSR_W + j];
        s += src[(size_t)c*sstride + f];
    }
    dst[(size_t)l*128 + f] = s;
}
__global__ void k_pn_stats(const float* __restrict__ x, int stride, int off, int n){
    int f = threadIdx.x;
    float s = 0.f, q = 0.f;
    for (int r = blockIdx.x; r < n; r += gridDim.x) {
        float v = x[(size_t)r*stride + off + f];
        s += v; q += v*v;
    }
    atomicAdd(&g_ws[O_STAT + f], s);
    atomicAdd(&g_ws[O_STAT + 128 + f], q);
}
__global__ void k_pn_scale(float n){
    int f = threadIdx.x;
    float mean = g_ws[O_STAT + f] / n;
    float var  = g_ws[O_STAT + 128 + f] / n - mean*mean;
    __shared__ float sh[128];
    sh[f] = var; __syncthreads();
    for (int s = 64; s > 0; s >>= 1) { if (f < s) sh[f] += sh[f+s]; __syncthreads(); }
    g_ws[O_STAT + f] = mean;
    if (f == 0) g_ws[O_STAT + 256] = rsqrtf(sh[0]*(1.f/128.f) + 1e-6f);
}
__global__ void k_pn_apply(const float* __restrict__ x, int stride, int off,
                           float* __restrict__ dst){
    int r = blockIdx.x, f = threadIdx.x;
    float scale = g_ws[O_STAT + 256];
    float v = (x[(size_t)r*stride + off + f] - g_ws[O_STAT + f]) * scale;
    size_t i = (size_t)r*128 + f;
    dst[i] = v*0.25f + 0.1f*dst[i];
}

// ---------------- host ----------------
template<int MODE, int EPI>
static void mmgemm(GArgs ga, const __nv_bfloat16* Bh, const __nv_bfloat16* Bl,
                   const float* bias, float* C, int M, int K, int KP, int Ntot, int relu,
                   float* out = nullptr, int round = 0,
                   const float* w1 = nullptr, const float* b1 = nullptr){
    cudaFuncSetAttribute(k_mma<MODE,EPI>, cudaFuncAttributeMaxDynamicSharedMemorySize, GEMM_SMEM);
    dim3 grid(Ntot/128, M/128);
    k_mma<MODE,EPI><<<grid, 256, GEMM_SMEM>>>(ga, Bh, Bl, bias, C, K, KP, Ntot, relu,
                                              out, round, w1, b1);
}

extern "C" void kernel_launch(void* const* d_in, const int* in_sizes, int n_in,
                              void* d_out, int out_size)
{
    (void)in_sizes; (void)n_in; (void)out_size;
    const int*   edge_lit    = (const int*)d_in[0];
    const int*   edge_clause = (const int*)d_in[1];
    const float* noise_v = (const float*)d_in[2];
    const float* noise_c = (const float*)d_in[3];
    const float* vq_w0 = (const float*)d_in[4];  const float* vq_b0 = (const float*)d_in[5];
    const float* vq_w1 = (const float*)d_in[6];  const float* vq_b1 = (const float*)d_in[7];
    const float* cq_w0 = (const float*)d_in[8];  const float* cq_b0 = (const float*)d_in[9];
    const float* cq_w1 = (const float*)d_in[10]; const float* cq_b1 = (const float*)d_in[11];
    const float* cm_w0 = (const float*)d_in[12]; const float* cm_b0 = (const float*)d_in[13];
    const float* cm_w1 = (const float*)d_in[14]; const float* cm_b1 = (const float*)d_in[15];
    const float* ug_w0 = (const float*)d_in[16]; const float* ug_b0 = (const float*)d_in[17];
    const float* ug_w1 = (const float*)d_in[18]; const float* ug_b1 = (const float*)d_in[19];
    const float* ug_w2 = (const float*)d_in[20]; const float* ug_b2 = (const float*)d_in[21];
    const float* co_w0 = (const float*)d_in[22]; const float* co_b0 = (const float*)d_in[23];
    const float* co_w1 = (const float*)d_in[24]; const float* co_b1 = (const float*)d_in[25];
    float* out = (float*)d_out;

    float* ws; cudaGetSymbolAddress((void**)&ws, g_ws);
    __nv_bfloat16* wh = reinterpret_cast<__nv_bfloat16*>(ws + O_WT);
    __nv_bfloat16* wl = wh + WH_TOTAL;

    // ---- setup: exactly 3 launches (first k_mma is graph launch #4) ----
    {
        size_t n = (size_t)(NV+NC)*128;   // VARS and CLS are contiguous
        k_init<<<(unsigned)((n+255)/256), 256>>>(ws + O_VARS, n);
    }
    k_count_csr<<<(NE+255)/256, 256>>>(edge_lit, edge_clause);
    {
        WSrc s;
        s.w[0]=vq_w0; s.w[1]=vq_w1; s.w[2]=cq_w0; s.w[3]=cq_w1; s.w[4]=cm_w0;
        s.w[5]=cm_w1; s.w[6]=ug_w0; s.w[7]=ug_w1; s.w[8]=ug_w2; s.w[9]=co_w0;
        k_weights_wsplit<<<(OW_END+255)/256, 256>>>(s, wh, wl);
    }

    for (int r = 0; r < 4; r++) {
        const float* nv_r = noise_v + (size_t)r*NV*4;
        const float* nc_r = noise_c + (size_t)r*NC*4;
        GArgs ga{};

        // clause-side first (big GEMM lands at launch #4 for ncu)
        ga = {ws+O_CLS, nc_r, 0, 0, 0, 0};
        mmgemm<M_CAT4,0>(ga, wh+OW_cq0, wl+OW_cq0, cq_b0, ws+O_HC, NC, 132, 136, 128, 1);
        ga = {ws+O_HC, 0, 0, 0, 0, 0};
        mmgemm<M_PLAIN,0>(ga, wh+OW_cq1, wl+OW_cq1, cq_b1, ws+O_CQ, NC, 128, 128, 128, 0);
        ga = {ws+O_VARS, nv_r, 0, 0, 0, 0};
        mmgemm<M_CAT4,0>(ga, wh+OW_vq0, wl+OW_vq0, vq_b0, ws+O_HV, NV, 132, 136, 128, 1);
        ga = {ws+O_HV, 0, 0, 0, 0, 0};
        mmgemm<M_PLAIN,0>(ga, wh+OW_vq1, wl+OW_vq1, vq_b1, ws+O_VQ, NV, 128, 128, 128, 0);

        // csum gather (sorted edge_clause) + loss + cgrad (no atomics)
        k_csum_loss<<<NC, 128>>>(edge_lit, edge_clause);

        // dlits = per-literal gather of LOSS rows (no atomics, no zeroing)
        k_gather<<<NL, 128>>>(ws+O_LOSS, 128, ws+O_DLITS);

        // clause message MLP (CMIN build fused into A-loader)
        ga = {ws+O_CLS, ws+O_LOSS, ws+O_CGRAD, 0, 0, 0};
        mmgemm<M_CMIN,0>(ga, wh+OW_cm0, wl+OW_cm0, cm_b0, ws+O_HC, NC, 384, 384, 256, 1);
        ga = {ws+O_HC, 0, 0, 0, 0, 0};
        mmgemm<M_PLAIN,0>(ga, wh+OW_cm1, wl+OW_cm1, cm_b1, ws+O_CDATA, NC, 256, 256, 256, 0);

        // variables_loss = per-literal gather of CDATA[:, :128] rows
        k_gather<<<NL, 128>>>(ws+O_CDATA, 256, ws+O_VL);

        // clauses = pair_norm(cdata[:,128:])*0.25 + 0.1*clauses
        k_zero<<<2, 256>>>(ws+O_STAT, 257);
        k_pn_stats<<<512, 128>>>(ws+O_CDATA, 256, 128, NC);
        k_pn_scale<<<1, 128>>>((float)NC);
        k_pn_apply<<<NC, 128>>>(ws+O_CDATA, 256, 128, ws+O_CLS);

        // variable update MLP3 (UNIT build fused into A-loader)
        ga = {ws+O_VQ, ws+O_DLITS, ws+O_VARS, ws+O_VL, ws+O_DEGW, ws+O_VDEGW};
        mmgemm<M_UNIT,0>(ga, wh+OW_ug0, wl+OW_ug0, ug_b0, ws+O_HV, NV, 512, 512, 256, 1);
        ga = {ws+O_HV, 0, 0, 0, 0, 0};
        mmgemm<M_PLAIN,0>(ga, wh+OW_ug1, wl+OW_ug1, ug_b1, ws+O_HV2, NV, 256, 256, 256, 1);
        ga = {ws+O_HV2, 0, 0, 0, 0, 0};
        mmgemm<M_PLAIN,0>(ga, wh+OW_ug2, wl+OW_ug2, ug_b2, ws+O_VOUT, NV, 256, 256, 128, 0);

        k_zero<<<2, 256>>>(ws+O_STAT, 257);
        k_pn_stats<<<512, 128>>>(ws+O_VOUT, 128, 0, NV);
        k_pn_scale<<<1, 128>>>((float)NV);
        k_pn_apply<<<NV, 128>>>(ws+O_VOUT, 128, 0, ws+O_VARS);

        // output head: co0 GEMM with fused logits epilogue
        ga = {ws+O_CLS, 0, 0, 0, 0, 0};
        mmgemm<M_PLAIN,1>(ga, wh+OW_co0, wl+OW_co0, co_b0, nullptr, NC, 128, 128, 128, 1,
                          out, r, co_w1, co_b1);
    }
}

// round 8
// speedup vs baseline: 1.2420x; 1.0398x over previous
#include <cuda_runtime.h>
#include <cuda_bf16.h>
#include <math.h>
#include <stdint.h>

#define NV 24576
#define NC 98304
#define NE 294912
#define NL 49152              // 2*NV
#define INV_M (1.0f/12582912.0f)   // 1/(NC*128)
#define CSR_W 40

// ---------------- workspace layout (floats) ----------------
static constexpr size_t O_VARS   = 0;
static constexpr size_t O_CLS    = O_VARS  + (size_t)NV*128;
static constexpr size_t O_HV     = O_CLS   + (size_t)NC*128;   // NV x 256
static constexpr size_t O_HV2    = O_HV    + (size_t)NV*256;   // NV x 256
static constexpr size_t O_VQ     = O_HV2   + (size_t)NV*256;
static constexpr size_t O_HC     = O_VQ    + (size_t)NV*128;   // NC x 256
static constexpr size_t O_CQ     = O_HC    + (size_t)NC*256;
static constexpr size_t O_CGRAD  = O_CQ    + (size_t)NC*128;
static constexpr size_t O_LOSS   = O_CGRAD + (size_t)NC*128;
static constexpr size_t O_CDATA  = O_LOSS  + (size_t)NC*128;   // NC x 256
static constexpr size_t O_DLITS  = O_CDATA + (size_t)NC*256;   // NL x 128
static constexpr size_t O_VL     = O_DLITS + (size_t)NL*128;   // NL x 128
static constexpr size_t O_VOUT   = O_VL    + (size_t)NL*128;   // NV x 128
static constexpr size_t O_DEGW   = O_VOUT  + (size_t)NV*128;   // NL
static constexpr size_t O_VDEGW  = O_DEGW  + NL;               // NV
static constexpr size_t O_STAT   = O_VDEGW + NV;               // 128 sum, 128 ssq, 1 scale
static constexpr size_t O_WT     = O_STAT  + 260;              // bf16 split weights
static constexpr size_t WS_TOTAL = O_WT + 480000;

// weight offsets in HALVES within each hi/lo bf16 array ([N][KP] row-major)
static constexpr size_t WH_TOTAL = 477184;
static constexpr size_t OW_vq0 = 0;
static constexpr size_t OW_vq1 = 17408;
static constexpr size_t OW_cq0 = 33792;
static constexpr size_t OW_cq1 = 51200;
static constexpr size_t OW_cm0 = 67584;
static constexpr size_t OW_cm1 = 165888;
static constexpr size_t OW_ug0 = 231424;
static constexpr size_t OW_ug1 = 362496;
static constexpr size_t OW_ug2 = 428032;
static constexpr size_t OW_co0 = 460800;
static constexpr int    OW_END = 477184;

__device__ float g_ws[WS_TOTAL];
__device__ int   g_deg[NL];
__device__ int   g_csr[(size_t)NL * CSR_W];

// ---------------- PTX helpers ----------------
__device__ __forceinline__ uint32_t smem_u32(const void* p){
    uint32_t a;
    asm("{ .reg .u64 t; cvta.to.shared.u64 t, %1; cvt.u32.u64 %0, t; }" : "=r"(a) : "l"(p));
    return a;
}
__device__ __forceinline__ void ldsm4(uint32_t* r, uint32_t addr){
    asm volatile("ldmatrix.sync.aligned.m8n8.x4.shared.b16 {%0,%1,%2,%3}, [%4];"
        : "=r"(r[0]), "=r"(r[1]), "=r"(r[2]), "=r"(r[3]) : "r"(addr));
}
__device__ __forceinline__ void mma_bf16(float* c, const uint32_t* a, const uint32_t* b){
    asm volatile("mma.sync.aligned.m16n8k16.row.col.f32.bf16.bf16.f32 "
        "{%0,%1,%2,%3}, {%4,%5,%6,%7}, {%8,%9}, {%0,%1,%2,%3};"
        : "+f"(c[0]), "+f"(c[1]), "+f"(c[2]), "+f"(c[3])
        : "r"(a[0]), "r"(a[1]), "r"(a[2]), "r"(a[3]), "r"(b[0]), "r"(b[1]));
}
__device__ __forceinline__ uint32_t pack_bf16x2(float lo, float hi){
    uint32_t r;
    asm("cvt.rn.bf16x2.f32 %0, %1, %2;" : "=r"(r) : "f"(hi), "f"(lo));
    return r;
}
__device__ __forceinline__ void cp16(uint32_t dst, const void* src, bool pred){
    int sz = pred ? 16 : 0;
    asm volatile("cp.async.cg.shared.global [%0], [%1], 16, %2;"
                 :: "r"(dst), "l"(src), "r"(sz));
}
#define CP_COMMIT() asm volatile("cp.async.commit_group;" ::: "memory")
#define CP_WAIT1()  asm volatile("cp.async.wait_group 1;" ::: "memory")

__device__ __forceinline__ float sigm(float x){ return 1.f/(1.f+expf(-x)); }
__device__ __forceinline__ float softplusf(float x){ return fmaxf(x,0.f)+log1pf(expf(-fabsf(x))); }

// A-loader modes
#define M_PLAIN 0
#define M_CAT4  1
#define M_CMIN  2
#define M_UNIT  3

struct GArgs {
    const float* p0; const float* p1; const float* p2;
    const float* p3; const float* p4; const float* p5;
};

// ---------------- bf16-split MMA GEMM, 512 threads / 16 warps ----------------
static constexpr int GEMM_SMEM = 102400;
static constexpr int GEMM_THREADS = 512;

template<int MODE, int EPI>
__global__ void __launch_bounds__(GEMM_THREADS, 1)
k_mma(GArgs ga, const __nv_bfloat16* __restrict__ Bhg,
      const __nv_bfloat16* __restrict__ Blg, const float* __restrict__ bias,
      float* __restrict__ C, int K, int KP, int Ntot, int relu,
      float* __restrict__ out, int round,
      const float* __restrict__ w1, const float* __restrict__ b1)
{
    extern __shared__ __align__(16) char smem[];
    const uint32_t sbase = smem_u32(smem);
    const int t = threadIdx.x;
    const int lane = t & 31, wid = t >> 5;
    const int warp_m = wid & 3;        // 4 x 32 rows
    const int warp_n = wid >> 2;       // 4 x 32 cols
    const int bm = blockIdx.y * 128;
    const int bn = blockIdx.x * 128;

    constexpr int LDH  = 40;
    constexpr int HALF = 10240;     // one 128x32 bf16 plane (with pad)
    constexpr int A0   = 0;         // A stage s: hi at s*2*HALF, lo +HALF
    constexpr int B0   = 40960;     // B buf b:  hi at B0+b*2*HALF, lo +HALF

    float acc[2][4][4];
    #pragma unroll
    for (int i=0;i<2;i++)
        #pragma unroll
        for(int j=0;j<4;j++)
            #pragma unroll
            for(int q=0;q<4;q++) acc[i][j][q]=0.f;

    const int nch = (K + 31) >> 5;
    float4 aReg[2];

    auto loadA = [&](int c){
        const int k0 = c << 5;
        #pragma unroll
        for (int i = 0; i < 2; i++) {
            int idx = t + i*GEMM_THREADS;
            int row = idx >> 3, col4 = (idx & 7) << 2;
            int gk = k0 + col4;
            int r = bm + row;
            float4 v = make_float4(0.f,0.f,0.f,0.f);
            if (MODE == M_PLAIN) {
                if (gk < K) v = *reinterpret_cast<const float4*>(&ga.p0[(size_t)r*K + gk]);
            } else if (MODE == M_CAT4) {
                if (gk < 128)       v = *reinterpret_cast<const float4*>(&ga.p0[(size_t)r*128 + gk]);
                else if (gk == 128) v = *reinterpret_cast<const float4*>(&ga.p1[(size_t)r*4]);
            } else if (MODE == M_CMIN) {
                int seg = gk >> 7, cc = gk & 127;
                if (seg == 0)      v = *reinterpret_cast<const float4*>(&ga.p0[(size_t)r*128 + cc]);
                else if (seg == 1) {
                    v = *reinterpret_cast<const float4*>(&ga.p1[(size_t)r*128 + cc]);
                    v.x*=4.f; v.y*=4.f; v.z*=4.f; v.w*=4.f;
                } else             v = *reinterpret_cast<const float4*>(&ga.p2[(size_t)r*128 + cc]);
            } else { // M_UNIT
                int seg = gk >> 7, cc = gk & 127;
                if (seg == 0) {
                    float4 vq = *reinterpret_cast<const float4*>(&ga.p0[(size_t)r*128 + cc]);
                    float4 dp = *reinterpret_cast<const float4*>(&ga.p1[(size_t)r*128 + cc]);
                    float4 dn = *reinterpret_cast<const float4*>(&ga.p1[(size_t)(r+NV)*128 + cc]);
                    float w = ga.p5[r];
                    float sp;
                    sp = sigm(vq.x); v.x = -INV_M*(dp.x*sp - dn.x*(1.f-sp))*w;
                    sp = sigm(vq.y); v.y = -INV_M*(dp.y*sp - dn.y*(1.f-sp))*w;
                    sp = sigm(vq.z); v.z = -INV_M*(dp.z*sp - dn.z*(1.f-sp))*w;
                    sp = sigm(vq.w); v.w = -INV_M*(dp.w*sp - dn.w*(1.f-sp))*w;
                } else if (seg == 1) {
                    v = *reinterpret_cast<const float4*>(&ga.p2[(size_t)r*128 + cc]);
                } else if (seg == 2) {
                    v = *reinterpret_cast<const float4*>(&ga.p3[(size_t)r*128 + cc]);
                    float w = ga.p4[r];
                    v.x*=w; v.y*=w; v.z*=w; v.w*=w;
                } else {
                    v = *reinterpret_cast<const float4*>(&ga.p3[(size_t)(r+NV)*128 + cc]);
                    float w = ga.p4[r+NV];
                    v.x*=w; v.y*=w; v.z*=w; v.w*=w;
                }
            }
            aReg[i] = v;
        }
    };
    auto cpB = [&](int c){
        const int k0 = c << 5;
        const uint32_t bb = sbase + B0 + (uint32_t)(c % 3)*(2*HALF);
        int row = t >> 2, q = t & 3;          // 512 = 128 rows x 4 chunks
        int gk = k0 + q*8;
        bool ok = (gk + 8 <= KP);
        size_t off = ok ? ((size_t)(bn+row)*KP + gk) : 0;
        uint32_t d = bb + (uint32_t)(row*LDH + q*8)*2;
        cp16(d,        Bhg + off, ok);
        cp16(d + HALF, Blg + off, ok);
    };
    auto storeA = [&](int s){
        char* sc = smem + A0 + s*(2*HALF);
        #pragma unroll
        for (int i = 0; i < 2; i++) {
            int idx = t + i*GEMM_THREADS;
            int row = idx >> 3, col4 = (idx & 7) << 2;
            uint32_t h0 = pack_bf16x2(aReg[i].x, aReg[i].y);
            uint32_t h1 = pack_bf16x2(aReg[i].z, aReg[i].w);
            float hx = __uint_as_float(h0 << 16);
            float hy = __uint_as_float(h0 & 0xffff0000u);
            float hz = __uint_as_float(h1 << 16);
            float hw = __uint_as_float(h1 & 0xffff0000u);
            uint32_t l0 = pack_bf16x2(aReg[i].x - hx, aReg[i].y - hy);
            uint32_t l1 = pack_bf16x2(aReg[i].z - hz, aReg[i].w - hw);
            int boff = (row*LDH + col4)*2;
            *reinterpret_cast<uint2*>(sc + boff)        = make_uint2(h0,h1);
            *reinterpret_cast<uint2*>(sc + HALF + boff) = make_uint2(l0,l1);
        }
    };
    auto compute = [&](int c){
        const uint32_t sa = sbase + A0 + (uint32_t)(c & 1)*(2*HALF);
        const uint32_t sb = sbase + B0 + (uint32_t)(c % 3)*(2*HALF);
        const int grp = lane >> 3, r = lane & 7;
        #pragma unroll
        for (int ks = 0; ks < 32; ks += 16) {
            uint32_t aH[2][4], aL[2][4], bH[4][2], bL[4][2];
            #pragma unroll
            for (int mt = 0; mt < 2; mt++) {
                int arow = warp_m*32 + mt*16 + (grp & 1)*8 + r;
                int acol = ks + (grp >> 1)*8;
                uint32_t adr = sa + (uint32_t)(arow*LDH + acol)*2;
                ldsm4(aH[mt], adr);
                ldsm4(aL[mt], adr + HALF);
            }
            #pragma unroll
            for (int p = 0; p < 2; p++) {
                int brow = warp_n*32 + p*16 + (grp >> 1)*8 + r;
                int bcol = ks + (grp & 1)*8;
                uint32_t adr = sb + (uint32_t)(brow*LDH + bcol)*2;
                uint32_t tmp[4];
                ldsm4(tmp, adr);
                bH[2*p][0]=tmp[0]; bH[2*p][1]=tmp[1]; bH[2*p+1][0]=tmp[2]; bH[2*p+1][1]=tmp[3];
                ldsm4(tmp, adr + HALF);
                bL[2*p][0]=tmp[0]; bL[2*p][1]=tmp[1]; bL[2*p+1][0]=tmp[2]; bL[2*p+1][1]=tmp[3];
            }
            #pragma unroll
            for (int mt = 0; mt < 2; mt++)
                #pragma unroll
                for (int nt = 0; nt < 4; nt++) {
                    mma_bf16(acc[mt][nt], aH[mt], bH[nt]);
                    mma_bf16(acc[mt][nt], aH[mt], bL[nt]);
                    mma_bf16(acc[mt][nt], aL[mt], bH[nt]);
                }
        }
    };

    loadA(0);
    cpB(0);
    CP_COMMIT();
    storeA(0);
    if (nch > 1) { loadA(1); cpB(1); }
    CP_COMMIT();
    CP_WAIT1();
    __syncthreads();

    for (int c = 0; c < nch; c++) {
        compute(c);
        if (c+1 < nch) storeA((c+1) & 1);
        if (c+2 < nch) cpB(c+2);
        CP_COMMIT();
        if (c+2 < nch) loadA(c+2);
        CP_WAIT1();
        __syncthreads();
    }

    if (EPI == 0) {
        #pragma unroll
        for (int mt = 0; mt < 2; mt++) {
            int row0 = bm + warp_m*32 + mt*16 + (lane >> 2);
            #pragma unroll
            for (int nt = 0; nt < 4; nt++) {
                int col = bn + warp_n*32 + nt*8 + (lane & 3)*2;
                float2 bv = *reinterpret_cast<const float2*>(&bias[col]);
                float v0 = acc[mt][nt][0] + bv.x, v1 = acc[mt][nt][1] + bv.y;
                float v2 = acc[mt][nt][2] + bv.x, v3 = acc[mt][nt][3] + bv.y;
                if (relu) { v0=fmaxf(v0,0.f); v1=fmaxf(v1,0.f); v2=fmaxf(v2,0.f); v3=fmaxf(v3,0.f); }
                *reinterpret_cast<float2*>(&C[(size_t)row0*Ntot + col])     = make_float2(v0,v1);
                *reinterpret_cast<float2*>(&C[(size_t)(row0+8)*Ntot + col]) = make_float2(v2,v3);
            }
        }
    } else {
        float* red = reinterpret_cast<float*>(smem);
        if (t < 128) red[t] = 0.f;
        __syncthreads();
        #pragma unroll
        for (int mt = 0; mt < 2; mt++) {
            int rl = warp_m*32 + mt*16 + (lane >> 2);
            float p0 = 0.f, p1 = 0.f;
            #pragma unroll
            for (int nt = 0; nt < 4; nt++) {
                int col = warp_n*32 + nt*8 + (lane & 3)*2;
                float2 bv = *reinterpret_cast<const float2*>(&bias[col]);
                float wa = __ldg(&w1[col]), wb = __ldg(&w1[col+1]);
                float v0 = fmaxf(acc[mt][nt][0] + bv.x, 0.f);
                float v1 = fmaxf(acc[mt][nt][1] + bv.y, 0.f);
                float v2 = fmaxf(acc[mt][nt][2] + bv.x, 0.f);
                float v3 = fmaxf(acc[mt][nt][3] + bv.y, 0.f);
                p0 += v0*wa + v1*wb;
                p1 += v2*wa + v3*wb;
            }
            atomicAdd(&red[rl], p0);
            atomicAdd(&red[rl+8], p1);
        }
        __syncthreads();
        if (t < 128) {
            float x = red[t] + __ldg(&b1[0]);
            int row = bm + t;
            out[(size_t)round*NC + row] = sigm(x);
            out[(size_t)4*NC + (size_t)round*NC + row] = softplusf(x);
        }
    }
}

// ---------------- setup kernels (exactly 3 launches; launch #4 = first k_mma) ----------------
__global__ void k_init(float* p, size_t nfill){
    size_t i = (size_t)blockIdx.x*blockDim.x + threadIdx.x;
    if (i < nfill) p[i] = 1.f;
    if (i < NL) g_deg[i] = 0;
}
__global__ void k_count_csr(const int* __restrict__ lit, const int* __restrict__ cls){
    int e = blockIdx.x*blockDim.x + threadIdx.x;
    if (e >= NE) return;
    int l = lit[e];
    int pos = atomicAdd(&g_deg[l], 1);
    if (pos < CSR_W) g_csr[(size_t)l*CSR_W + pos] = cls[e];
}
struct WSrc { const float* w[10]; };
__global__ void k_weights_wsplit(WSrc ws, __nv_bfloat16* __restrict__ hi,
                                 __nv_bfloat16* __restrict__ lo){
    const int offs[11] = {0, 17408, 33792, 51200, 67584, 165888, 231424,
                          362496, 428032, 460800, 477184};
    const int Ks[10]  = {132,128,132,128,384,256,512,256,256,128};
    const int KPs[10] = {136,128,136,128,384,256,512,256,256,128};
    const int Ns[10]  = {128,128,128,128,256,256,256,256,128,128};
    int idx = blockIdx.x*blockDim.x + threadIdx.x;
    if (idx < NL) g_ws[O_DEGW + idx] = rsqrtf(fmaxf((float)g_deg[idx], 1.f));
    if (idx < NV) g_ws[O_VDEGW + idx] = 4.f*rsqrtf(fmaxf((float)(g_deg[idx] + g_deg[idx+NV]), 1.f));
    if (idx >= offs[10]) return;
    int seg = 0;
    #pragma unroll
    for (int s = 1; s < 10; s++) if (idx >= offs[s]) seg = s;
    int local = idx - offs[seg];
    int K = Ks[seg], KP = KPs[seg], N = Ns[seg];
    int n = local / KP, k = local % KP;
    float v = (k < K) ? ws.w[seg][(size_t)k*N + n] : 0.f;
    __nv_bfloat16 h = __float2bfloat16(v);
    hi[idx] = h;
    lo[idx] = __float2bfloat16(v - __bfloat162float(h));
}

// ---------------- misc kernels ----------------
__global__ void k_zero(float* p, size_t n){
    size_t i = (size_t)blockIdx.x*blockDim.x + threadIdx.x;
    if (i < n) p[i] = 0.f;
}
__global__ void k_csum_loss(const int* __restrict__ lit, const int* __restrict__ cls){
    const int c = blockIdx.x, f = threadIdx.x;
    __shared__ int se[2];
    if (f < 2) {
        int key = c + f;
        int lo = 0, hi = NE;
        while (lo < hi) { int mid = (lo+hi) >> 1; if (cls[mid] < key) lo = mid+1; else hi = mid; }
        se[f] = lo;
    }
    __syncthreads();
    float csum = 0.f;
    for (int e = se[0]; e < se[1]; e++) {
        int l = lit[e];
        float z = (l < NV) ? g_ws[O_VQ + (size_t)l*128 + f]
                           : -g_ws[O_VQ + (size_t)(l-NV)*128 + f];
        csum += softplusf(z);
    }
    size_t i = (size_t)c*128 + f;
    float s = sigm(g_ws[O_CQ + i]);
    float l = expf(-csum) * s;
    g_ws[O_LOSS + i]  = l;
    g_ws[O_CGRAD + i] = l * (1.f - s) * INV_M;
}
__global__ void k_gather(const float* __restrict__ src, int sstride,
                         float* __restrict__ dst){
    const int l = blockIdx.x, f = threadIdx.x;
    int d = g_deg[l];
    if (d > CSR_W) d = CSR_W;
    float s = 0.f;
    for (int j = 0; j < d; j++) {
        int c = g_csr[(size_t)l*CSR_W + j];
        s += src[(size_t)c*sstride + f];
    }
    dst[(size_t)l*128 + f] = s;
}
__global__ void k_pn_stats(const float* __restrict__ x, int stride, int off, int n){
    int f = threadIdx.x;
    float s = 0.f, q = 0.f;
    for (int r = blockIdx.x; r < n; r += gridDim.x) {
        float v = x[(size_t)r*stride + off + f];
        s += v; q += v*v;
    }
    atomicAdd(&g_ws[O_STAT + f], s);
    atomicAdd(&g_ws[O_STAT + 128 + f], q);
}
__global__ void k_pn_scale(float n){
    int f = threadIdx.x;
    float mean = g_ws[O_STAT + f] / n;
    float var  = g_ws[O_STAT + 128 + f] / n - mean*mean;
    __shared__ float sh[128];
    sh[f] = var; __syncthreads();
    for (int s = 64; s > 0; s >>= 1) { if (f < s) sh[f] += sh[f+s]; __syncthreads(); }
    g_ws[O_STAT + f] = mean;
    if (f == 0) g_ws[O_STAT + 256] = rsqrtf(sh[0]*(1.f/128.f) + 1e-6f);
}
__global__ void k_pn_apply(const float* __restrict__ x, int stride, int off,
                           float* __restrict__ dst){
    int r = blockIdx.x, f = threadIdx.x;
    float scale = g_ws[O_STAT + 256];
    float v = (x[(size_t)r*stride + off + f] - g_ws[O_STAT + f]) * scale;
    size_t i = (size_t)r*128 + f;
    dst[i] = v*0.25f + 0.1f*dst[i];
}

// ---------------- host ----------------
template<int MODE, int EPI>
static void mmgemm(GArgs ga, const __nv_bfloat16* Bh, const __nv_bfloat16* Bl,
                   const float* bias, float* C, int M, int K, int KP, int Ntot, int relu,
                   float* out = nullptr, int round = 0,
                   const float* w1 = nullptr, const float* b1 = nullptr){
    cudaFuncSetAttribute(k_mma<MODE,EPI>, cudaFuncAttributeMaxDynamicSharedMemorySize, GEMM_SMEM);
    dim3 grid(Ntot/128, M/128);
    k_mma<MODE,EPI><<<grid, GEMM_THREADS, GEMM_SMEM>>>(ga, Bh, Bl, bias, C, K, KP, Ntot, relu,
                                                       out, round, w1, b1);
}

extern "C" void kernel_launch(void* const* d_in, const int* in_sizes, int n_in,
                              void* d_out, int out_size)
{
    (void)in_sizes; (void)n_in; (void)out_size;
    const int*   edge_lit    = (const int*)d_in[0];
    const int*   edge_clause = (const int*)d_in[1];
    const float* noise_v = (const float*)d_in[2];
    const float* noise_c = (const float*)d_in[3];
    const float* vq_w0 = (const float*)d_in[4];  const float* vq_b0 = (const float*)d_in[5];
    const float* vq_w1 = (const float*)d_in[6];  const float* vq_b1 = (const float*)d_in[7];
    const float* cq_w0 = (const float*)d_in[8];  const float* cq_b0 = (const float*)d_in[9];
    const float* cq_w1 = (const float*)d_in[10]; const float* cq_b1 = (const float*)d_in[11];
    const float* cm_w0 = (const float*)d_in[12]; const float* cm_b0 = (const float*)d_in[13];
    const float* cm_w1 = (const float*)d_in[14]; const float* cm_b1 = (const float*)d_in[15];
    const float* ug_w0 = (const float*)d_in[16]; const float* ug_b0 = (const float*)d_in[17];
    const float* ug_w1 = (const float*)d_in[18]; const float* ug_b1 = (const float*)d_in[19];
    const float* ug_w2 = (const float*)d_in[20]; const float* ug_b2 = (const float*)d_in[21];
    const float* co_w0 = (const float*)d_in[22]; const float* co_b0 = (const float*)d_in[23];
    const float* co_w1 = (const float*)d_in[24]; const float* co_b1 = (const float*)d_in[25];
    float* out = (float*)d_out;

    float* ws; cudaGetSymbolAddress((void**)&ws, g_ws);
    __nv_bfloat16* wh = reinterpret_cast<__nv_bfloat16*>(ws + O_WT);
    __nv_bfloat16* wl = wh + WH_TOTAL;

    // ---- setup: exactly 3 launches (first k_mma is graph launch #4) ----
    {
        size_t n = (size_t)(NV+NC)*128;
        k_init<<<(unsigned)((n+255)/256), 256>>>(ws + O_VARS, n);
    }
    k_count_csr<<<(NE+255)/256, 256>>>(edge_lit, edge_clause);
    {
        WSrc s;
        s.w[0]=vq_w0; s.w[1]=vq_w1; s.w[2]=cq_w0; s.w[3]=cq_w1; s.w[4]=cm_w0;
        s.w[5]=cm_w1; s.w[6]=ug_w0; s.w[7]=ug_w1; s.w[8]=ug_w2; s.w[9]=co_w0;
        k_weights_wsplit<<<(OW_END+255)/256, 256>>>(s, wh, wl);
    }

    for (int r = 0; r < 4; r++) {
        const float* nv_r = noise_v + (size_t)r*NV*4;
        const float* nc_r = noise_c + (size_t)r*NC*4;
        GArgs ga{};

        ga = {ws+O_CLS, nc_r, 0, 0, 0, 0};
        mmgemm<M_CAT4,0>(ga, wh+OW_cq0, wl+OW_cq0, cq_b0, ws+O_HC, NC, 132, 136, 128, 1);
        ga = {ws+O_HC, 0, 0, 0, 0, 0};
        mmgemm<M_PLAIN,0>(ga, wh+OW_cq1, wl+OW_cq1, cq_b1, ws+O_CQ, NC, 128, 128, 128, 0);
        ga = {ws+O_VARS, nv_r, 0, 0, 0, 0};
        mmgemm<M_CAT4,0>(ga, wh+OW_vq0, wl+OW_vq0, vq_b0, ws+O_HV, NV, 132, 136, 128, 1);
        ga = {ws+O_HV, 0, 0, 0, 0, 0};
        mmgemm<M_PLAIN,0>(ga, wh+OW_vq1, wl+OW_vq1, vq_b1, ws+O_VQ, NV, 128, 128, 128, 0);

        k_csum_loss<<<NC, 128>>>(edge_lit, edge_clause);
        k_gather<<<NL, 128>>>(ws+O_LOSS, 128, ws+O_DLITS);

        ga = {ws+O_CLS, ws+O_LOSS, ws+O_CGRAD, 0, 0, 0};
        mmgemm<M_CMIN,0>(ga, wh+OW_cm0, wl+OW_cm0, cm_b0, ws+O_HC, NC, 384, 384, 256, 1);
        ga = {ws+O_HC, 0, 0, 0, 0, 0};
        mmgemm<M_PLAIN,0>(ga, wh+OW_cm1, wl+OW_cm1, cm_b1, ws+O_CDATA, NC, 256, 256, 256, 0);

        k_gather<<<NL, 128>>>(ws+O_CDATA, 256, ws+O_VL);

        k_zero<<<2, 256>>>(ws+O_STAT, 257);
        k_pn_stats<<<512, 128>>>(ws+O_CDATA, 256, 128, NC);
        k_pn_scale<<<1, 128>>>((float)NC);
        k_pn_apply<<<NC, 128>>>(ws+O_CDATA, 256, 128, ws+O_CLS);

        ga = {ws+O_VQ, ws+O_DLITS, ws+O_VARS, ws+O_VL, ws+O_DEGW, ws+O_VDEGW};
        mmgemm<M_UNIT,0>(ga, wh+OW_ug0, wl+OW_ug0, ug_b0, ws+O_HV, NV, 512, 512, 256, 1);
        ga = {ws+O_HV, 0, 0, 0, 0, 0};
        mmgemm<M_PLAIN,0>(ga, wh+OW_ug1, wl+OW_ug1, ug_b1, ws+O_HV2, NV, 256, 256, 256, 1);
        ga = {ws+O_HV2, 0, 0, 0, 0, 0};
        mmgemm<M_PLAIN,0>(ga, wh+OW_ug2, wl+OW_ug2, ug_b2, ws+O_VOUT, NV, 256, 256, 128, 0);

        k_zero<<<2, 256>>>(ws+O_STAT, 257);
        k_pn_stats<<<512, 128>>>(ws+O_VOUT, 128, 0, NV);
        k_pn_scale<<<1, 128>>>((float)NV);
        k_pn_apply<<<NV, 128>>>(ws+O_VOUT, 128, 0, ws+O_VARS);

        ga = {ws+O_CLS, 0, 0, 0, 0, 0};
        mmgemm<M_PLAIN,1>(ga, wh+OW_co0, wl+OW_co0, co_b0, nullptr, NC, 128, 128, 128, 1,
                          out, r, co_w1, co_b1);
    }
}

// round 9
// speedup vs baseline: 1.5709x; 1.2649x over previous
#include <cuda_runtime.h>
#include <cuda_fp16.h>
#include <math.h>
#include <stdint.h>

#define NV 24576
#define NC 98304
#define NE 294912
#define NL 49152              // 2*NV
#define INV_M (1.0f/12582912.0f)   // 1/(NC*128)
#define CSR_W 40

// ---------------- workspace layout (floats) ----------------
static constexpr size_t O_VARS   = 0;
static constexpr size_t O_CLS    = O_VARS  + (size_t)NV*128;
static constexpr size_t O_HV     = O_CLS   + (size_t)NC*128;   // NV x 256
static constexpr size_t O_HV2    = O_HV    + (size_t)NV*256;   // NV x 256
static constexpr size_t O_VQ     = O_HV2   + (size_t)NV*256;
static constexpr size_t O_HC     = O_VQ    + (size_t)NV*128;   // NC x 256
static constexpr size_t O_CQ     = O_HC    + (size_t)NC*256;
static constexpr size_t O_CGRAD  = O_CQ    + (size_t)NC*128;
static constexpr size_t O_LOSS   = O_CGRAD + (size_t)NC*128;
static constexpr size_t O_CDATA  = O_LOSS  + (size_t)NC*128;   // NC x 256
static constexpr size_t O_DLITS  = O_CDATA + (size_t)NC*256;   // NL x 128
static constexpr size_t O_VL     = O_DLITS + (size_t)NL*128;   // NL x 128
static constexpr size_t O_VOUT   = O_VL    + (size_t)NL*128;   // NV x 128
static constexpr size_t O_DEGW   = O_VOUT  + (size_t)NV*128;   // NL
static constexpr size_t O_VDEGW  = O_DEGW  + NL;               // NV
static constexpr size_t O_STAT   = O_VDEGW + NV;               // 128 sum, 128 ssq, 1 scale
static constexpr size_t O_WT     = O_STAT  + 260;              // fp16 weights
static constexpr size_t WS_TOTAL = O_WT + 240000;

// weight offsets in HALVES within the fp16 array ([N][KP] row-major)
static constexpr size_t OW_vq0 = 0;
static constexpr size_t OW_vq1 = 17408;
static constexpr size_t OW_cq0 = 33792;
static constexpr size_t OW_cq1 = 51200;
static constexpr size_t OW_cm0 = 67584;
static constexpr size_t OW_cm1 = 165888;
static constexpr size_t OW_ug0 = 231424;
static constexpr size_t OW_ug1 = 362496;
static constexpr size_t OW_ug2 = 428032;
static constexpr size_t OW_co0 = 460800;
static constexpr int    OW_END = 477184;

__device__ float g_ws[WS_TOTAL];
__device__ int   g_deg[NL];
__device__ int   g_csr[(size_t)NL * CSR_W];

// ---------------- PTX helpers ----------------
__device__ __forceinline__ uint32_t smem_u32(const void* p){
    uint32_t a;
    asm("{ .reg .u64 t; cvta.to.shared.u64 t, %1; cvt.u32.u64 %0, t; }" : "=r"(a) : "l"(p));
    return a;
}
__device__ __forceinline__ void ldsm4(uint32_t* r, uint32_t addr){
    asm volatile("ldmatrix.sync.aligned.m8n8.x4.shared.b16 {%0,%1,%2,%3}, [%4];"
        : "=r"(r[0]), "=r"(r[1]), "=r"(r[2]), "=r"(r[3]) : "r"(addr));
}
__device__ __forceinline__ void mma_f16(float* c, const uint32_t* a, const uint32_t* b){
    asm volatile("mma.sync.aligned.m16n8k16.row.col.f32.f16.f16.f32 "
        "{%0,%1,%2,%3}, {%4,%5,%6,%7}, {%8,%9}, {%0,%1,%2,%3};"
        : "+f"(c[0]), "+f"(c[1]), "+f"(c[2]), "+f"(c[3])
        : "r"(a[0]), "r"(a[1]), "r"(a[2]), "r"(a[3]), "r"(b[0]), "r"(b[1]));
}
__device__ __forceinline__ void cp16(uint32_t dst, const void* src, bool pred){
    int sz = pred ? 16 : 0;
    asm volatile("cp.async.cg.shared.global [%0], [%1], 16, %2;"
                 :: "r"(dst), "l"(src), "r"(sz));
}
#define CP_COMMIT() asm volatile("cp.async.commit_group;" ::: "memory")
#define CP_WAIT1()  asm volatile("cp.async.wait_group 1;" ::: "memory")

__device__ __forceinline__ float sigm(float x){ return 1.f/(1.f+expf(-x)); }
__device__ __forceinline__ float softplusf(float x){ return fmaxf(x,0.f)+log1pf(expf(-fabsf(x))); }

// A-loader modes
#define M_PLAIN 0
#define M_CAT4  1
#define M_CMIN  2
#define M_UNIT  3

struct GArgs {
    const float* p0; const float* p1; const float* p2;
    const float* p3; const float* p4; const float* p5;
};

// ---------------- single-pass fp16 MMA GEMM, 512 threads / 16 warps ----------------
// smem: A 2-stage [0,20480), B 3-buf [20480,51200)
static constexpr int GEMM_SMEM = 51200;
static constexpr int GEMM_THREADS = 512;

template<int MODE, int EPI>
__global__ void __launch_bounds__(GEMM_THREADS, 1)
k_mma(GArgs ga, const __half* __restrict__ Bg, const float* __restrict__ bias,
      float* __restrict__ C, int K, int KP, int Ntot, int relu,
      float* __restrict__ out, int round,
      const float* __restrict__ w1, const float* __restrict__ b1)
{
    extern __shared__ __align__(16) char smem[];
    const uint32_t sbase = smem_u32(smem);
    const int t = threadIdx.x;
    const int lane = t & 31, wid = t >> 5;
    const int warp_m = wid & 3;        // 4 x 32 rows
    const int warp_n = wid >> 2;       // 4 x 32 cols
    const int bm = blockIdx.y * 128;
    const int bn = blockIdx.x * 128;

    constexpr int LDH   = 40;
    constexpr int PLANE = 10240;    // one 128x32 fp16 plane (with pad)
    constexpr int A0    = 0;        // A stage s at s*PLANE
    constexpr int B0    = 20480;    // B buf b at B0+b*PLANE

    float acc[2][4][4];
    #pragma unroll
    for (int i=0;i<2;i++)
        #pragma unroll
        for(int j=0;j<4;j++)
            #pragma unroll
            for(int q=0;q<4;q++) acc[i][j][q]=0.f;

    const int nch = (K + 31) >> 5;
    float4 aReg[2];

    auto loadA = [&](int c){
        const int k0 = c << 5;
        #pragma unroll
        for (int i = 0; i < 2; i++) {
            int idx = t + i*GEMM_THREADS;
            int row = idx >> 3, col4 = (idx & 7) << 2;
            int gk = k0 + col4;
            int r = bm + row;
            float4 v = make_float4(0.f,0.f,0.f,0.f);
            if (MODE == M_PLAIN) {
                if (gk < K) v = *reinterpret_cast<const float4*>(&ga.p0[(size_t)r*K + gk]);
            } else if (MODE == M_CAT4) {
                if (gk < 128)       v = *reinterpret_cast<const float4*>(&ga.p0[(size_t)r*128 + gk]);
                else if (gk == 128) v = *reinterpret_cast<const float4*>(&ga.p1[(size_t)r*4]);
            } else if (MODE == M_CMIN) {
                int seg = gk >> 7, cc = gk & 127;
                if (seg == 0)      v = *reinterpret_cast<const float4*>(&ga.p0[(size_t)r*128 + cc]);
                else if (seg == 1) {
                    v = *reinterpret_cast<const float4*>(&ga.p1[(size_t)r*128 + cc]);
                    v.x*=4.f; v.y*=4.f; v.z*=4.f; v.w*=4.f;
                } else             v = *reinterpret_cast<const float4*>(&ga.p2[(size_t)r*128 + cc]);
            } else { // M_UNIT
                int seg = gk >> 7, cc = gk & 127;
                if (seg == 0) {
                    float4 vq = *reinterpret_cast<const float4*>(&ga.p0[(size_t)r*128 + cc]);
                    float4 dp = *reinterpret_cast<const float4*>(&ga.p1[(size_t)r*128 + cc]);
                    float4 dn = *reinterpret_cast<const float4*>(&ga.p1[(size_t)(r+NV)*128 + cc]);
                    float w = ga.p5[r];
                    float sp;
                    sp = sigm(vq.x); v.x = -INV_M*(dp.x*sp - dn.x*(1.f-sp))*w;
                    sp = sigm(vq.y); v.y = -INV_M*(dp.y*sp - dn.y*(1.f-sp))*w;
                    sp = sigm(vq.z); v.z = -INV_M*(dp.z*sp - dn.z*(1.f-sp))*w;
                    sp = sigm(vq.w); v.w = -INV_M*(dp.w*sp - dn.w*(1.f-sp))*w;
                } else if (seg == 1) {
                    v = *reinterpret_cast<const float4*>(&ga.p2[(size_t)r*128 + cc]);
                } else if (seg == 2) {
                    v = *reinterpret_cast<const float4*>(&ga.p3[(size_t)r*128 + cc]);
                    float w = ga.p4[r];
                    v.x*=w; v.y*=w; v.z*=w; v.w*=w;
                } else {
                    v = *reinterpret_cast<const float4*>(&ga.p3[(size_t)(r+NV)*128 + cc]);
                    float w = ga.p4[r+NV];
                    v.x*=w; v.y*=w; v.z*=w; v.w*=w;
                }
            }
            aReg[i] = v;
        }
    };
    auto cpB = [&](int c){
        const int k0 = c << 5;
        const uint32_t bb = sbase + B0 + (uint32_t)(c % 3)*PLANE;
        int row = t >> 2, q = t & 3;          // 512 = 128 rows x 4 x 16B
        int gk = k0 + q*8;
        bool ok = (gk + 8 <= KP);
        size_t off = ok ? ((size_t)(bn+row)*KP + gk) : 0;
        cp16(bb + (uint32_t)(row*LDH + q*8)*2, Bg + off, ok);
    };
    auto storeA = [&](int s){
        char* sc = smem + A0 + s*PLANE;
        #pragma unroll
        for (int i = 0; i < 2; i++) {
            int idx = t + i*GEMM_THREADS;
            int row = idx >> 3, col4 = (idx & 7) << 2;
            __half2 h0 = __floats2half2_rn(aReg[i].x, aReg[i].y);
            __half2 h1 = __floats2half2_rn(aReg[i].z, aReg[i].w);
            uint2 pk;
            pk.x = *reinterpret_cast<uint32_t*>(&h0);
            pk.y = *reinterpret_cast<uint32_t*>(&h1);
            *reinterpret_cast<uint2*>(sc + (row*LDH + col4)*2) = pk;
        }
    };
    auto compute = [&](int c){
        const uint32_t sa = sbase + A0 + (uint32_t)(c & 1)*PLANE;
        const uint32_t sb = sbase + B0 + (uint32_t)(c % 3)*PLANE;
        const int grp = lane >> 3, r = lane & 7;
        #pragma unroll
        for (int ks = 0; ks < 32; ks += 16) {
            uint32_t aH[2][4], bX[4][2];
            #pragma unroll
            for (int mt = 0; mt < 2; mt++) {
                int arow = warp_m*32 + mt*16 + (grp & 1)*8 + r;
                int acol = ks + (grp >> 1)*8;
                ldsm4(aH[mt], sa + (uint32_t)(arow*LDH + acol)*2);
            }
            #pragma unroll
            for (int p = 0; p < 2; p++) {
                int brow = warp_n*32 + p*16 + (grp >> 1)*8 + r;
                int bcol = ks + (grp & 1)*8;
                uint32_t tmp[4];
                ldsm4(tmp, sb + (uint32_t)(brow*LDH + bcol)*2);
                bX[2*p][0]=tmp[0]; bX[2*p][1]=tmp[1]; bX[2*p+1][0]=tmp[2]; bX[2*p+1][1]=tmp[3];
            }
            #pragma unroll
            for (int mt = 0; mt < 2; mt++)
                #pragma unroll
                for (int nt = 0; nt < 4; nt++)
                    mma_f16(acc[mt][nt], aH[mt], bX[nt]);
        }
    };

    loadA(0);
    cpB(0);
    CP_COMMIT();
    storeA(0);
    if (nch > 1) { loadA(1); cpB(1); }
    CP_COMMIT();
    CP_WAIT1();
    __syncthreads();

    for (int c = 0; c < nch; c++) {
        compute(c);
        if (c+1 < nch) storeA((c+1) & 1);
        if (c+2 < nch) cpB(c+2);
        CP_COMMIT();
        if (c+2 < nch) loadA(c+2);
        CP_WAIT1();
        __syncthreads();
    }

    if (EPI == 0) {
        #pragma unroll
        for (int mt = 0; mt < 2; mt++) {
            int row0 = bm + warp_m*32 + mt*16 + (lane >> 2);
            #pragma unroll
            for (int nt = 0; nt < 4; nt++) {
                int col = bn + warp_n*32 + nt*8 + (lane & 3)*2;
                float2 bv = *reinterpret_cast<const float2*>(&bias[col]);
                float v0 = acc[mt][nt][0] + bv.x, v1 = acc[mt][nt][1] + bv.y;
                float v2 = acc[mt][nt][2] + bv.x, v3 = acc[mt][nt][3] + bv.y;
                if (relu) { v0=fmaxf(v0,0.f); v1=fmaxf(v1,0.f); v2=fmaxf(v2,0.f); v3=fmaxf(v3,0.f); }
                *reinterpret_cast<float2*>(&C[(size_t)row0*Ntot + col])     = make_float2(v0,v1);
                *reinterpret_cast<float2*>(&C[(size_t)(row0+8)*Ntot + col]) = make_float2(v2,v3);
            }
        }
    } else {
        float* red = reinterpret_cast<float*>(smem);
        if (t < 128) red[t] = 0.f;
        __syncthreads();
        #pragma unroll
        for (int mt = 0; mt < 2; mt++) {
            int rl = warp_m*32 + mt*16 + (lane >> 2);
            float p0 = 0.f, p1 = 0.f;
            #pragma unroll
            for (int nt = 0; nt < 4; nt++) {
                int col = warp_n*32 + nt*8 + (lane & 3)*2;
                float2 bv = *reinterpret_cast<const float2*>(&bias[col]);
                float wa = __ldg(&w1[col]), wb = __ldg(&w1[col+1]);
                float v0 = fmaxf(acc[mt][nt][0] + bv.x, 0.f);
                float v1 = fmaxf(acc[mt][nt][1] + bv.y, 0.f);
                float v2 = fmaxf(acc[mt][nt][2] + bv.x, 0.f);
                float v3 = fmaxf(acc[mt][nt][3] + bv.y, 0.f);
                p0 += v0*wa + v1*wb;
                p1 += v2*wa + v3*wb;
            }
            atomicAdd(&red[rl], p0);
            atomicAdd(&red[rl+8], p1);
        }
        __syncthreads();
        if (t < 128) {
            float x = red[t] + __ldg(&b1[0]);
            int row = bm + t;
            out[(size_t)round*NC + row] = sigm(x);
            out[(size_t)4*NC + (size_t)round*NC + row] = softplusf(x);
        }
    }
}

// ---------------- setup kernels (exactly 3 launches; launch #4 = first k_mma) ----------------
__global__ void k_init(float* p, size_t nfill){
    size_t i = (size_t)blockIdx.x*blockDim.x + threadIdx.x;
    if (i < nfill) p[i] = 1.f;
    if (i < NL) g_deg[i] = 0;
}
__global__ void k_count_csr(const int* __restrict__ lit, const int* __restrict__ cls){
    int e = blockIdx.x*blockDim.x + threadIdx.x;
    if (e >= NE) return;
    int l = lit[e];
    int pos = atomicAdd(&g_deg[l], 1);
    if (pos < CSR_W) g_csr[(size_t)l*CSR_W + pos] = cls[e];
}
struct WSrc { const float* w[10]; };
__global__ void k_weights_wsplit(WSrc ws, __half* __restrict__ w16){
    const int offs[11] = {0, 17408, 33792, 51200, 67584, 165888, 231424,
                          362496, 428032, 460800, 477184};
    const int Ks[10]  = {132,128,132,128,384,256,512,256,256,128};
    const int KPs[10] = {136,128,136,128,384,256,512,256,256,128};
    const int Ns[10]  = {128,128,128,128,256,256,256,256,128,128};
    int idx = blockIdx.x*blockDim.x + threadIdx.x;
    if (idx < NL) g_ws[O_DEGW + idx] = rsqrtf(fmaxf((float)g_deg[idx], 1.f));
    if (idx < NV) g_ws[O_VDEGW + idx] = 4.f*rsqrtf(fmaxf((float)(g_deg[idx] + g_deg[idx+NV]), 1.f));
    if (idx >= offs[10]) return;
    int seg = 0;
    #pragma unroll
    for (int s = 1; s < 10; s++) if (idx >= offs[s]) seg = s;
    int local = idx - offs[seg];
    int K = Ks[seg], KP = KPs[seg], N = Ns[seg];
    int n = local / KP, k = local % KP;
    float v = (k < K) ? ws.w[seg][(size_t)k*N + n] : 0.f;
    w16[idx] = __float2half_rn(v);
}

// ---------------- misc kernels ----------------
__global__ void k_zero(float* p, size_t n){
    size_t i = (size_t)blockIdx.x*blockDim.x + threadIdx.x;
    if (i < n) p[i] = 0.f;
}
__global__ void k_csum_loss(const int* __restrict__ lit, const int* __restrict__ cls){
    const int c = blockIdx.x, f = threadIdx.x;
    __shared__ int se[2];
    if (f < 2) {
        int key = c + f;
        int lo = 0, hi = NE;
        while (lo < hi) { int mid = (lo+hi) >> 1; if (cls[mid] < key) lo = mid+1; else hi = mid; }
        se[f] = lo;
    }
    __syncthreads();
    float csum = 0.f;
    for (int e = se[0]; e < se[1]; e++) {
        int l = lit[e];
        float z = (l < NV) ? g_ws[O_VQ + (size_t)l*128 + f]
                           : -g_ws[O_VQ + (size_t)(l-NV)*128 + f];
        csum += softplusf(z);
    }
    size_t i = (size_t)c*128 + f;
    float s = sigm(g_ws[O_CQ + i]);
    float l = expf(-csum) * s;
    g_ws[O_LOSS + i]  = l;
    g_ws[O_CGRAD + i] = l * (1.f - s) * INV_M;
}
__global__ void k_gather(const float* __restrict__ src, int sstride,
                         float* __restrict__ dst){
    const int l = blockIdx.x, f = threadIdx.x;
    int d = g_deg[l];
    if (d > CSR_W) d = CSR_W;
    float s = 0.f;
    for (int j = 0; j < d; j++) {
        int c = g_csr[(size_t)l*CSR_W + j];
        s += src[(size_t)c*sstride + f];
    }
    dst[(size_t)l*128 + f] = s;
}
__global__ void k_pn_stats(const float* __restrict__ x, int stride, int off, int n){
    int f = threadIdx.x;
    float s = 0.f, q = 0.f;
    for (int r = blockIdx.x; r < n; r += gridDim.x) {
        float v = x[(size_t)r*stride + off + f];
        s += v; q += v*v;
    }
    atomicAdd(&g_ws[O_STAT + f], s);
    atomicAdd(&g_ws[O_STAT + 128 + f], q);
}
__global__ void k_pn_scale(float n){
    int f = threadIdx.x;
    float mean = g_ws[O_STAT + f] / n;
    float var  = g_ws[O_STAT + 128 + f] / n - mean*mean;
    __shared__ float sh[128];
    sh[f] = var; __syncthreads();
    for (int s = 64; s > 0; s >>= 1) { if (f < s) sh[f] += sh[f+s]; __syncthreads(); }
    g_ws[O_STAT + f] = mean;
    if (f == 0) g_ws[O_STAT + 256] = rsqrtf(sh[0]*(1.f/128.f) + 1e-6f);
}
__global__ void k_pn_apply(const float* __restrict__ x, int stride, int off,
                           float* __restrict__ dst){
    int r = blockIdx.x, f = threadIdx.x;
    float scale = g_ws[O_STAT + 256];
    float v = (x[(size_t)r*stride + off + f] - g_ws[O_STAT + f]) * scale;
    size_t i = (size_t)r*128 + f;
    dst[i] = v*0.25f + 0.1f*dst[i];
}

// ---------------- host ----------------
template<int MODE, int EPI>
static void mmgemm(GArgs ga, const __half* Bg, const float* bias, float* C,
                   int M, int K, int KP, int Ntot, int relu,
                   float* out = nullptr, int round = 0,
                   const float* w1 = nullptr, const float* b1 = nullptr){
    cudaFuncSetAttribute(k_mma<MODE,EPI>, cudaFuncAttributeMaxDynamicSharedMemorySize, GEMM_SMEM);
    dim3 grid(Ntot/128, M/128);
    k_mma<MODE,EPI><<<grid, GEMM_THREADS, GEMM_SMEM>>>(ga, Bg, bias, C, K, KP, Ntot, relu,
                                                       out, round, w1, b1);
}

extern "C" void kernel_launch(void* const* d_in, const int* in_sizes, int n_in,
                              void* d_out, int out_size)
{
    (void)in_sizes; (void)n_in; (void)out_size;
    const int*   edge_lit    = (const int*)d_in[0];
    const int*   edge_clause = (const int*)d_in[1];
    const float* noise_v = (const float*)d_in[2];
    const float* noise_c = (const float*)d_in[3];
    const float* vq_w0 = (const float*)d_in[4];  const float* vq_b0 = (const float*)d_in[5];
    const float* vq_w1 = (const float*)d_in[6];  const float* vq_b1 = (const float*)d_in[7];
    const float* cq_w0 = (const float*)d_in[8];  const float* cq_b0 = (const float*)d_in[9];
    const float* cq_w1 = (const float*)d_in[10]; const float* cq_b1 = (const float*)d_in[11];
    const float* cm_w0 = (const float*)d_in[12]; const float* cm_b0 = (const float*)d_in[13];
    const float* cm_w1 = (const float*)d_in[14]; const float* cm_b1 = (const float*)d_in[15];
    const float* ug_w0 = (const float*)d_in[16]; const float* ug_b0 = (const float*)d_in[17];
    const float* ug_w1 = (const float*)d_in[18]; const float* ug_b1 = (const float*)d_in[19];
    const float* ug_w2 = (const float*)d_in[20]; const float* ug_b2 = (const float*)d_in[21];
    const float* co_w0 = (const float*)d_in[22]; const float* co_b0 = (const float*)d_in[23];
    const float* co_w1 = (const float*)d_in[24]; const float* co_b1 = (const float*)d_in[25];
    float* out = (float*)d_out;

    float* ws; cudaGetSymbolAddress((void**)&ws, g_ws);
    __half* w16 = reinterpret_cast<__half*>(ws + O_WT);

    // ---- setup: exactly 3 launches (first k_mma is graph launch #4) ----
    {
        size_t n = (size_t)(NV+NC)*128;
        k_init<<<(unsigned)((n+255)/256), 256>>>(ws + O_VARS, n);
    }
    k_count_csr<<<(NE+255)/256, 256>>>(edge_lit, edge_clause);
    {
        WSrc s;
        s.w[0]=vq_w0; s.w[1]=vq_w1; s.w[2]=cq_w0; s.w[3]=cq_w1; s.w[4]=cm_w0;
        s.w[5]=cm_w1; s.w[6]=ug_w0; s.w[7]=ug_w1; s.w[8]=ug_w2; s.w[9]=co_w0;
        k_weights_wsplit<<<(OW_END+255)/256, 256>>>(s, w16);
    }

    for (int r = 0; r < 4; r++) {
        const float* nv_r = noise_v + (size_t)r*NV*4;
        const float* nc_r = noise_c + (size_t)r*NC*4;
        GArgs ga{};

        ga = {ws+O_CLS, nc_r, 0, 0, 0, 0};
        mmgemm<M_CAT4,0>(ga, w16+OW_cq0, cq_b0, ws+O_HC, NC, 132, 136, 128, 1);
        ga = {ws+O_HC, 0, 0, 0, 0, 0};
        mmgemm<M_PLAIN,0>(ga, w16+OW_cq1, cq_b1, ws+O_CQ, NC, 128, 128, 128, 0);
        ga = {ws+O_VARS, nv_r, 0, 0, 0, 0};
        mmgemm<M_CAT4,0>(ga, w16+OW_vq0, vq_b0, ws+O_HV, NV, 132, 136, 128, 1);
        ga = {ws+O_HV, 0, 0, 0, 0, 0};
        mmgemm<M_PLAIN,0>(ga, w16+OW_vq1, vq_b1, ws+O_VQ, NV, 128, 128, 128, 0);

        k_csum_loss<<<NC, 128>>>(edge_lit, edge_clause);
        k_gather<<<NL, 128>>>(ws+O_LOSS, 128, ws+O_DLITS);

        ga = {ws+O_CLS, ws+O_LOSS, ws+O_CGRAD, 0, 0, 0};
        mmgemm<M_CMIN,0>(ga, w16+OW_cm0, cm_b0, ws+O_HC, NC, 384, 384, 256, 1);
        ga = {ws+O_HC, 0, 0, 0, 0, 0};
        mmgemm<M_PLAIN,0>(ga, w16+OW_cm1, cm_b1, ws+O_CDATA, NC, 256, 256, 256, 0);

        k_gather<<<NL, 128>>>(ws+O_CDATA, 256, ws+O_VL);

        k_zero<<<2, 256>>>(ws+O_STAT, 257);
        k_pn_stats<<<512, 128>>>(ws+O_CDATA, 256, 128, NC);
        k_pn_scale<<<1, 128>>>((float)NC);
        k_pn_apply<<<NC, 128>>>(ws+O_CDATA, 256, 128, ws+O_CLS);

        ga = {ws+O_VQ, ws+O_DLITS, ws+O_VARS, ws+O_VL, ws+O_DEGW, ws+O_VDEGW};
        mmgemm<M_UNIT,0>(ga, w16+OW_ug0, ug_b0, ws+O_HV, NV, 512, 512, 256, 1);
        ga = {ws+O_HV, 0, 0, 0, 0, 0};
        mmgemm<M_PLAIN,0>(ga, w16+OW_ug1, ug_b1, ws+O_HV2, NV, 256, 256, 256, 1);
        ga = {ws+O_HV2, 0, 0, 0, 0, 0};
        mmgemm<M_PLAIN,0>(ga, w16+OW_ug2, ug_b2, ws+O_VOUT, NV, 256, 256, 128, 0);

        k_zero<<<2, 256>>>(ws+O_STAT, 257);
        k_pn_stats<<<512, 128>>>(ws+O_VOUT, 128, 0, NV);
        k_pn_scale<<<1, 128>>>((float)NV);
        k_pn_apply<<<NV, 128>>>(ws+O_VOUT, 128, 0, ws+O_VARS);

        ga = {ws+O_CLS, 0, 0, 0, 0, 0};
        mmgemm<M_PLAIN,1>(ga, w16+OW_co0, co_b0, nullptr, NC, 128, 128, 128, 1,
                          out, r, co_w1, co_b1);
    }
}

// round 10
// speedup vs baseline: 1.7125x; 1.0901x over previous
#include <cuda_runtime.h>
#include <cuda_fp16.h>
#include <math.h>
#include <stdint.h>

#define NV 24576
#define NC 98304
#define NE 294912
#define NL 49152
#define INV_M (1.0f/12582912.0f)
#define CSR_W 40

// ---------------- workspace layout (floats) ----------------
static constexpr size_t O_VARS   = 0;
static constexpr size_t O_CLS    = O_VARS  + (size_t)NV*128;
static constexpr size_t O_HV     = O_CLS   + (size_t)NC*128;   // NV x 256
static constexpr size_t O_HV2    = O_HV    + (size_t)NV*256;   // NV x 256
static constexpr size_t O_VQ     = O_HV2   + (size_t)NV*256;
static constexpr size_t O_HC     = O_VQ    + (size_t)NV*128;   // NC x 256
static constexpr size_t O_CQ     = O_HC    + (size_t)NC*256;
static constexpr size_t O_CGRAD  = O_CQ    + (size_t)NC*128;
static constexpr size_t O_LOSS   = O_CGRAD + (size_t)NC*128;
static constexpr size_t O_CDATA  = O_LOSS  + (size_t)NC*128;   // NC x 256
static constexpr size_t O_DLITS  = O_CDATA + (size_t)NC*256;   // NL x 128
static constexpr size_t O_VL     = O_DLITS + (size_t)NL*128;   // NL x 128
static constexpr size_t O_VOUT   = O_VL    + (size_t)NL*128;   // NV x 128
static constexpr size_t O_DEGW   = O_VOUT  + (size_t)NV*128;   // NL
static constexpr size_t O_VDEGW  = O_DEGW  + NL;               // NV
// stat buffers: [0,128) col sums, [128,256) col sq, [256,384) mean, [384] scale
static constexpr size_t O_STATC  = O_VDEGW + NV;
static constexpr size_t O_STATV  = O_STATC + 512;
static constexpr size_t O_WT     = O_STATV + 512;
static constexpr size_t WS_TOTAL = O_WT + 240000;

// weight offsets in HALVES within the fp16 array ([N][KP] row-major)
static constexpr size_t OW_vq0 = 0;
static constexpr size_t OW_vq1 = 17408;
static constexpr size_t OW_cq0 = 33792;
static constexpr size_t OW_cq1 = 51200;
static constexpr size_t OW_cm0 = 67584;
static constexpr size_t OW_cm1 = 165888;
static constexpr size_t OW_ug0 = 231424;
static constexpr size_t OW_ug1 = 362496;
static constexpr size_t OW_ug2 = 428032;
static constexpr size_t OW_co0 = 460800;
static constexpr int    OW_END = 477184;

__device__ float g_ws[WS_TOTAL];
__device__ int   g_deg[NL];
__device__ int   g_csr[(size_t)NL * CSR_W];

// ---------------- PTX helpers ----------------
__device__ __forceinline__ uint32_t smem_u32(const void* p){
    uint32_t a;
    asm("{ .reg .u64 t; cvta.to.shared.u64 t, %1; cvt.u32.u64 %0, t; }" : "=r"(a) : "l"(p));
    return a;
}
__device__ __forceinline__ void ldsm4(uint32_t* r, uint32_t addr){
    asm volatile("ldmatrix.sync.aligned.m8n8.x4.shared.b16 {%0,%1,%2,%3}, [%4];"
        : "=r"(r[0]), "=r"(r[1]), "=r"(r[2]), "=r"(r[3]) : "r"(addr));
}
__device__ __forceinline__ void mma_f16(float* c, const uint32_t* a, const uint32_t* b){
    asm volatile("mma.sync.aligned.m16n8k16.row.col.f32.f16.f16.f32 "
        "{%0,%1,%2,%3}, {%4,%5,%6,%7}, {%8,%9}, {%0,%1,%2,%3};"
        : "+f"(c[0]), "+f"(c[1]), "+f"(c[2]), "+f"(c[3])
        : "r"(a[0]), "r"(a[1]), "r"(a[2]), "r"(a[3]), "r"(b[0]), "r"(b[1]));
}
__device__ __forceinline__ void cp16(uint32_t dst, const void* src, bool pred){
    int sz = pred ? 16 : 0;
    asm volatile("cp.async.cg.shared.global [%0], [%1], 16, %2;"
                 :: "r"(dst), "l"(src), "r"(sz));
}
#define CP_COMMIT() asm volatile("cp.async.commit_group;" ::: "memory")
#define CP_WAIT1()  asm volatile("cp.async.wait_group 1;" ::: "memory")

__device__ __forceinline__ float sigm(float x){ return 1.f/(1.f+expf(-x)); }
__device__ __forceinline__ float softplusf(float x){ return fmaxf(x,0.f)+log1pf(expf(-fabsf(x))); }

#define M_PLAIN 0
#define M_CAT4  1
#define M_CMIN  2
#define M_UNIT  3

struct GArgs {
    const float* p0; const float* p1; const float* p2;
    const float* p3; const float* p4; const float* p5;
};

// ---------------- fp16 MMA GEMM, tile 128x64, 256 thr, 2 CTAs/SM ----------------
// smem: A 2-stage [0,20480), B 3-buf [20480,35840)
static constexpr int G64_SMEM = 35840;

template<int MODE, int STATS>   // STATS: 0 none, 1 STATC (cols>=128), 2 STATV (all cols)
__global__ void __launch_bounds__(256, 2)
k_mma64(GArgs ga, const __half* __restrict__ Bg, const float* __restrict__ bias,
        float* __restrict__ C, int K, int KP, int Ntot, int relu,
        float* __restrict__ statp)
{
    extern __shared__ __align__(16) char smem[];
    const uint32_t sbase = smem_u32(smem);
    const int t = threadIdx.x;
    const int lane = t & 31, wid = t >> 5;
    const int warp_m = wid & 3;        // 4 x 32 rows
    const int warp_n = wid >> 2;       // 2 x 32 cols
    const int bm = blockIdx.y * 128;
    const int bn = blockIdx.x * 64;

    constexpr int LDH    = 40;
    constexpr int APLANE = 10240;   // 128x32 fp16 + pad
    constexpr int BPLANE = 5120;    // 64x32 fp16 + pad
    constexpr int A0     = 0;
    constexpr int B0     = 20480;

    float acc[2][4][4];
    #pragma unroll
    for (int i=0;i<2;i++)
        #pragma unroll
        for(int j=0;j<4;j++)
            #pragma unroll
            for(int q=0;q<4;q++) acc[i][j][q]=0.f;

    const int nch = (K + 31) >> 5;
    float4 aReg[4];

    auto loadA = [&](int c){
        const int k0 = c << 5;
        #pragma unroll
        for (int i = 0; i < 4; i++) {
            int idx = t + i*256;
            int row = idx >> 3, col4 = (idx & 7) << 2;
            int gk = k0 + col4;
            int r = bm + row;
            float4 v = make_float4(0.f,0.f,0.f,0.f);
            if (MODE == M_PLAIN) {
                if (gk < K) v = *reinterpret_cast<const float4*>(&ga.p0[(size_t)r*K + gk]);
            } else if (MODE == M_CAT4) {
                if (gk < 128)       v = *reinterpret_cast<const float4*>(&ga.p0[(size_t)r*128 + gk]);
                else if (gk == 128) v = *reinterpret_cast<const float4*>(&ga.p1[(size_t)r*4]);
            } else if (MODE == M_CMIN) {
                int seg = gk >> 7, cc = gk & 127;
                if (seg == 0)      v = *reinterpret_cast<const float4*>(&ga.p0[(size_t)r*128 + cc]);
                else if (seg == 1) {
                    v = *reinterpret_cast<const float4*>(&ga.p1[(size_t)r*128 + cc]);
                    v.x*=4.f; v.y*=4.f; v.z*=4.f; v.w*=4.f;
                } else             v = *reinterpret_cast<const float4*>(&ga.p2[(size_t)r*128 + cc]);
            } else { // M_UNIT
                int seg = gk >> 7, cc = gk & 127;
                if (seg == 0) {
                    float4 vq = *reinterpret_cast<const float4*>(&ga.p0[(size_t)r*128 + cc]);
                    float4 dp = *reinterpret_cast<const float4*>(&ga.p1[(size_t)r*128 + cc]);
                    float4 dn = *reinterpret_cast<const float4*>(&ga.p1[(size_t)(r+NV)*128 + cc]);
                    float w = ga.p5[r];
                    float sp;
                    sp = sigm(vq.x); v.x = -INV_M*(dp.x*sp - dn.x*(1.f-sp))*w;
                    sp = sigm(vq.y); v.y = -INV_M*(dp.y*sp - dn.y*(1.f-sp))*w;
                    sp = sigm(vq.z); v.z = -INV_M*(dp.z*sp - dn.z*(1.f-sp))*w;
                    sp = sigm(vq.w); v.w = -INV_M*(dp.w*sp - dn.w*(1.f-sp))*w;
                } else if (seg == 1) {
                    v = *reinterpret_cast<const float4*>(&ga.p2[(size_t)r*128 + cc]);
                } else if (seg == 2) {
                    v = *reinterpret_cast<const float4*>(&ga.p3[(size_t)r*128 + cc]);
                    float w = ga.p4[r];
                    v.x*=w; v.y*=w; v.z*=w; v.w*=w;
                } else {
                    v = *reinterpret_cast<const float4*>(&ga.p3[(size_t)(r+NV)*128 + cc]);
                    float w = ga.p4[r+NV];
                    v.x*=w; v.y*=w; v.z*=w; v.w*=w;
                }
            }
            aReg[i] = v;
        }
    };
    auto cpB = [&](int c){
        const int k0 = c << 5;
        const uint32_t bb = sbase + B0 + (uint32_t)(c % 3)*BPLANE;
        int row = t >> 2, q = t & 3;   // 64 rows x 4 x 16B
        int gk = k0 + q*8;
        bool ok = (gk + 8 <= KP);
        size_t off = ok ? ((size_t)(bn+row)*KP + gk) : 0;
        cp16(bb + (uint32_t)(row*LDH + q*8)*2, Bg + off, ok);
    };
    auto storeA = [&](int s){
        char* sc = smem + A0 + s*APLANE;
        #pragma unroll
        for (int i = 0; i < 4; i++) {
            int idx = t + i*256;
            int row = idx >> 3, col4 = (idx & 7) << 2;
            __half2 h0 = __floats2half2_rn(aReg[i].x, aReg[i].y);
            __half2 h1 = __floats2half2_rn(aReg[i].z, aReg[i].w);
            uint2 pk;
            pk.x = *reinterpret_cast<uint32_t*>(&h0);
            pk.y = *reinterpret_cast<uint32_t*>(&h1);
            *reinterpret_cast<uint2*>(sc + (row*LDH + col4)*2) = pk;
        }
    };
    auto compute = [&](int c){
        const uint32_t sa = sbase + A0 + (uint32_t)(c & 1)*APLANE;
        const uint32_t sb = sbase + B0 + (uint32_t)(c % 3)*BPLANE;
        const int grp = lane >> 3, r = lane & 7;
        #pragma unroll
        for (int ks = 0; ks < 32; ks += 16) {
            uint32_t aH[2][4], bX[4][2];
            #pragma unroll
            for (int mt = 0; mt < 2; mt++) {
                int arow = warp_m*32 + mt*16 + (grp & 1)*8 + r;
                int acol = ks + (grp >> 1)*8;
                ldsm4(aH[mt], sa + (uint32_t)(arow*LDH + acol)*2);
            }
            #pragma unroll
            for (int p = 0; p < 2; p++) {
                int brow = warp_n*32 + p*16 + (grp >> 1)*8 + r;
                int bcol = ks + (grp & 1)*8;
                uint32_t tmp[4];
                ldsm4(tmp, sb + (uint32_t)(brow*LDH + bcol)*2);
                bX[2*p][0]=tmp[0]; bX[2*p][1]=tmp[1]; bX[2*p+1][0]=tmp[2]; bX[2*p+1][1]=tmp[3];
            }
            #pragma unroll
            for (int mt = 0; mt < 2; mt++)
                #pragma unroll
                for (int nt = 0; nt < 4; nt++)
                    mma_f16(acc[mt][nt], aH[mt], bX[nt]);
        }
    };

    loadA(0);
    cpB(0);
    CP_COMMIT();
    storeA(0);
    if (nch > 1) { loadA(1); cpB(1); }
    CP_COMMIT();
    CP_WAIT1();
    __syncthreads();

    for (int c = 0; c < nch; c++) {
        compute(c);
        if (c+1 < nch) storeA((c+1) & 1);
        if (c+2 < nch) cpB(c+2);
        CP_COMMIT();
        if (c+2 < nch) loadA(c+2);
        CP_WAIT1();
        __syncthreads();
    }

    // ---- store C ----
    #pragma unroll
    for (int mt = 0; mt < 2; mt++) {
        int row0 = bm + warp_m*32 + mt*16 + (lane >> 2);
        #pragma unroll
        for (int nt = 0; nt < 4; nt++) {
            int col = bn + warp_n*32 + nt*8 + (lane & 3)*2;
            float2 bv = *reinterpret_cast<const float2*>(&bias[col]);
            float v0 = acc[mt][nt][0] + bv.x, v1 = acc[mt][nt][1] + bv.y;
            float v2 = acc[mt][nt][2] + bv.x, v3 = acc[mt][nt][3] + bv.y;
            if (relu) { v0=fmaxf(v0,0.f); v1=fmaxf(v1,0.f); v2=fmaxf(v2,0.f); v3=fmaxf(v3,0.f); }
            *reinterpret_cast<float2*>(&C[(size_t)row0*Ntot + col])     = make_float2(v0,v1);
            *reinterpret_cast<float2*>(&C[(size_t)(row0+8)*Ntot + col]) = make_float2(v2,v3);
        }
    }

    // ---- fused pairnorm stats (on raw output incl. bias, relu=0 for these) ----
    if (STATS) {
        bool active = (STATS == 2) || (bn >= 128);
        if (active) {
            float* red = reinterpret_cast<float*>(smem);
            if (t < 128) red[t] = 0.f;
            __syncthreads();
            #pragma unroll
            for (int nt = 0; nt < 4; nt++) {
                int c0 = warp_n*32 + nt*8 + (lane & 3)*2;
                float b0 = __ldg(&bias[bn + c0]), b1 = __ldg(&bias[bn + c0 + 1]);
                float s0=0.f, s1=0.f, q0=0.f, q1=0.f;
                #pragma unroll
                for (int mt = 0; mt < 2; mt++) {
                    float v0 = acc[mt][nt][0] + b0, v1 = acc[mt][nt][1] + b1;
                    float v2 = acc[mt][nt][2] + b0, v3 = acc[mt][nt][3] + b1;
                    s0 += v0 + v2; s1 += v1 + v3;
                    q0 += v0*v0 + v2*v2; q1 += v1*v1 + v3*v3;
                }
                #pragma unroll
                for (int o = 4; o < 32; o <<= 1) {
                    s0 += __shfl_xor_sync(0xffffffffu, s0, o);
                    s1 += __shfl_xor_sync(0xffffffffu, s1, o);
                    q0 += __shfl_xor_sync(0xffffffffu, q0, o);
                    q1 += __shfl_xor_sync(0xffffffffu, q1, o);
                }
                if (lane < 4) {
                    atomicAdd(&red[c0],      s0);
                    atomicAdd(&red[c0+1],    s1);
                    atomicAdd(&red[64+c0],   q0);
                    atomicAdd(&red[64+c0+1], q1);
                }
            }
            __syncthreads();
            int cb = (STATS == 1) ? (bn - 128) : bn;
            if (t < 64) {
                atomicAdd(&statp[cb + t],       red[t]);
                atomicAdd(&statp[128 + cb + t], red[64 + t]);
            }
        }
    }
}

// ---------------- co0 kernel: 512 thr, tile 128x128, pn-apply loader, logits epilogue ----
static constexpr int CO_SMEM = 51200;

__global__ void __launch_bounds__(512, 1)
k_co0(const float* __restrict__ cdata, float* __restrict__ cls,
      const float* __restrict__ statc,
      const __half* __restrict__ Bg, const float* __restrict__ bias,
      float* __restrict__ out, int round,
      const float* __restrict__ w1, const float* __restrict__ b1)
{
    extern __shared__ __align__(16) char smem[];
    const uint32_t sbase = smem_u32(smem);
    const int t = threadIdx.x;
    const int lane = t & 31, wid = t >> 5;
    const int warp_m = wid & 3, warp_n = wid >> 2;
    const int bm = blockIdx.y * 128;

    constexpr int LDH = 40, PLANE = 10240, A0 = 0, B0 = 20480;
    constexpr int K = 128, nch = 4;

    float acc[2][4][4];
    #pragma unroll
    for (int i=0;i<2;i++)
        #pragma unroll
        for(int j=0;j<4;j++)
            #pragma unroll
            for(int q=0;q<4;q++) acc[i][j][q]=0.f;

    float4 aReg[2];
    const float scale = statc[384];

    auto loadA = [&](int c){
        const int k0 = c << 5;
        #pragma unroll
        for (int i = 0; i < 2; i++) {
            int idx = t + i*512;
            int row = idx >> 3, col4 = (idx & 7) << 2;
            int gk = k0 + col4;
            int r = bm + row;
            float4 v = *reinterpret_cast<const float4*>(&cdata[(size_t)r*256 + 128 + gk]);
            float4 m = *reinterpret_cast<const float4*>(&statc[256 + gk]);
            float4 o = *reinterpret_cast<const float4*>(&cls[(size_t)r*128 + gk]);
            v.x = (v.x - m.x)*scale*0.25f + 0.1f*o.x;
            v.y = (v.y - m.y)*scale*0.25f + 0.1f*o.y;
            v.z = (v.z - m.z)*scale*0.25f + 0.1f*o.z;
            v.w = (v.w - m.w)*scale*0.25f + 0.1f*o.w;
            *reinterpret_cast<float4*>(&cls[(size_t)r*128 + gk]) = v;  // write-back (grid.x=1, once)
            aReg[i] = v;
        }
    };
    auto cpB = [&](int c){
        const int k0 = c << 5;
        const uint32_t bb = sbase + B0 + (uint32_t)(c % 3)*PLANE;
        int row = t >> 2, q = t & 3;
        int gk = k0 + q*8;
        cp16(bb + (uint32_t)(row*LDH + q*8)*2, Bg + (size_t)row*K + gk, true);
    };
    auto storeA = [&](int s){
        char* sc = smem + A0 + s*PLANE;
        #pragma unroll
        for (int i = 0; i < 2; i++) {
            int idx = t + i*512;
            int row = idx >> 3, col4 = (idx & 7) << 2;
            __half2 h0 = __floats2half2_rn(aReg[i].x, aReg[i].y);
            __half2 h1 = __floats2half2_rn(aReg[i].z, aReg[i].w);
            uint2 pk;
            pk.x = *reinterpret_cast<uint32_t*>(&h0);
            pk.y = *reinterpret_cast<uint32_t*>(&h1);
            *reinterpret_cast<uint2*>(sc + (row*LDH + col4)*2) = pk;
        }
    };
    auto compute = [&](int c){
        const uint32_t sa = sbase + A0 + (uint32_t)(c & 1)*PLANE;
        const uint32_t sb = sbase + B0 + (uint32_t)(c % 3)*PLANE;
        const int grp = lane >> 3, r = lane & 7;
        #pragma unroll
        for (int ks = 0; ks < 32; ks += 16) {
            uint32_t aH[2][4], bX[4][2];
            #pragma unroll
            for (int mt = 0; mt < 2; mt++) {
                int arow = warp_m*32 + mt*16 + (grp & 1)*8 + r;
                int acol = ks + (grp >> 1)*8;
                ldsm4(aH[mt], sa + (uint32_t)(arow*LDH + acol)*2);
            }
            #pragma unroll
            for (int p = 0; p < 2; p++) {
                int brow = warp_n*32 + p*16 + (grp >> 1)*8 + r;
                int bcol = ks + (grp & 1)*8;
                uint32_t tmp[4];
                ldsm4(tmp, sb + (uint32_t)(brow*LDH + bcol)*2);
                bX[2*p][0]=tmp[0]; bX[2*p][1]=tmp[1]; bX[2*p+1][0]=tmp[2]; bX[2*p+1][1]=tmp[3];
            }
            #pragma unroll
            for (int mt = 0; mt < 2; mt++)
                #pragma unroll
                for (int nt = 0; nt < 4; nt++)
                    mma_f16(acc[mt][nt], aH[mt], bX[nt]);
        }
    };

    loadA(0);
    cpB(0);
    CP_COMMIT();
    storeA(0);
    loadA(1); cpB(1);
    CP_COMMIT();
    CP_WAIT1();
    __syncthreads();

    for (int c = 0; c < nch; c++) {
        compute(c);
        if (c+1 < nch) storeA((c+1) & 1);
        if (c+2 < nch) cpB(c+2);
        CP_COMMIT();
        if (c+2 < nch) loadA(c+2);
        CP_WAIT1();
        __syncthreads();
    }

    // logits epilogue
    float* red = reinterpret_cast<float*>(smem);
    if (t < 128) red[t] = 0.f;
    __syncthreads();
    #pragma unroll
    for (int mt = 0; mt < 2; mt++) {
        int rl = warp_m*32 + mt*16 + (lane >> 2);
        float p0 = 0.f, p1 = 0.f;
        #pragma unroll
        for (int nt = 0; nt < 4; nt++) {
            int col = warp_n*32 + nt*8 + (lane & 3)*2;
            float2 bv = *reinterpret_cast<const float2*>(&bias[col]);
            float wa = __ldg(&w1[col]), wb = __ldg(&w1[col+1]);
            float v0 = fmaxf(acc[mt][nt][0] + bv.x, 0.f);
            float v1 = fmaxf(acc[mt][nt][1] + bv.y, 0.f);
            float v2 = fmaxf(acc[mt][nt][2] + bv.x, 0.f);
            float v3 = fmaxf(acc[mt][nt][3] + bv.y, 0.f);
            p0 += v0*wa + v1*wb;
            p1 += v2*wa + v3*wb;
        }
        atomicAdd(&red[rl], p0);
        atomicAdd(&red[rl+8], p1);
    }
    __syncthreads();
    if (t < 128) {
        float x = red[t] + __ldg(&b1[0]);
        int row = bm + t;
        out[(size_t)round*NC + row] = sigm(x);
        out[(size_t)4*NC + (size_t)round*NC + row] = softplusf(x);
    }
}

// ---------------- setup kernels ----------------
__global__ void k_init(float* p, size_t nfill){
    size_t i = (size_t)blockIdx.x*blockDim.x + threadIdx.x;
    if (i < nfill) p[i] = 1.f;
    if (i < NL) g_deg[i] = 0;
    if (i < 256) { g_ws[O_STATC + i] = 0.f; g_ws[O_STATV + i] = 0.f; }
}
__global__ void k_count_csr(const int* __restrict__ lit, const int* __restrict__ cls){
    int e = blockIdx.x*blockDim.x + threadIdx.x;
    if (e >= NE) return;
    int l = lit[e];
    int pos = atomicAdd(&g_deg[l], 1);
    if (pos < CSR_W) g_csr[(size_t)l*CSR_W + pos] = cls[e];
}
struct WSrc { const float* w[10]; };
__global__ void k_weights_wsplit(WSrc ws, __half* __restrict__ w16){
    const int offs[11] = {0, 17408, 33792, 51200, 67584, 165888, 231424,
                          362496, 428032, 460800, 477184};
    const int Ks[10]  = {132,128,132,128,384,256,512,256,256,128};
    const int KPs[10] = {136,128,136,128,384,256,512,256,256,128};
    const int Ns[10]  = {128,128,128,128,256,256,256,256,128,128};
    int idx = blockIdx.x*blockDim.x + threadIdx.x;
    if (idx < NL) g_ws[O_DEGW + idx] = rsqrtf(fmaxf((float)g_deg[idx], 1.f));
    if (idx < NV) g_ws[O_VDEGW + idx] = 4.f*rsqrtf(fmaxf((float)(g_deg[idx] + g_deg[idx+NV]), 1.f));
    if (idx >= offs[10]) return;
    int seg = 0;
    #pragma unroll
    for (int s = 1; s < 10; s++) if (idx >= offs[s]) seg = s;
    int local = idx - offs[seg];
    int K = Ks[seg], KP = KPs[seg], N = Ns[seg];
    int n = local / KP, k = local % KP;
    float v = (k < K) ? ws.w[seg][(size_t)k*N + n] : 0.f;
    w16[idx] = __float2half_rn(v);
}

// ---------------- misc kernels ----------------
__global__ void k_csum_loss(const int* __restrict__ lit, const int* __restrict__ cls){
    const int c = blockIdx.x, f = threadIdx.x;
    __shared__ int se[2];
    if (f < 2) {
        int key = c + f;
        int lo = 0, hi = NE;
        while (lo < hi) { int mid = (lo+hi) >> 1; if (cls[mid] < key) lo = mid+1; else hi = mid; }
        se[f] = lo;
    }
    __syncthreads();
    float csum = 0.f;
    for (int e = se[0]; e < se[1]; e++) {
        int l = lit[e];
        float z = (l < NV) ? g_ws[O_VQ + (size_t)l*128 + f]
                           : -g_ws[O_VQ + (size_t)(l-NV)*128 + f];
        csum += softplusf(z);
    }
    size_t i = (size_t)c*128 + f;
    float s = sigm(g_ws[O_CQ + i]);
    float l = expf(-csum) * s;
    g_ws[O_LOSS + i]  = l;
    g_ws[O_CGRAD + i] = l * (1.f - s) * INV_M;
}
__global__ void k_gather(const float* __restrict__ src, int sstride,
                         float* __restrict__ dst){
    const int l = blockIdx.x, f = threadIdx.x;
    int d = g_deg[l];
    if (d > CSR_W) d = CSR_W;
    float s = 0.f;
    for (int j = 0; j < d; j++) {
        int c = g_csr[(size_t)l*CSR_W + j];
        s += src[(size_t)c*sstride + f];
    }
    dst[(size_t)l*128 + f] = s;
}
// reads col sums/sq, computes mean/scale, zeroes sums for next use
__global__ void k_pn_scale(float n, float* stat){
    int f = threadIdx.x;
    float mean = stat[f] / n;
    float var  = stat[128 + f] / n - mean*mean;
    __shared__ float sh[128];
    sh[f] = var; __syncthreads();
    for (int s = 64; s > 0; s >>= 1) { if (f < s) sh[f] += sh[f+s]; __syncthreads(); }
    stat[256 + f] = mean;
    if (f == 0) stat[384] = rsqrtf(sh[0]*(1.f/128.f) + 1e-6f);
    stat[f] = 0.f;
    stat[128 + f] = 0.f;
}
__global__ void k_pn_apply(const float* __restrict__ x, const float* __restrict__ stat,
                           float* __restrict__ dst){
    int r = blockIdx.x, f = threadIdx.x;
    float v = (x[(size_t)r*128 + f] - stat[256 + f]) * stat[384];
    size_t i = (size_t)r*128 + f;
    dst[i] = v*0.25f + 0.1f*dst[i];
}

// ---------------- host ----------------
template<int MODE, int STATS>
static void mmgemm(GArgs ga, const __half* Bg, const float* bias, float* C,
                   int M, int K, int KP, int Ntot, int relu, float* statp = nullptr){
    cudaFuncSetAttribute(k_mma64<MODE,STATS>, cudaFuncAttributeMaxDynamicSharedMemorySize, G64_SMEM);
    dim3 grid(Ntot/64, M/128);
    k_mma64<MODE,STATS><<<grid, 256, G64_SMEM>>>(ga, Bg, bias, C, K, KP, Ntot, relu, statp);
}

extern "C" void kernel_launch(void* const* d_in, const int* in_sizes, int n_in,
                              void* d_out, int out_size)
{
    (void)in_sizes; (void)n_in; (void)out_size;
    const int*   edge_lit    = (const int*)d_in[0];
    const int*   edge_clause = (const int*)d_in[1];
    const float* noise_v = (const float*)d_in[2];
    const float* noise_c = (const float*)d_in[3];
    const float* vq_w0 = (const float*)d_in[4];  const float* vq_b0 = (const float*)d_in[5];
    const float* vq_w1 = (const float*)d_in[6];  const float* vq_b1 = (const float*)d_in[7];
    const float* cq_w0 = (const float*)d_in[8];  const float* cq_b0 = (const float*)d_in[9];
    const float* cq_w1 = (const float*)d_in[10]; const float* cq_b1 = (const float*)d_in[11];
    const float* cm_w0 = (const float*)d_in[12]; const float* cm_b0 = (const float*)d_in[13];
    const float* cm_w1 = (const float*)d_in[14]; const float* cm_b1 = (const float*)d_in[15];
    const float* ug_w0 = (const float*)d_in[16]; const float* ug_b0 = (const float*)d_in[17];
    const float* ug_w1 = (const float*)d_in[18]; const float* ug_b1 = (const float*)d_in[19];
    const float* ug_w2 = (const float*)d_in[20]; const float* ug_b2 = (const float*)d_in[21];
    const float* co_w0 = (const float*)d_in[22]; const float* co_b0 = (const float*)d_in[23];
    const float* co_w1 = (const float*)d_in[24]; const float* co_b1 = (const float*)d_in[25];
    float* out = (float*)d_out;

    float* ws; cudaGetSymbolAddress((void**)&ws, g_ws);
    __half* w16 = reinterpret_cast<__half*>(ws + O_WT);
    float* statc = ws + O_STATC;
    float* statv = ws + O_STATV;

    cudaFuncSetAttribute(k_co0, cudaFuncAttributeMaxDynamicSharedMemorySize, CO_SMEM);

    // ---- setup: 3 launches ----
    {
        size_t n = (size_t)(NV+NC)*128;
        k_init<<<(unsigned)((n+255)/256), 256>>>(ws + O_VARS, n);
    }
    k_count_csr<<<(NE+255)/256, 256>>>(edge_lit, edge_clause);
    {
        WSrc s;
        s.w[0]=vq_w0; s.w[1]=vq_w1; s.w[2]=cq_w0; s.w[3]=cq_w1; s.w[4]=cm_w0;
        s.w[5]=cm_w1; s.w[6]=ug_w0; s.w[7]=ug_w1; s.w[8]=ug_w2; s.w[9]=co_w0;
        k_weights_wsplit<<<(OW_END+255)/256, 256>>>(s, w16);
    }

    for (int r = 0; r < 4; r++) {
        const float* nv_r = noise_v + (size_t)r*NV*4;
        const float* nc_r = noise_c + (size_t)r*NC*4;
        GArgs ga{};

        ga = {ws+O_CLS, nc_r, 0, 0, 0, 0};
        mmgemm<M_CAT4,0>(ga, w16+OW_cq0, cq_b0, ws+O_HC, NC, 132, 136, 128, 1);
        ga = {ws+O_HC, 0, 0, 0, 0, 0};
        mmgemm<M_PLAIN,0>(ga, w16+OW_cq1, cq_b1, ws+O_CQ, NC, 128, 128, 128, 0);
        ga = {ws+O_VARS, nv_r, 0, 0, 0, 0};
        mmgemm<M_CAT4,0>(ga, w16+OW_vq0, vq_b0, ws+O_HV, NV, 132, 136, 128, 1);
        ga = {ws+O_HV, 0, 0, 0, 0, 0};
        mmgemm<M_PLAIN,0>(ga, w16+OW_vq1, vq_b1, ws+O_VQ, NV, 128, 128, 128, 0);

        k_csum_loss<<<NC, 128>>>(edge_lit, edge_clause);
        k_gather<<<NL, 128>>>(ws+O_LOSS, 128, ws+O_DLITS);

        ga = {ws+O_CLS, ws+O_LOSS, ws+O_CGRAD, 0, 0, 0};
        mmgemm<M_CMIN,0>(ga, w16+OW_cm0, cm_b0, ws+O_HC, NC, 384, 384, 256, 1);
        ga = {ws+O_HC, 0, 0, 0, 0, 0};
        mmgemm<M_PLAIN,1>(ga, w16+OW_cm1, cm_b1, ws+O_CDATA, NC, 256, 256, 256, 0, statc);

        k_gather<<<NL, 128>>>(ws+O_CDATA, 256, ws+O_VL);
        k_pn_scale<<<1, 128>>>((float)NC, statc);

        ga = {ws+O_VQ, ws+O_DLITS, ws+O_VARS, ws+O_VL, ws+O_DEGW, ws+O_VDEGW};
        mmgemm<M_UNIT,0>(ga, w16+OW_ug0, ug_b0, ws+O_HV, NV, 512, 512, 256, 1);
        ga = {ws+O_HV, 0, 0, 0, 0, 0};
        mmgemm<M_PLAIN,0>(ga, w16+OW_ug1, ug_b1, ws+O_HV2, NV, 256, 256, 256, 1);
        ga = {ws+O_HV2, 0, 0, 0, 0, 0};
        mmgemm<M_PLAIN,2>(ga, w16+OW_ug2, ug_b2, ws+O_VOUT, NV, 256, 256, 128, 0, statv);

        k_pn_scale<<<1, 128>>>((float)NV, statv);
        k_pn_apply<<<NV, 128>>>(ws+O_VOUT, statv, ws+O_VARS);

        // co0: pn-apply(CLS) fused into loader (+write-back), logits epilogue
        k_co0<<<dim3(1, NC/128), 512, CO_SMEM>>>(ws+O_CDATA, ws+O_CLS, statc,
                                                 w16+OW_co0, co_b0, out, r, co_w1, co_b1);
    }
}

// round 11
// speedup vs baseline: 2.1668x; 1.2652x over previous
#include <cuda_runtime.h>
#include <cuda_fp16.h>
#include <math.h>
#include <stdint.h>

#define NV 24576
#define NC 98304
#define NE 294912
#define NL 49152
#define INV_M (1.0f/12582912.0f)
#define CSR_W 40

// ---------------- workspace layout (floats) ----------------
static constexpr size_t O_VARS   = 0;
static constexpr size_t O_CLS    = O_VARS  + (size_t)NV*128;
static constexpr size_t O_HV     = O_CLS   + (size_t)NC*128;   // NV x 256 (also SP: NL x 128)
static constexpr size_t O_HV2    = O_HV    + (size_t)NV*256;   // NV x 256
static constexpr size_t O_VQ     = O_HV2   + (size_t)NV*256;
static constexpr size_t O_HC     = O_VQ    + (size_t)NV*128;   // NC x 256
static constexpr size_t O_CQ     = O_HC    + (size_t)NC*256;
static constexpr size_t O_CGRAD  = O_CQ    + (size_t)NC*128;
static constexpr size_t O_LOSS   = O_CGRAD + (size_t)NC*128;
static constexpr size_t O_CDATA  = O_LOSS  + (size_t)NC*128;   // NC x 256
static constexpr size_t O_DLITS  = O_CDATA + (size_t)NC*256;   // NL x 128
static constexpr size_t O_VL     = O_DLITS + (size_t)NL*128;   // NL x 128
static constexpr size_t O_VOUT   = O_VL    + (size_t)NL*128;   // NV x 128
static constexpr size_t O_DEGW   = O_VOUT  + (size_t)NV*128;   // NL
static constexpr size_t O_VDEGW  = O_DEGW  + NL;               // NV
static constexpr size_t O_STATC  = O_VDEGW + NV;               // 512
static constexpr size_t O_STATV  = O_STATC + 512;              // 512
static constexpr size_t O_WT     = O_STATV + 512;
static constexpr size_t WS_TOTAL = O_WT + 240000;

static constexpr size_t OW_vq0 = 0;
static constexpr size_t OW_vq1 = 17408;
static constexpr size_t OW_cq0 = 33792;
static constexpr size_t OW_cq1 = 51200;
static constexpr size_t OW_cm0 = 67584;
static constexpr size_t OW_cm1 = 165888;
static constexpr size_t OW_ug0 = 231424;
static constexpr size_t OW_ug1 = 362496;
static constexpr size_t OW_ug2 = 428032;
static constexpr size_t OW_co0 = 460800;
static constexpr int    OW_END = 477184;

__device__ float g_ws[WS_TOTAL];
__device__ int   g_deg[NL];
__device__ int   g_csr[(size_t)NL * CSR_W];

// ---------------- PTX helpers ----------------
__device__ __forceinline__ uint32_t smem_u32(const void* p){
    uint32_t a;
    asm("{ .reg .u64 t; cvta.to.shared.u64 t, %1; cvt.u32.u64 %0, t; }" : "=r"(a) : "l"(p));
    return a;
}
__device__ __forceinline__ void ldsm4(uint32_t* r, uint32_t addr){
    asm volatile("ldmatrix.sync.aligned.m8n8.x4.shared.b16 {%0,%1,%2,%3}, [%4];"
        : "=r"(r[0]), "=r"(r[1]), "=r"(r[2]), "=r"(r[3]) : "r"(addr));
}
__device__ __forceinline__ void mma_f16(float* c, const uint32_t* a, const uint32_t* b){
    asm volatile("mma.sync.aligned.m16n8k16.row.col.f32.f16.f16.f32 "
        "{%0,%1,%2,%3}, {%4,%5,%6,%7}, {%8,%9}, {%0,%1,%2,%3};"
        : "+f"(c[0]), "+f"(c[1]), "+f"(c[2]), "+f"(c[3])
        : "r"(a[0]), "r"(a[1]), "r"(a[2]), "r"(a[3]), "r"(b[0]), "r"(b[1]));
}
__device__ __forceinline__ void cp16(uint32_t dst, const void* src, bool pred){
    int sz = pred ? 16 : 0;
    asm volatile("cp.async.cg.shared.global [%0], [%1], 16, %2;"
                 :: "r"(dst), "l"(src), "r"(sz));
}
#define CP_COMMIT() asm volatile("cp.async.commit_group;" ::: "memory")
#define CP_WAIT1()  asm volatile("cp.async.wait_group 1;" ::: "memory")

__device__ __forceinline__ float sigm(float x){ return 1.f/(1.f+expf(-x)); }
__device__ __forceinline__ float softplusf(float x){ return fmaxf(x,0.f)+log1pf(expf(-fabsf(x))); }
// fast variants for inner loops (rel err ~1e-5, well under budget)
__device__ __forceinline__ float fsigm(float x){ return __fdividef(1.f, 1.f+__expf(-x)); }
__device__ __forceinline__ float fsoftplus(float x){ return fmaxf(x,0.f)+__logf(1.f+__expf(-fabsf(x))); }

#define M_PLAIN 0
#define M_CAT4  1
#define M_CMIN  2
#define M_UNIT  3

struct GArgs {
    const float* p0; const float* p1; const float* p2;
    const float* p3; const float* p4; const float* p5;
};

// ---------------- fp16 MMA GEMM, tile 128x64, 256 thr, 2 CTAs/SM ----------------
static constexpr int G64_SMEM = 35840;

template<int MODE, int STATS>
__global__ void __launch_bounds__(256, 2)
k_mma64(GArgs ga, const __half* __restrict__ Bg, const float* __restrict__ bias,
        float* __restrict__ C, int K, int KP, int Ntot, int relu,
        float* __restrict__ statp)
{
    extern __shared__ __align__(16) char smem[];
    const uint32_t sbase = smem_u32(smem);
    const int t = threadIdx.x;
    const int lane = t & 31, wid = t >> 5;
    const int warp_m = wid & 3;
    const int warp_n = wid >> 2;
    const int bm = blockIdx.y * 128;
    const int bn = blockIdx.x * 64;

    constexpr int LDH    = 40;
    constexpr int APLANE = 10240;
    constexpr int BPLANE = 5120;
    constexpr int A0     = 0;
    constexpr int B0     = 20480;

    float acc[2][4][4];
    #pragma unroll
    for (int i=0;i<2;i++)
        #pragma unroll
        for(int j=0;j<4;j++)
            #pragma unroll
            for(int q=0;q<4;q++) acc[i][j][q]=0.f;

    const int nch = (K + 31) >> 5;
    float4 aReg[4];

    auto loadA = [&](int c){
        const int k0 = c << 5;
        #pragma unroll
        for (int i = 0; i < 4; i++) {
            int idx = t + i*256;
            int row = idx >> 3, col4 = (idx & 7) << 2;
            int gk = k0 + col4;
            int r = bm + row;
            float4 v = make_float4(0.f,0.f,0.f,0.f);
            if (MODE == M_PLAIN) {
                if (gk < K) v = *reinterpret_cast<const float4*>(&ga.p0[(size_t)r*K + gk]);
            } else if (MODE == M_CAT4) {
                if (gk < 128)       v = *reinterpret_cast<const float4*>(&ga.p0[(size_t)r*128 + gk]);
                else if (gk == 128) v = *reinterpret_cast<const float4*>(&ga.p1[(size_t)r*4]);
            } else if (MODE == M_CMIN) {
                int seg = gk >> 7, cc = gk & 127;
                if (seg == 0)      v = *reinterpret_cast<const float4*>(&ga.p0[(size_t)r*128 + cc]);
                else if (seg == 1) {
                    v = *reinterpret_cast<const float4*>(&ga.p1[(size_t)r*128 + cc]);
                    v.x*=4.f; v.y*=4.f; v.z*=4.f; v.w*=4.f;
                } else             v = *reinterpret_cast<const float4*>(&ga.p2[(size_t)r*128 + cc]);
            } else { // M_UNIT
                int seg = gk >> 7, cc = gk & 127;
                if (seg == 0) {
                    float4 vq = *reinterpret_cast<const float4*>(&ga.p0[(size_t)r*128 + cc]);
                    float4 dp = *reinterpret_cast<const float4*>(&ga.p1[(size_t)r*128 + cc]);
                    float4 dn = *reinterpret_cast<const float4*>(&ga.p1[(size_t)(r+NV)*128 + cc]);
                    float w = ga.p5[r];
                    float sp;
                    sp = fsigm(vq.x); v.x = -INV_M*(dp.x*sp - dn.x*(1.f-sp))*w;
                    sp = fsigm(vq.y); v.y = -INV_M*(dp.y*sp - dn.y*(1.f-sp))*w;
                    sp = fsigm(vq.z); v.z = -INV_M*(dp.z*sp - dn.z*(1.f-sp))*w;
                    sp = fsigm(vq.w); v.w = -INV_M*(dp.w*sp - dn.w*(1.f-sp))*w;
                } else if (seg == 1) {
                    v = *reinterpret_cast<const float4*>(&ga.p2[(size_t)r*128 + cc]);
                } else if (seg == 2) {
                    v = *reinterpret_cast<const float4*>(&ga.p3[(size_t)r*128 + cc]);
                    float w = ga.p4[r];
                    v.x*=w; v.y*=w; v.z*=w; v.w*=w;
                } else {
                    v = *reinterpret_cast<const float4*>(&ga.p3[(size_t)(r+NV)*128 + cc]);
                    float w = ga.p4[r+NV];
                    v.x*=w; v.y*=w; v.z*=w; v.w*=w;
                }
            }
            aReg[i] = v;
        }
    };
    auto cpB = [&](int c){
        const int k0 = c << 5;
        const uint32_t bb = sbase + B0 + (uint32_t)(c % 3)*BPLANE;
        int row = t >> 2, q = t & 3;
        int gk = k0 + q*8;
        bool ok = (gk + 8 <= KP);
        size_t off = ok ? ((size_t)(bn+row)*KP + gk) : 0;
        cp16(bb + (uint32_t)(row*LDH + q*8)*2, Bg + off, ok);
    };
    auto storeA = [&](int s){
        char* sc = smem + A0 + s*APLANE;
        #pragma unroll
        for (int i = 0; i < 4; i++) {
            int idx = t + i*256;
            int row = idx >> 3, col4 = (idx & 7) << 2;
            __half2 h0 = __floats2half2_rn(aReg[i].x, aReg[i].y);
            __half2 h1 = __floats2half2_rn(aReg[i].z, aReg[i].w);
            uint2 pk;
            pk.x = *reinterpret_cast<uint32_t*>(&h0);
            pk.y = *reinterpret_cast<uint32_t*>(&h1);
            *reinterpret_cast<uint2*>(sc + (row*LDH + col4)*2) = pk;
        }
    };
    auto compute = [&](int c){
        const uint32_t sa = sbase + A0 + (uint32_t)(c & 1)*APLANE;
        const uint32_t sb = sbase + B0 + (uint32_t)(c % 3)*BPLANE;
        const int grp = lane >> 3, r = lane & 7;
        #pragma unroll
        for (int ks = 0; ks < 32; ks += 16) {
            uint32_t aH[2][4], bX[4][2];
            #pragma unroll
            for (int mt = 0; mt < 2; mt++) {
                int arow = warp_m*32 + mt*16 + (grp & 1)*8 + r;
                int acol = ks + (grp >> 1)*8;
                ldsm4(aH[mt], sa + (uint32_t)(arow*LDH + acol)*2);
            }
            #pragma unroll
            for (int p = 0; p < 2; p++) {
                int brow = warp_n*32 + p*16 + (grp >> 1)*8 + r;
                int bcol = ks + (grp & 1)*8;
                uint32_t tmp[4];
                ldsm4(tmp, sb + (uint32_t)(brow*LDH + bcol)*2);
                bX[2*p][0]=tmp[0]; bX[2*p][1]=tmp[1]; bX[2*p+1][0]=tmp[2]; bX[2*p+1][1]=tmp[3];
            }
            #pragma unroll
            for (int mt = 0; mt < 2; mt++)
                #pragma unroll
                for (int nt = 0; nt < 4; nt++)
                    mma_f16(acc[mt][nt], aH[mt], bX[nt]);
        }
    };

    loadA(0);
    cpB(0);
    CP_COMMIT();
    storeA(0);
    if (nch > 1) { loadA(1); cpB(1); }
    CP_COMMIT();
    CP_WAIT1();
    __syncthreads();

    for (int c = 0; c < nch; c++) {
        compute(c);
        if (c+1 < nch) storeA((c+1) & 1);
        if (c+2 < nch) cpB(c+2);
        CP_COMMIT();
        if (c+2 < nch) loadA(c+2);
        CP_WAIT1();
        __syncthreads();
    }

    #pragma unroll
    for (int mt = 0; mt < 2; mt++) {
        int row0 = bm + warp_m*32 + mt*16 + (lane >> 2);
        #pragma unroll
        for (int nt = 0; nt < 4; nt++) {
            int col = bn + warp_n*32 + nt*8 + (lane & 3)*2;
            float2 bv = *reinterpret_cast<const float2*>(&bias[col]);
            float v0 = acc[mt][nt][0] + bv.x, v1 = acc[mt][nt][1] + bv.y;
            float v2 = acc[mt][nt][2] + bv.x, v3 = acc[mt][nt][3] + bv.y;
            if (relu) { v0=fmaxf(v0,0.f); v1=fmaxf(v1,0.f); v2=fmaxf(v2,0.f); v3=fmaxf(v3,0.f); }
            *reinterpret_cast<float2*>(&C[(size_t)row0*Ntot + col])     = make_float2(v0,v1);
            *reinterpret_cast<float2*>(&C[(size_t)(row0+8)*Ntot + col]) = make_float2(v2,v3);
        }
    }

    if (STATS) {
        bool active = (STATS == 2) || (bn >= 128);
        if (active) {
            float* red = reinterpret_cast<float*>(smem);
            if (t < 128) red[t] = 0.f;
            __syncthreads();
            #pragma unroll
            for (int nt = 0; nt < 4; nt++) {
                int c0 = warp_n*32 + nt*8 + (lane & 3)*2;
                float b0 = __ldg(&bias[bn + c0]), b1 = __ldg(&bias[bn + c0 + 1]);
                float s0=0.f, s1=0.f, q0=0.f, q1=0.f;
                #pragma unroll
                for (int mt = 0; mt < 2; mt++) {
                    float v0 = acc[mt][nt][0] + b0, v1 = acc[mt][nt][1] + b1;
                    float v2 = acc[mt][nt][2] + b0, v3 = acc[mt][nt][3] + b1;
                    s0 += v0 + v2; s1 += v1 + v3;
                    q0 += v0*v0 + v2*v2; q1 += v1*v1 + v3*v3;
                }
                #pragma unroll
                for (int o = 4; o < 32; o <<= 1) {
                    s0 += __shfl_xor_sync(0xffffffffu, s0, o);
                    s1 += __shfl_xor_sync(0xffffffffu, s1, o);
                    q0 += __shfl_xor_sync(0xffffffffu, q0, o);
                    q1 += __shfl_xor_sync(0xffffffffu, q1, o);
                }
                if (lane < 4) {
                    atomicAdd(&red[c0],      s0);
                    atomicAdd(&red[c0+1],    s1);
                    atomicAdd(&red[64+c0],   q0);
                    atomicAdd(&red[64+c0+1], q1);
                }
            }
            __syncthreads();
            int cb = (STATS == 1) ? (bn - 128) : bn;
            if (t < 64) {
                atomicAdd(&statp[cb + t],       red[t]);
                atomicAdd(&statp[128 + cb + t], red[64 + t]);
            }
        }
    }
}

// ---------------- co0 kernel ----------------
static constexpr int CO_SMEM = 51200;

__global__ void __launch_bounds__(512, 1)
k_co0(const float* __restrict__ cdata, float* __restrict__ cls,
      const float* __restrict__ statc,
      const __half* __restrict__ Bg, const float* __restrict__ bias,
      float* __restrict__ out, int round,
      const float* __restrict__ w1, const float* __restrict__ b1)
{
    extern __shared__ __align__(16) char smem[];
    const uint32_t sbase = smem_u32(smem);
    const int t = threadIdx.x;
    const int lane = t & 31, wid = t >> 5;
    const int warp_m = wid & 3, warp_n = wid >> 2;
    const int bm = blockIdx.y * 128;

    constexpr int LDH = 40, PLANE = 10240, A0 = 0, B0 = 20480;
    constexpr int K = 128, nch = 4;

    float acc[2][4][4];
    #pragma unroll
    for (int i=0;i<2;i++)
        #pragma unroll
        for(int j=0;j<4;j++)
            #pragma unroll
            for(int q=0;q<4;q++) acc[i][j][q]=0.f;

    float4 aReg[2];
    const float scale = statc[384];

    auto loadA = [&](int c){
        const int k0 = c << 5;
        #pragma unroll
        for (int i = 0; i < 2; i++) {
            int idx = t + i*512;
            int row = idx >> 3, col4 = (idx & 7) << 2;
            int gk = k0 + col4;
            int r = bm + row;
            float4 v = *reinterpret_cast<const float4*>(&cdata[(size_t)r*256 + 128 + gk]);
            float4 m = *reinterpret_cast<const float4*>(&statc[256 + gk]);
            float4 o = *reinterpret_cast<const float4*>(&cls[(size_t)r*128 + gk]);
            v.x = (v.x - m.x)*scale*0.25f + 0.1f*o.x;
            v.y = (v.y - m.y)*scale*0.25f + 0.1f*o.y;
            v.z = (v.z - m.z)*scale*0.25f + 0.1f*o.z;
            v.w = (v.w - m.w)*scale*0.25f + 0.1f*o.w;
            *reinterpret_cast<float4*>(&cls[(size_t)r*128 + gk]) = v;
            aReg[i] = v;
        }
    };
    auto cpB = [&](int c){
        const int k0 = c << 5;
        const uint32_t bb = sbase + B0 + (uint32_t)(c % 3)*PLANE;
        int row = t >> 2, q = t & 3;
        int gk = k0 + q*8;
        cp16(bb + (uint32_t)(row*LDH + q*8)*2, Bg + (size_t)row*K + gk, true);
    };
    auto storeA = [&](int s){
        char* sc = smem + A0 + s*PLANE;
        #pragma unroll
        for (int i = 0; i < 2; i++) {
            int idx = t + i*512;
            int row = idx >> 3, col4 = (idx & 7) << 2;
            __half2 h0 = __floats2half2_rn(aReg[i].x, aReg[i].y);
            __half2 h1 = __floats2half2_rn(aReg[i].z, aReg[i].w);
            uint2 pk;
            pk.x = *reinterpret_cast<uint32_t*>(&h0);
            pk.y = *reinterpret_cast<uint32_t*>(&h1);
            *reinterpret_cast<uint2*>(sc + (row*LDH + col4)*2) = pk;
        }
    };
    auto compute = [&](int c){
        const uint32_t sa = sbase + A0 + (uint32_t)(c & 1)*PLANE;
        const uint32_t sb = sbase + B0 + (uint32_t)(c % 3)*PLANE;
        const int grp = lane >> 3, r = lane & 7;
        #pragma unroll
        for (int ks = 0; ks < 32; ks += 16) {
            uint32_t aH[2][4], bX[4][2];
            #pragma unroll
            for (int mt = 0; mt < 2; mt++) {
                int arow = warp_m*32 + mt*16 + (grp & 1)*8 + r;
                int acol = ks + (grp >> 1)*8;
                ldsm4(aH[mt], sa + (uint32_t)(arow*LDH + acol)*2);
            }
            #pragma unroll
            for (int p = 0; p < 2; p++) {
                int brow = warp_n*32 + p*16 + (grp >> 1)*8 + r;
                int bcol = ks + (grp & 1)*8;
                uint32_t tmp[4];
                ldsm4(tmp, sb + (uint32_t)(brow*LDH + bcol)*2);
                bX[2*p][0]=tmp[0]; bX[2*p][1]=tmp[1]; bX[2*p+1][0]=tmp[2]; bX[2*p+1][1]=tmp[3];
            }
            #pragma unroll
            for (int mt = 0; mt < 2; mt++)
                #pragma unroll
                for (int nt = 0; nt < 4; nt++)
                    mma_f16(acc[mt][nt], aH[mt], bX[nt]);
        }
    };

    loadA(0);
    cpB(0);
    CP_COMMIT();
    storeA(0);
    loadA(1); cpB(1);
    CP_COMMIT();
    CP_WAIT1();
    __syncthreads();

    for (int c = 0; c < nch; c++) {
        compute(c);
        if (c+1 < nch) storeA((c+1) & 1);
        if (c+2 < nch) cpB(c+2);
        CP_COMMIT();
        if (c+2 < nch) loadA(c+2);
        CP_WAIT1();
        __syncthreads();
    }

    float* red = reinterpret_cast<float*>(smem);
    if (t < 128) red[t] = 0.f;
    __syncthreads();
    #pragma unroll
    for (int mt = 0; mt < 2; mt++) {
        int rl = warp_m*32 + mt*16 + (lane >> 2);
        float p0 = 0.f, p1 = 0.f;
        #pragma unroll
        for (int nt = 0; nt < 4; nt++) {
            int col = warp_n*32 + nt*8 + (lane & 3)*2;
            float2 bv = *reinterpret_cast<const float2*>(&bias[col]);
            float wa = __ldg(&w1[col]), wb = __ldg(&w1[col+1]);
            float v0 = fmaxf(acc[mt][nt][0] + bv.x, 0.f);
            float v1 = fmaxf(acc[mt][nt][1] + bv.y, 0.f);
            float v2 = fmaxf(acc[mt][nt][2] + bv.x, 0.f);
            float v3 = fmaxf(acc[mt][nt][3] + bv.y, 0.f);
            p0 += v0*wa + v1*wb;
            p1 += v2*wa + v3*wb;
        }
        atomicAdd(&red[rl], p0);
        atomicAdd(&red[rl+8], p1);
    }
    __syncthreads();
    if (t < 128) {
        float x = red[t] + __ldg(&b1[0]);
        int row = bm + t;
        out[(size_t)round*NC + row] = sigm(x);        // accurate at the output
        out[(size_t)4*NC + (size_t)round*NC + row] = softplusf(x);
    }
}

// ---------------- setup kernels ----------------
__global__ void k_init(float* p, size_t nfill){
    size_t i = (size_t)blockIdx.x*blockDim.x + threadIdx.x;
    if (i < nfill) p[i] = 1.f;
    if (i < NL) g_deg[i] = 0;
    if (i < 256) { g_ws[O_STATC + i] = 0.f; g_ws[O_STATV + i] = 0.f; }
}
__global__ void k_count_csr(const int* __restrict__ lit, const int* __restrict__ cls){
    int e = blockIdx.x*blockDim.x + threadIdx.x;
    if (e >= NE) return;
    int l = lit[e];
    int pos = atomicAdd(&g_deg[l], 1);
    if (pos < CSR_W) g_csr[(size_t)l*CSR_W + pos] = cls[e];
}
struct WSrc { const float* w[10]; };
__global__ void k_weights_wsplit(WSrc ws, __half* __restrict__ w16){
    const int offs[11] = {0, 17408, 33792, 51200, 67584, 165888, 231424,
                          362496, 428032, 460800, 477184};
    const int Ks[10]  = {132,128,132,128,384,256,512,256,256,128};
    const int KPs[10] = {136,128,136,128,384,256,512,256,256,128};
    const int Ns[10]  = {128,128,128,128,256,256,256,256,128,128};
    int idx = blockIdx.x*blockDim.x + threadIdx.x;
    if (idx < NL) g_ws[O_DEGW + idx] = rsqrtf(fmaxf((float)g_deg[idx], 1.f));
    if (idx < NV) g_ws[O_VDEGW + idx] = 4.f*rsqrtf(fmaxf((float)(g_deg[idx] + g_deg[idx+NV]), 1.f));
    if (idx >= offs[10]) return;
    int seg = 0;
    #pragma unroll
    for (int s = 1; s < 10; s++) if (idx >= offs[s]) seg = s;
    int local = idx - offs[seg];
    int K = Ks[seg], KP = KPs[seg], N = Ns[seg];
    int n = local / KP, k = local % KP;
    float v = (k < K) ? ws.w[seg][(size_t)k*N + n] : 0.f;
    w16[idx] = __float2half_rn(v);
}

// ---------------- edge kernels (vectorized) ----------------
// SP[l][f] = softplus of signed vq — transcendental cost O(NL), not O(NE)
__global__ void k_softplus(const float* __restrict__ vq, float* __restrict__ sp){
    int l = blockIdx.x*4 + (threadIdx.x >> 5);
    int f4 = (threadIdx.x & 31) << 2;
    float sgn = (l < NV) ? 1.f : -1.f;
    int v = (l < NV) ? l : l - NV;
    float4 q = *reinterpret_cast<const float4*>(&vq[(size_t)v*128 + f4]);
    float4 o;
    o.x = fsoftplus(sgn*q.x);
    o.y = fsoftplus(sgn*q.y);
    o.z = fsoftplus(sgn*q.z);
    o.w = fsoftplus(sgn*q.w);
    *reinterpret_cast<float4*>(&sp[(size_t)l*128 + f4]) = o;
}
// csum gather over sorted clause ranges + loss + cgrad (warp per clause, float4)
__global__ void k_csum_loss(const int* __restrict__ lit, const int* __restrict__ cls,
                            const float* __restrict__ sp){
    const int warp = threadIdx.x >> 5, lane = threadIdx.x & 31;
    const int c = blockIdx.x*4 + warp;
    int s01 = 0;
    if (lane < 2) {
        int key = c + lane;
        int lo = 0, hi = NE;
        while (lo < hi) { int mid = (lo+hi) >> 1; if (cls[mid] < key) lo = mid+1; else hi = mid; }
        s01 = lo;
    }
    int s0 = __shfl_sync(0xffffffffu, s01, 0);
    int s1 = __shfl_sync(0xffffffffu, s01, 1);
    int f4 = lane << 2;
    float4 csum = make_float4(0.f,0.f,0.f,0.f);
    for (int e = s0; e < s1; e++) {
        int l = __ldg(&lit[e]);
        float4 v = *reinterpret_cast<const float4*>(&sp[(size_t)l*128 + f4]);
        csum.x += v.x; csum.y += v.y; csum.z += v.z; csum.w += v.w;
    }
    size_t i = (size_t)c*128 + f4;
    float4 cq = *reinterpret_cast<const float4*>(&g_ws[O_CQ + i]);
    float4 lo4, cg4;
    float sg;
    sg = fsigm(cq.x); lo4.x = __expf(-csum.x)*sg; cg4.x = lo4.x*(1.f-sg)*INV_M;
    sg = fsigm(cq.y); lo4.y = __expf(-csum.y)*sg; cg4.y = lo4.y*(1.f-sg)*INV_M;
    sg = fsigm(cq.z); lo4.z = __expf(-csum.z)*sg; cg4.z = lo4.z*(1.f-sg)*INV_M;
    sg = fsigm(cq.w); lo4.w = __expf(-csum.w)*sg; cg4.w = lo4.w*(1.f-sg)*INV_M;
    *reinterpret_cast<float4*>(&g_ws[O_LOSS + i])  = lo4;
    *reinterpret_cast<float4*>(&g_ws[O_CGRAD + i]) = cg4;
}
// per-literal CSR gather (warp per literal, float4)
__global__ void k_gather(const float* __restrict__ src, int sstride,
                         float* __restrict__ dst){
    const int warp = threadIdx.x >> 5, lane = threadIdx.x & 31;
    const int l = blockIdx.x*4 + warp;
    int f4 = lane << 2;
    int d = g_deg[l];
    if (d > CSR_W) d = CSR_W;
    float4 s = make_float4(0.f,0.f,0.f,0.f);
    for (int j = 0; j < d; j++) {
        int c = g_csr[(size_t)l*CSR_W + j];
        float4 v = *reinterpret_cast<const float4*>(&src[(size_t)c*sstride + f4]);
        s.x += v.x; s.y += v.y; s.z += v.z; s.w += v.w;
    }
    *reinterpret_cast<float4*>(&dst[(size_t)l*128 + f4]) = s;
}
__global__ void k_pn_scale(float n, float* stat){
    int f = threadIdx.x;
    float mean = stat[f] / n;
    float var  = stat[128 + f] / n - mean*mean;
    __shared__ float sh[128];
    sh[f] = var; __syncthreads();
    for (int s = 64; s > 0; s >>= 1) { if (f < s) sh[f] += sh[f+s]; __syncthreads(); }
    stat[256 + f] = mean;
    if (f == 0) stat[384] = rsqrtf(sh[0]*(1.f/128.f) + 1e-6f);
    stat[f] = 0.f;
    stat[128 + f] = 0.f;
}
__global__ void k_pn_apply(const float* __restrict__ x, const float* __restrict__ stat,
                           float* __restrict__ dst){
    int r = blockIdx.x, f = threadIdx.x;
    float v = (x[(size_t)r*128 + f] - stat[256 + f]) * stat[384];
    size_t i = (size_t)r*128 + f;
    dst[i] = v*0.25f + 0.1f*dst[i];
}

// ---------------- host ----------------
template<int MODE, int STATS>
static void mmgemm(GArgs ga, const __half* Bg, const float* bias, float* C,
                   int M, int K, int KP, int Ntot, int relu, float* statp = nullptr){
    cudaFuncSetAttribute(k_mma64<MODE,STATS>, cudaFuncAttributeMaxDynamicSharedMemorySize, G64_SMEM);
    dim3 grid(Ntot/64, M/128);
    k_mma64<MODE,STATS><<<grid, 256, G64_SMEM>>>(ga, Bg, bias, C, K, KP, Ntot, relu, statp);
}

extern "C" void kernel_launch(void* const* d_in, const int* in_sizes, int n_in,
                              void* d_out, int out_size)
{
    (void)in_sizes; (void)n_in; (void)out_size;
    const int*   edge_lit    = (const int*)d_in[0];
    const int*   edge_clause = (const int*)d_in[1];
    const float* noise_v = (const float*)d_in[2];
    const float* noise_c = (const float*)d_in[3];
    const float* vq_w0 = (const float*)d_in[4];  const float* vq_b0 = (const float*)d_in[5];
    const float* vq_w1 = (const float*)d_in[6];  const float* vq_b1 = (const float*)d_in[7];
    const float* cq_w0 = (const float*)d_in[8];  const float* cq_b0 = (const float*)d_in[9];
    const float* cq_w1 = (const float*)d_in[10]; const float* cq_b1 = (const float*)d_in[11];
    const float* cm_w0 = (const float*)d_in[12]; const float* cm_b0 = (const float*)d_in[13];
    const float* cm_w1 = (const float*)d_in[14]; const float* cm_b1 = (const float*)d_in[15];
    const float* ug_w0 = (const float*)d_in[16]; const float* ug_b0 = (const float*)d_in[17];
    const float* ug_w1 = (const float*)d_in[18]; const float* ug_b1 = (const float*)d_in[19];
    const float* ug_w2 = (const float*)d_in[20]; const float* ug_b2 = (const float*)d_in[21];
    const float* co_w0 = (const float*)d_in[22]; const float* co_b0 = (const float*)d_in[23];
    const float* co_w1 = (const float*)d_in[24]; const float* co_b1 = (const float*)d_in[25];
    float* out = (float*)d_out;

    float* ws; cudaGetSymbolAddress((void**)&ws, g_ws);
    __half* w16 = reinterpret_cast<__half*>(ws + O_WT);
    float* statc = ws + O_STATC;
    float* statv = ws + O_STATV;

    cudaFuncSetAttribute(k_co0, cudaFuncAttributeMaxDynamicSharedMemorySize, CO_SMEM);

    {
        size_t n = (size_t)(NV+NC)*128;
        k_init<<<(unsigned)((n+255)/256), 256>>>(ws + O_VARS, n);
    }
    k_count_csr<<<(NE+255)/256, 256>>>(edge_lit, edge_clause);
    {
        WSrc s;
        s.w[0]=vq_w0; s.w[1]=vq_w1; s.w[2]=cq_w0; s.w[3]=cq_w1; s.w[4]=cm_w0;
        s.w[5]=cm_w1; s.w[6]=ug_w0; s.w[7]=ug_w1; s.w[8]=ug_w2; s.w[9]=co_w0;
        k_weights_wsplit<<<(OW_END+255)/256, 256>>>(s, w16);
    }

    for (int r = 0; r < 4; r++) {
        const float* nv_r = noise_v + (size_t)r*NV*4;
        const float* nc_r = noise_c + (size_t)r*NC*4;
        GArgs ga{};

        ga = {ws+O_CLS, nc_r, 0, 0, 0, 0};
        mmgemm<M_CAT4,0>(ga, w16+OW_cq0, cq_b0, ws+O_HC, NC, 132, 136, 128, 1);
        ga = {ws+O_HC, 0, 0, 0, 0, 0};
        mmgemm<M_PLAIN,0>(ga, w16+OW_cq1, cq_b1, ws+O_CQ, NC, 128, 128, 128, 0);
        ga = {ws+O_VARS, nv_r, 0, 0, 0, 0};
        mmgemm<M_CAT4,0>(ga, w16+OW_vq0, vq_b0, ws+O_HV, NV, 132, 136, 128, 1);
        ga = {ws+O_HV, 0, 0, 0, 0, 0};
        mmgemm<M_PLAIN,0>(ga, w16+OW_vq1, vq_b1, ws+O_VQ, NV, 128, 128, 128, 0);

        // SP once per literal (HV is free now), then csum gather + loss/cgrad
        k_softplus<<<NL/4, 128>>>(ws+O_VQ, ws+O_HV);
        k_csum_loss<<<NC/4, 128>>>(edge_lit, edge_clause, ws+O_HV);
        k_gather<<<NL/4, 128>>>(ws+O_LOSS, 128, ws+O_DLITS);

        ga = {ws+O_CLS, ws+O_LOSS, ws+O_CGRAD, 0, 0, 0};
        mmgemm<M_CMIN,0>(ga, w16+OW_cm0, cm_b0, ws+O_HC, NC, 384, 384, 256, 1);
        ga = {ws+O_HC, 0, 0, 0, 0, 0};
        mmgemm<M_PLAIN,1>(ga, w16+OW_cm1, cm_b1, ws+O_CDATA, NC, 256, 256, 256, 0, statc);

        k_gather<<<NL/4, 128>>>(ws+O_CDATA, 256, ws+O_VL);
        k_pn_scale<<<1, 128>>>((float)NC, statc);

        ga = {ws+O_VQ, ws+O_DLITS, ws+O_VARS, ws+O_VL, ws+O_DEGW, ws+O_VDEGW};
        mmgemm<M_UNIT,0>(ga, w16+OW_ug0, ug_b0, ws+O_HV, NV, 512, 512, 256, 1);
        ga = {ws+O_HV, 0, 0, 0, 0, 0};
        mmgemm<M_PLAIN,0>(ga, w16+OW_ug1, ug_b1, ws+O_HV2, NV, 256, 256, 256, 1);
        ga = {ws+O_HV2, 0, 0, 0, 0, 0};
        mmgemm<M_PLAIN,2>(ga, w16+OW_ug2, ug_b2, ws+O_VOUT, NV, 256, 256, 128, 0, statv);

        k_pn_scale<<<1, 128>>>((float)NV, statv);
        k_pn_apply<<<NV, 128>>>(ws+O_VOUT, statv, ws+O_VARS);

        k_co0<<<dim3(1, NC/128), 512, CO_SMEM>>>(ws+O_CDATA, ws+O_CLS, statc,
                                                 w16+OW_co0, co_b0, out, r, co_w1, co_b1);
    }
}

// round 12
// speedup vs baseline: 2.2856x; 1.0548x over previous
#include <cuda_runtime.h>
#include <cuda_fp16.h>
#include <math.h>
#include <stdint.h>

#define NV 24576
#define NC 98304
#define NE 294912
#define NL 49152
#define INV_M (1.0f/12582912.0f)
#define CSR_W 40

// ---------------- workspace layout (floats) ----------------
static constexpr size_t O_VARS   = 0;
static constexpr size_t O_CLS    = O_VARS  + (size_t)NV*128;
static constexpr size_t O_HV     = O_CLS   + (size_t)NC*128;   // NV x 256 fp32: SP table (NL x 128)
static constexpr size_t O_VQ     = O_HV    + (size_t)NV*256;
static constexpr size_t O_CQ     = O_VQ    + (size_t)NV*128;
static constexpr size_t O_CGRAD  = O_CQ    + (size_t)NC*128;
static constexpr size_t O_LOSS   = O_CGRAD + (size_t)NC*128;
static constexpr size_t O_CDATA  = O_LOSS  + (size_t)NC*128;   // NC x 256
static constexpr size_t O_DLITS  = O_CDATA + (size_t)NC*256;   // NL x 128
static constexpr size_t O_VL     = O_DLITS + (size_t)NL*128;   // NL x 128
static constexpr size_t O_VOUT   = O_VL    + (size_t)NL*128;   // NV x 128
static constexpr size_t O_DEGW   = O_VOUT  + (size_t)NV*128;   // NL
static constexpr size_t O_VDEGW  = O_DEGW  + NL;               // NV
static constexpr size_t O_STATC  = O_VDEGW + NV;               // 512
static constexpr size_t O_STATV  = O_STATC + 512;              // 512
static constexpr size_t O_WT     = O_STATV + 512;              // fp16 weights (238592 floats)
static constexpr size_t O_H16A   = O_WT    + 240000;           // fp16: NC x 256 halves
static constexpr size_t O_H16B   = O_H16A  + (size_t)NC*128;   // fp16: NV x 256 halves
static constexpr size_t WS_TOTAL = O_H16B  + (size_t)NV*128 + 64;

static constexpr size_t OW_vq0 = 0;
static constexpr size_t OW_vq1 = 17408;
static constexpr size_t OW_cq0 = 33792;
static constexpr size_t OW_cq1 = 51200;
static constexpr size_t OW_cm0 = 67584;
static constexpr size_t OW_cm1 = 165888;
static constexpr size_t OW_ug0 = 231424;
static constexpr size_t OW_ug1 = 362496;
static constexpr size_t OW_ug2 = 428032;
static constexpr size_t OW_co0 = 460800;
static constexpr int    OW_END = 477184;

__device__ float g_ws[WS_TOTAL];
__device__ int   g_deg[NL];
__device__ int   g_csr[(size_t)NL * CSR_W];

// ---------------- PTX helpers ----------------
__device__ __forceinline__ uint32_t smem_u32(const void* p){
    uint32_t a;
    asm("{ .reg .u64 t; cvta.to.shared.u64 t, %1; cvt.u32.u64 %0, t; }" : "=r"(a) : "l"(p));
    return a;
}
__device__ __forceinline__ void ldsm4(uint32_t* r, uint32_t addr){
    asm volatile("ldmatrix.sync.aligned.m8n8.x4.shared.b16 {%0,%1,%2,%3}, [%4];"
        : "=r"(r[0]), "=r"(r[1]), "=r"(r[2]), "=r"(r[3]) : "r"(addr));
}
__device__ __forceinline__ void mma_f16(float* c, const uint32_t* a, const uint32_t* b){
    asm volatile("mma.sync.aligned.m16n8k16.row.col.f32.f16.f16.f32 "
        "{%0,%1,%2,%3}, {%4,%5,%6,%7}, {%8,%9}, {%0,%1,%2,%3};"
        : "+f"(c[0]), "+f"(c[1]), "+f"(c[2]), "+f"(c[3])
        : "r"(a[0]), "r"(a[1]), "r"(a[2]), "r"(a[3]), "r"(b[0]), "r"(b[1]));
}
__device__ __forceinline__ void cp16(uint32_t dst, const void* src, bool pred){
    int sz = pred ? 16 : 0;
    asm volatile("cp.async.cg.shared.global [%0], [%1], 16, %2;"
                 :: "r"(dst), "l"(src), "r"(sz));
}
#define CP_COMMIT() asm volatile("cp.async.commit_group;" ::: "memory")
#define CP_WAIT1()  asm volatile("cp.async.wait_group 1;" ::: "memory")

__device__ __forceinline__ float sigm(float x){ return 1.f/(1.f+expf(-x)); }
__device__ __forceinline__ float softplusf(float x){ return fmaxf(x,0.f)+log1pf(expf(-fabsf(x))); }
__device__ __forceinline__ float fsigm(float x){ return __fdividef(1.f, 1.f+__expf(-x)); }
__device__ __forceinline__ float fsoftplus(float x){ return fmaxf(x,0.f)+__logf(1.f+__expf(-fabsf(x))); }

#define M_PLAIN 0
#define M_CAT4  1
#define M_CMIN  2
#define M_UNIT  3
#define M_A16   4     // A already fp16, row-major [M][K], loaded via cp.async

struct GArgs {
    const float* p0; const float* p1; const float* p2;
    const float* p3; const float* p4; const float* p5;
};

// ---------------- fp16 MMA GEMM, tile 128x64, 256 thr, 2 CTAs/SM ----------------
// smem: A 3 planes [0,30720), B 3 planes [30720,61440)
static constexpr int G64_SMEM = 61440;

// CH: write C as fp16 (C points to half buffer). SPE: also emit softplus table (vq1).
template<int MODE, int STATS, int CH, int SPE>
__global__ void __launch_bounds__(256, 2)
k_mma64(GArgs ga, const __half* __restrict__ Bg, const float* __restrict__ bias,
        void* __restrict__ Cv, int K, int KP, int Ntot, int relu,
        float* __restrict__ statp, float* __restrict__ spbuf)
{
    extern __shared__ __align__(16) char smem[];
    const uint32_t sbase = smem_u32(smem);
    const int t = threadIdx.x;
    const int lane = t & 31, wid = t >> 5;
    const int warp_m = wid & 3;
    const int warp_n = wid >> 2;
    const int bm = blockIdx.y * 128;
    const int bn = blockIdx.x * 64;

    constexpr int LDH    = 40;
    constexpr int APLANE = 10240;
    constexpr int BPLANE = 5120;
    constexpr int A0     = 0;
    constexpr int B0     = 30720;

    float acc[2][4][4];
    #pragma unroll
    for (int i=0;i<2;i++)
        #pragma unroll
        for(int j=0;j<4;j++)
            #pragma unroll
            for(int q=0;q<4;q++) acc[i][j][q]=0.f;

    const int nch = (K + 31) >> 5;
    float4 aReg[4];

    auto loadA = [&](int c){
        const int k0 = c << 5;
        #pragma unroll
        for (int i = 0; i < 4; i++) {
            int idx = t + i*256;
            int row = idx >> 3, col4 = (idx & 7) << 2;
            int gk = k0 + col4;
            int r = bm + row;
            float4 v = make_float4(0.f,0.f,0.f,0.f);
            if (MODE == M_PLAIN) {
                if (gk < K) v = *reinterpret_cast<const float4*>(&ga.p0[(size_t)r*K + gk]);
            } else if (MODE == M_CAT4) {
                if (gk < 128)       v = *reinterpret_cast<const float4*>(&ga.p0[(size_t)r*128 + gk]);
                else if (gk == 128) v = *reinterpret_cast<const float4*>(&ga.p1[(size_t)r*4]);
            } else if (MODE == M_CMIN) {
                int seg = gk >> 7, cc = gk & 127;
                if (seg == 0)      v = *reinterpret_cast<const float4*>(&ga.p0[(size_t)r*128 + cc]);
                else if (seg == 1) {
                    v = *reinterpret_cast<const float4*>(&ga.p1[(size_t)r*128 + cc]);
                    v.x*=4.f; v.y*=4.f; v.z*=4.f; v.w*=4.f;
                } else             v = *reinterpret_cast<const float4*>(&ga.p2[(size_t)r*128 + cc]);
            } else if (MODE == M_UNIT) {
                int seg = gk >> 7, cc = gk & 127;
                if (seg == 0) {
                    float4 vq = *reinterpret_cast<const float4*>(&ga.p0[(size_t)r*128 + cc]);
                    float4 dp = *reinterpret_cast<const float4*>(&ga.p1[(size_t)r*128 + cc]);
                    float4 dn = *reinterpret_cast<const float4*>(&ga.p1[(size_t)(r+NV)*128 + cc]);
                    float w = ga.p5[r];
                    float sp;
                    sp = fsigm(vq.x); v.x = -INV_M*(dp.x*sp - dn.x*(1.f-sp))*w;
                    sp = fsigm(vq.y); v.y = -INV_M*(dp.y*sp - dn.y*(1.f-sp))*w;
                    sp = fsigm(vq.z); v.z = -INV_M*(dp.z*sp - dn.z*(1.f-sp))*w;
                    sp = fsigm(vq.w); v.w = -INV_M*(dp.w*sp - dn.w*(1.f-sp))*w;
                } else if (seg == 1) {
                    v = *reinterpret_cast<const float4*>(&ga.p2[(size_t)r*128 + cc]);
                } else if (seg == 2) {
                    v = *reinterpret_cast<const float4*>(&ga.p3[(size_t)r*128 + cc]);
                    float w = ga.p4[r];
                    v.x*=w; v.y*=w; v.z*=w; v.w*=w;
                } else {
                    v = *reinterpret_cast<const float4*>(&ga.p3[(size_t)(r+NV)*128 + cc]);
                    float w = ga.p4[r+NV];
                    v.x*=w; v.y*=w; v.z*=w; v.w*=w;
                }
            }
            aReg[i] = v;
        }
    };
    auto cpA16 = [&](int c){
        const __half* A16 = reinterpret_cast<const __half*>(ga.p0);
        const int k0 = c << 5;
        const uint32_t ab = sbase + A0 + (uint32_t)(c % 3)*APLANE;
        #pragma unroll
        for (int i = 0; i < 2; i++) {
            int idx = t + i*256;
            int row = idx >> 2, q = idx & 3;
            int gk = k0 + q*8;
            cp16(ab + (uint32_t)(row*LDH + q*8)*2, A16 + (size_t)(bm+row)*K + gk, true);
        }
    };
    auto cpB = [&](int c){
        const int k0 = c << 5;
        const uint32_t bb = sbase + B0 + (uint32_t)(c % 3)*BPLANE;
        int row = t >> 2, q = t & 3;
        int gk = k0 + q*8;
        bool ok = (gk + 8 <= KP);
        size_t off = ok ? ((size_t)(bn+row)*KP + gk) : 0;
        cp16(bb + (uint32_t)(row*LDH + q*8)*2, Bg + off, ok);
    };
    auto storeA = [&](int s){
        char* sc = smem + A0 + s*APLANE;
        #pragma unroll
        for (int i = 0; i < 4; i++) {
            int idx = t + i*256;
            int row = idx >> 3, col4 = (idx & 7) << 2;
            __half2 h0 = __floats2half2_rn(aReg[i].x, aReg[i].y);
            __half2 h1 = __floats2half2_rn(aReg[i].z, aReg[i].w);
            uint2 pk;
            pk.x = *reinterpret_cast<uint32_t*>(&h0);
            pk.y = *reinterpret_cast<uint32_t*>(&h1);
            *reinterpret_cast<uint2*>(sc + (row*LDH + col4)*2) = pk;
        }
    };
    auto compute = [&](int c){
        const int ap = (MODE == M_A16) ? (c % 3) : (c & 1);
        const uint32_t sa = sbase + A0 + (uint32_t)ap*APLANE;
        const uint32_t sb = sbase + B0 + (uint32_t)(c % 3)*BPLANE;
        const int grp = lane >> 3, r = lane & 7;
        #pragma unroll
        for (int ks = 0; ks < 32; ks += 16) {
            uint32_t aH[2][4], bX[4][2];
            #pragma unroll
            for (int mt = 0; mt < 2; mt++) {
                int arow = warp_m*32 + mt*16 + (grp & 1)*8 + r;
                int acol = ks + (grp >> 1)*8;
                ldsm4(aH[mt], sa + (uint32_t)(arow*LDH + acol)*2);
            }
            #pragma unroll
            for (int p = 0; p < 2; p++) {
                int brow = warp_n*32 + p*16 + (grp >> 1)*8 + r;
                int bcol = ks + (grp & 1)*8;
                uint32_t tmp[4];
                ldsm4(tmp, sb + (uint32_t)(brow*LDH + bcol)*2);
                bX[2*p][0]=tmp[0]; bX[2*p][1]=tmp[1]; bX[2*p+1][0]=tmp[2]; bX[2*p+1][1]=tmp[3];
            }
            #pragma unroll
            for (int mt = 0; mt < 2; mt++)
                #pragma unroll
                for (int nt = 0; nt < 4; nt++)
                    mma_f16(acc[mt][nt], aH[mt], bX[nt]);
        }
    };

    if (MODE == M_A16) {
        cpA16(0); cpB(0); CP_COMMIT();
        if (nch > 1) { cpA16(1); cpB(1); }
        CP_COMMIT();
        CP_WAIT1();
        __syncthreads();
        for (int c = 0; c < nch; c++) {
            compute(c);
            if (c+2 < nch) { cpA16(c+2); cpB(c+2); }
            CP_COMMIT();
            CP_WAIT1();
            __syncthreads();
        }
    } else {
        loadA(0);
        cpB(0);
        CP_COMMIT();
        storeA(0);
        if (nch > 1) { loadA(1); cpB(1); }
        CP_COMMIT();
        CP_WAIT1();
        __syncthreads();
        for (int c = 0; c < nch; c++) {
            compute(c);
            if (c+1 < nch) storeA((c+1) & 1);
            if (c+2 < nch) cpB(c+2);
            CP_COMMIT();
            if (c+2 < nch) loadA(c+2);
            CP_WAIT1();
            __syncthreads();
        }
    }

    // ---- store C ----
    #pragma unroll
    for (int mt = 0; mt < 2; mt++) {
        int row0 = bm + warp_m*32 + mt*16 + (lane >> 2);
        #pragma unroll
        for (int nt = 0; nt < 4; nt++) {
            int col = bn + warp_n*32 + nt*8 + (lane & 3)*2;
            float2 bv = *reinterpret_cast<const float2*>(&bias[col]);
            float v0 = acc[mt][nt][0] + bv.x, v1 = acc[mt][nt][1] + bv.y;
            float v2 = acc[mt][nt][2] + bv.x, v3 = acc[mt][nt][3] + bv.y;
            if (relu) { v0=fmaxf(v0,0.f); v1=fmaxf(v1,0.f); v2=fmaxf(v2,0.f); v3=fmaxf(v3,0.f); }
            if (CH) {
                __half* C16 = reinterpret_cast<__half*>(Cv);
                __half2 h01 = __floats2half2_rn(v0, v1);
                __half2 h23 = __floats2half2_rn(v2, v3);
                *reinterpret_cast<__half2*>(&C16[(size_t)row0*Ntot + col])     = h01;
                *reinterpret_cast<__half2*>(&C16[(size_t)(row0+8)*Ntot + col]) = h23;
            } else {
                float* C = reinterpret_cast<float*>(Cv);
                *reinterpret_cast<float2*>(&C[(size_t)row0*Ntot + col])     = make_float2(v0,v1);
                *reinterpret_cast<float2*>(&C[(size_t)(row0+8)*Ntot + col]) = make_float2(v2,v3);
            }
            if (SPE) {   // vq1: emit softplus(+v) and softplus(-v) tables
                *reinterpret_cast<float2*>(&spbuf[(size_t)row0*128 + col]) =
                    make_float2(fsoftplus(v0), fsoftplus(v1));
                *reinterpret_cast<float2*>(&spbuf[(size_t)(row0+NV)*128 + col]) =
                    make_float2(fsoftplus(-v0), fsoftplus(-v1));
                *reinterpret_cast<float2*>(&spbuf[(size_t)(row0+8)*128 + col]) =
                    make_float2(fsoftplus(v2), fsoftplus(v3));
                *reinterpret_cast<float2*>(&spbuf[(size_t)(row0+8+NV)*128 + col]) =
                    make_float2(fsoftplus(-v2), fsoftplus(-v3));
            }
        }
    }

    if (STATS) {
        bool active = (STATS == 2) || (bn >= 128);
        if (active) {
            float* red = reinterpret_cast<float*>(smem);
            if (t < 128) red[t] = 0.f;
            __syncthreads();
            #pragma unroll
            for (int nt = 0; nt < 4; nt++) {
                int c0 = warp_n*32 + nt*8 + (lane & 3)*2;
                float b0 = __ldg(&bias[bn + c0]), b1 = __ldg(&bias[bn + c0 + 1]);
                float s0=0.f, s1=0.f, q0=0.f, q1=0.f;
                #pragma unroll
                for (int mt = 0; mt < 2; mt++) {
                    float v0 = acc[mt][nt][0] + b0, v1 = acc[mt][nt][1] + b1;
                    float v2 = acc[mt][nt][2] + b0, v3 = acc[mt][nt][3] + b1;
                    s0 += v0 + v2; s1 += v1 + v3;
                    q0 += v0*v0 + v2*v2; q1 += v1*v1 + v3*v3;
                }
                #pragma unroll
                for (int o = 4; o < 32; o <<= 1) {
                    s0 += __shfl_xor_sync(0xffffffffu, s0, o);
                    s1 += __shfl_xor_sync(0xffffffffu, s1, o);
                    q0 += __shfl_xor_sync(0xffffffffu, q0, o);
                    q1 += __shfl_xor_sync(0xffffffffu, q1, o);
                }
                if (lane < 4) {
                    atomicAdd(&red[c0],      s0);
                    atomicAdd(&red[c0+1],    s1);
                    atomicAdd(&red[64+c0],   q0);
                    atomicAdd(&red[64+c0+1], q1);
                }
            }
            __syncthreads();
            int cb = (STATS == 1) ? (bn - 128) : bn;
            if (t < 64) {
                atomicAdd(&statp[cb + t],       red[t]);
                atomicAdd(&statp[128 + cb + t], red[64 + t]);
            }
        }
    }
}

// ---------------- co0 kernel (unchanged: fp32 pn-apply loader, logits epilogue) ----
static constexpr int CO_SMEM = 51200;

__global__ void __launch_bounds__(512, 1)
k_co0(const float* __restrict__ cdata, float* __restrict__ cls,
      const float* __restrict__ statc,
      const __half* __restrict__ Bg, const float* __restrict__ bias,
      float* __restrict__ out, int round,
      const float* __restrict__ w1, const float* __restrict__ b1)
{
    extern __shared__ __align__(16) char smem[];
    const uint32_t sbase = smem_u32(smem);
    const int t = threadIdx.x;
    const int lane = t & 31, wid = t >> 5;
    const int warp_m = wid & 3, warp_n = wid >> 2;
    const int bm = blockIdx.y * 128;

    constexpr int LDH = 40, PLANE = 10240, A0 = 0, B0 = 20480;
    constexpr int K = 128, nch = 4;

    float acc[2][4][4];
    #pragma unroll
    for (int i=0;i<2;i++)
        #pragma unroll
        for(int j=0;j<4;j++)
            #pragma unroll
            for(int q=0;q<4;q++) acc[i][j][q]=0.f;

    float4 aReg[2];
    const float scale = statc[384];

    auto loadA = [&](int c){
        const int k0 = c << 5;
        #pragma unroll
        for (int i = 0; i < 2; i++) {
            int idx = t + i*512;
            int row = idx >> 3, col4 = (idx & 7) << 2;
            int gk = k0 + col4;
            int r = bm + row;
            float4 v = *reinterpret_cast<const float4*>(&cdata[(size_t)r*256 + 128 + gk]);
            float4 m = *reinterpret_cast<const float4*>(&statc[256 + gk]);
            float4 o = *reinterpret_cast<const float4*>(&cls[(size_t)r*128 + gk]);
            v.x = (v.x - m.x)*scale*0.25f + 0.1f*o.x;
            v.y = (v.y - m.y)*scale*0.25f + 0.1f*o.y;
            v.z = (v.z - m.z)*scale*0.25f + 0.1f*o.z;
            v.w = (v.w - m.w)*scale*0.25f + 0.1f*o.w;
            *reinterpret_cast<float4*>(&cls[(size_t)r*128 + gk]) = v;
            aReg[i] = v;
        }
    };
    auto cpB = [&](int c){
        const int k0 = c << 5;
        const uint32_t bb = sbase + B0 + (uint32_t)(c % 3)*PLANE;
        int row = t >> 2, q = t & 3;
        int gk = k0 + q*8;
        cp16(bb + (uint32_t)(row*LDH + q*8)*2, Bg + (size_t)row*K + gk, true);
    };
    auto storeA = [&](int s){
        char* sc = smem + A0 + s*PLANE;
        #pragma unroll
        for (int i = 0; i < 2; i++) {
            int idx = t + i*512;
            int row = idx >> 3, col4 = (idx & 7) << 2;
            __half2 h0 = __floats2half2_rn(aReg[i].x, aReg[i].y);
            __half2 h1 = __floats2half2_rn(aReg[i].z, aReg[i].w);
            uint2 pk;
            pk.x = *reinterpret_cast<uint32_t*>(&h0);
            pk.y = *reinterpret_cast<uint32_t*>(&h1);
            *reinterpret_cast<uint2*>(sc + (row*LDH + col4)*2) = pk;
        }
    };
    auto compute = [&](int c){
        const uint32_t sa = sbase + A0 + (uint32_t)(c & 1)*PLANE;
        const uint32_t sb = sbase + B0 + (uint32_t)(c % 3)*PLANE;
        const int grp = lane >> 3, r = lane & 7;
        #pragma unroll
        for (int ks = 0; ks < 32; ks += 16) {
            uint32_t aH[2][4], bX[4][2];
            #pragma unroll
            for (int mt = 0; mt < 2; mt++) {
                int arow = warp_m*32 + mt*16 + (grp & 1)*8 + r;
                int acol = ks + (grp >> 1)*8;
                ldsm4(aH[mt], sa + (uint32_t)(arow*LDH + acol)*2);
            }
            #pragma unroll
            for (int p = 0; p < 2; p++) {
                int brow = warp_n*32 + p*16 + (grp >> 1)*8 + r;
                int bcol = ks + (grp & 1)*8;
                uint32_t tmp[4];
                ldsm4(tmp, sb + (uint32_t)(brow*LDH + bcol)*2);
                bX[2*p][0]=tmp[0]; bX[2*p][1]=tmp[1]; bX[2*p+1][0]=tmp[2]; bX[2*p+1][1]=tmp[3];
            }
            #pragma unroll
            for (int mt = 0; mt < 2; mt++)
                #pragma unroll
                for (int nt = 0; nt < 4; nt++)
                    mma_f16(acc[mt][nt], aH[mt], bX[nt]);
        }
    };

    loadA(0);
    cpB(0);
    CP_COMMIT();
    storeA(0);
    loadA(1); cpB(1);
    CP_COMMIT();
    CP_WAIT1();
    __syncthreads();

    for (int c = 0; c < nch; c++) {
        compute(c);
        if (c+1 < nch) storeA((c+1) & 1);
        if (c+2 < nch) cpB(c+2);
        CP_COMMIT();
        if (c+2 < nch) loadA(c+2);
        CP_WAIT1();
        __syncthreads();
    }

    float* red = reinterpret_cast<float*>(smem);
    if (t < 128) red[t] = 0.f;
    __syncthreads();
    #pragma unroll
    for (int mt = 0; mt < 2; mt++) {
        int rl = warp_m*32 + mt*16 + (lane >> 2);
        float p0 = 0.f, p1 = 0.f;
        #pragma unroll
        for (int nt = 0; nt < 4; nt++) {
            int col = warp_n*32 + nt*8 + (lane & 3)*2;
            float2 bv = *reinterpret_cast<const float2*>(&bias[col]);
            float wa = __ldg(&w1[col]), wb = __ldg(&w1[col+1]);
            float v0 = fmaxf(acc[mt][nt][0] + bv.x, 0.f);
            float v1 = fmaxf(acc[mt][nt][1] + bv.y, 0.f);
            float v2 = fmaxf(acc[mt][nt][2] + bv.x, 0.f);
            float v3 = fmaxf(acc[mt][nt][3] + bv.y, 0.f);
            p0 += v0*wa + v1*wb;
            p1 += v2*wa + v3*wb;
        }
        atomicAdd(&red[rl], p0);
        atomicAdd(&red[rl+8], p1);
    }
    __syncthreads();
    if (t < 128) {
        float x = red[t] + __ldg(&b1[0]);
        int row = bm + t;
        out[(size_t)round*NC + row] = sigm(x);
        out[(size_t)4*NC + (size_t)round*NC + row] = softplusf(x);
    }
}

// ---------------- setup kernels ----------------
__global__ void k_init(float* p, size_t nfill){
    size_t i = (size_t)blockIdx.x*blockDim.x + threadIdx.x;
    if (i < nfill) p[i] = 1.f;
    if (i < NL) g_deg[i] = 0;
    if (i < 256) { g_ws[O_STATC + i] = 0.f; g_ws[O_STATV + i] = 0.f; }
}
__global__ void k_count_csr(const int* __restrict__ lit, const int* __restrict__ cls){
    int e = blockIdx.x*blockDim.x + threadIdx.x;
    if (e >= NE) return;
    int l = lit[e];
    int pos = atomicAdd(&g_deg[l], 1);
    if (pos < CSR_W) g_csr[(size_t)l*CSR_W + pos] = cls[e];
}
struct WSrc { const float* w[10]; };
__global__ void k_weights_wsplit(WSrc ws, __half* __restrict__ w16){
    const int offs[11] = {0, 17408, 33792, 51200, 67584, 165888, 231424,
                          362496, 428032, 460800, 477184};
    const int Ks[10]  = {132,128,132,128,384,256,512,256,256,128};
    const int KPs[10] = {136,128,136,128,384,256,512,256,256,128};
    const int Ns[10]  = {128,128,128,128,256,256,256,256,128,128};
    int idx = blockIdx.x*blockDim.x + threadIdx.x;
    if (idx < NL) g_ws[O_DEGW + idx] = rsqrtf(fmaxf((float)g_deg[idx], 1.f));
    if (idx < NV) g_ws[O_VDEGW + idx] = 4.f*rsqrtf(fmaxf((float)(g_deg[idx] + g_deg[idx+NV]), 1.f));
    if (idx >= offs[10]) return;
    int seg = 0;
    #pragma unroll
    for (int s = 1; s < 10; s++) if (idx >= offs[s]) seg = s;
    int local = idx - offs[seg];
    int K = Ks[seg], KP = KPs[seg], N = Ns[seg];
    int n = local / KP, k = local % KP;
    float v = (k < K) ? ws.w[seg][(size_t)k*N + n] : 0.f;
    w16[idx] = __float2half_rn(v);
}

// ---------------- edge kernels ----------------
__global__ void k_csum_loss(const int* __restrict__ lit, const int* __restrict__ cls,
                            const float* __restrict__ sp){
    const int warp = threadIdx.x >> 5, lane = threadIdx.x & 31;
    const int c = blockIdx.x*4 + warp;
    int s01 = 0;
    if (lane < 2) {
        int key = c + lane;
        int lo = 0, hi = NE;
        while (lo < hi) { int mid = (lo+hi) >> 1; if (cls[mid] < key) lo = mid+1; else hi = mid; }
        s01 = lo;
    }
    int s0 = __shfl_sync(0xffffffffu, s01, 0);
    int s1 = __shfl_sync(0xffffffffu, s01, 1);
    int f4 = lane << 2;
    float4 csum = make_float4(0.f,0.f,0.f,0.f);
    for (int e = s0; e < s1; e++) {
        int l = __ldg(&lit[e]);
        float4 v = *reinterpret_cast<const float4*>(&sp[(size_t)l*128 + f4]);
        csum.x += v.x; csum.y += v.y; csum.z += v.z; csum.w += v.w;
    }
    size_t i = (size_t)c*128 + f4;
    float4 cq = *reinterpret_cast<const float4*>(&g_ws[O_CQ + i]);
    float4 lo4, cg4;
    float sg;
    sg = fsigm(cq.x); lo4.x = __expf(-csum.x)*sg; cg4.x = lo4.x*(1.f-sg)*INV_M;
    sg = fsigm(cq.y); lo4.y = __expf(-csum.y)*sg; cg4.y = lo4.y*(1.f-sg)*INV_M;
    sg = fsigm(cq.z); lo4.z = __expf(-csum.z)*sg; cg4.z = lo4.z*(1.f-sg)*INV_M;
    sg = fsigm(cq.w); lo4.w = __expf(-csum.w)*sg; cg4.w = lo4.w*(1.f-sg)*INV_M;
    *reinterpret_cast<float4*>(&g_ws[O_LOSS + i])  = lo4;
    *reinterpret_cast<float4*>(&g_ws[O_CGRAD + i]) = cg4;
}
__global__ void k_gather(const float* __restrict__ src, int sstride,
                         float* __restrict__ dst){
    const int warp = threadIdx.x >> 5, lane = threadIdx.x & 31;
    const int l = blockIdx.x*4 + warp;
    int f4 = lane << 2;
    int d = g_deg[l];
    if (d > CSR_W) d = CSR_W;
    float4 s = make_float4(0.f,0.f,0.f,0.f);
    for (int j = 0; j < d; j++) {
        int c = g_csr[(size_t)l*CSR_W + j];
        float4 v = *reinterpret_cast<const float4*>(&src[(size_t)c*sstride + f4]);
        s.x += v.x; s.y += v.y; s.z += v.z; s.w += v.w;
    }
    *reinterpret_cast<float4*>(&dst[(size_t)l*128 + f4]) = s;
}
__global__ void k_pn_scale(float n, float* stat){
    int f = threadIdx.x;
    float mean = stat[f] / n;
    float var  = stat[128 + f] / n - mean*mean;
    __shared__ float sh[128];
    sh[f] = var; __syncthreads();
    for (int s = 64; s > 0; s >>= 1) { if (f < s) sh[f] += sh[f+s]; __syncthreads(); }
    stat[256 + f] = mean;
    if (f == 0) stat[384] = rsqrtf(sh[0]*(1.f/128.f) + 1e-6f);
    stat[f] = 0.f;
    stat[128 + f] = 0.f;
}
__global__ void k_pn_apply(const float* __restrict__ x, const float* __restrict__ stat,
                           float* __restrict__ dst){
    int r = blockIdx.x, f = threadIdx.x;
    float v = (x[(size_t)r*128 + f] - stat[256 + f]) * stat[384];
    size_t i = (size_t)r*128 + f;
    dst[i] = v*0.25f + 0.1f*dst[i];
}

// ---------------- host ----------------
template<int MODE, int STATS, int CH, int SPE>
static void mmgemm(GArgs ga, const __half* Bg, const float* bias, void* C,
                   int M, int K, int KP, int Ntot, int relu,
                   float* statp = nullptr, float* spbuf = nullptr){
    cudaFuncSetAttribute(k_mma64<MODE,STATS,CH,SPE>,
                         cudaFuncAttributeMaxDynamicSharedMemorySize, G64_SMEM);
    dim3 grid(Ntot/64, M/128);
    k_mma64<MODE,STATS,CH,SPE><<<grid, 256, G64_SMEM>>>(ga, Bg, bias, C, K, KP, Ntot, relu,
                                                        statp, spbuf);
}

extern "C" void kernel_launch(void* const* d_in, const int* in_sizes, int n_in,
                              void* d_out, int out_size)
{
    (void)in_sizes; (void)n_in; (void)out_size;
    const int*   edge_lit    = (const int*)d_in[0];
    const int*   edge_clause = (const int*)d_in[1];
    const float* noise_v = (const float*)d_in[2];
    const float* noise_c = (const float*)d_in[3];
    const float* vq_w0 = (const float*)d_in[4];  const float* vq_b0 = (const float*)d_in[5];
    const float* vq_w1 = (const float*)d_in[6];  const float* vq_b1 = (const float*)d_in[7];
    const float* cq_w0 = (const float*)d_in[8];  const float* cq_b0 = (const float*)d_in[9];
    const float* cq_w1 = (const float*)d_in[10]; const float* cq_b1 = (const float*)d_in[11];
    const float* cm_w0 = (const float*)d_in[12]; const float* cm_b0 = (const float*)d_in[13];
    const float* cm_w1 = (const float*)d_in[14]; const float* cm_b1 = (const float*)d_in[15];
    const float* ug_w0 = (const float*)d_in[16]; const float* ug_b0 = (const float*)d_in[17];
    const float* ug_w1 = (const float*)d_in[18]; const float* ug_b1 = (const float*)d_in[19];
    const float* ug_w2 = (const float*)d_in[20]; const float* ug_b2 = (const float*)d_in[21];
    const float* co_w0 = (const float*)d_in[22]; const float* co_b0 = (const float*)d_in[23];
    const float* co_w1 = (const float*)d_in[24]; const float* co_b1 = (const float*)d_in[25];
    float* out = (float*)d_out;

    float* ws; cudaGetSymbolAddress((void**)&ws, g_ws);
    __half* w16  = reinterpret_cast<__half*>(ws + O_WT);
    __half* h16a = reinterpret_cast<__half*>(ws + O_H16A);
    __half* h16b = reinterpret_cast<__half*>(ws + O_H16B);
    float* statc = ws + O_STATC;
    float* statv = ws + O_STATV;
    float* spbuf = ws + O_HV;          // softplus table, NL x 128

    cudaFuncSetAttribute(k_co0, cudaFuncAttributeMaxDynamicSharedMemorySize, CO_SMEM);

    {
        size_t n = (size_t)(NV+NC)*128;
        k_init<<<(unsigned)((n+255)/256), 256>>>(ws + O_VARS, n);
    }
    k_count_csr<<<(NE+255)/256, 256>>>(edge_lit, edge_clause);
    {
        WSrc s;
        s.w[0]=vq_w0; s.w[1]=vq_w1; s.w[2]=cq_w0; s.w[3]=cq_w1; s.w[4]=cm_w0;
        s.w[5]=cm_w1; s.w[6]=ug_w0; s.w[7]=ug_w1; s.w[8]=ug_w2; s.w[9]=co_w0;
        k_weights_wsplit<<<(OW_END+255)/256, 256>>>(s, w16);
    }

    for (int r = 0; r < 4; r++) {
        const float* nv_r = noise_v + (size_t)r*NV*4;
        const float* nc_r = noise_c + (size_t)r*NC*4;
        GArgs ga{};

        // cq: CLS+noise -> H16A (fp16) -> CQ (fp32)
        ga = {ws+O_CLS, nc_r, 0, 0, 0, 0};
        mmgemm<M_CAT4,0,1,0>(ga, w16+OW_cq0, cq_b0, h16a, NC, 132, 136, 128, 1);
        ga = {(const float*)h16a, 0, 0, 0, 0, 0};
        mmgemm<M_A16,0,0,0>(ga, w16+OW_cq1, cq_b1, ws+O_CQ, NC, 128, 128, 128, 0);
        // vq: VARS+noise -> H16A -> VQ (fp32) + softplus table
        ga = {ws+O_VARS, nv_r, 0, 0, 0, 0};
        mmgemm<M_CAT4,0,1,0>(ga, w16+OW_vq0, vq_b0, h16a, NV, 132, 136, 128, 1);
        ga = {(const float*)h16a, 0, 0, 0, 0, 0};
        mmgemm<M_A16,0,0,1>(ga, w16+OW_vq1, vq_b1, ws+O_VQ, NV, 128, 128, 128, 0,
                            nullptr, spbuf);

        k_csum_loss<<<NC/4, 128>>>(edge_lit, edge_clause, spbuf);
        k_gather<<<NL/4, 128>>>(ws+O_LOSS, 128, ws+O_DLITS);

        // cm: [CLS|4*loss|cgrad] -> H16A (NCx256 fp16) -> CDATA (fp32) + statc
        ga = {ws+O_CLS, ws+O_LOSS, ws+O_CGRAD, 0, 0, 0};
        mmgemm<M_CMIN,0,1,0>(ga, w16+OW_cm0, cm_b0, h16a, NC, 384, 384, 256, 1);
        ga = {(const float*)h16a, 0, 0, 0, 0, 0};
        mmgemm<M_A16,1,0,0>(ga, w16+OW_cm1, cm_b1, ws+O_CDATA, NC, 256, 256, 256, 0, statc);

        k_gather<<<NL/4, 128>>>(ws+O_CDATA, 256, ws+O_VL);
        k_pn_scale<<<1, 128>>>((float)NC, statc);

        // ug: unit -> H16A -> H16B -> VOUT (fp32) + statv
        ga = {ws+O_VQ, ws+O_DLITS, ws+O_VARS, ws+O_VL, ws+O_DEGW, ws+O_VDEGW};
        mmgemm<M_UNIT,0,1,0>(ga, w16+OW_ug0, ug_b0, h16a, NV, 512, 512, 256, 1);
        ga = {(const float*)h16a, 0, 0, 0, 0, 0};
        mmgemm<M_A16,0,1,0>(ga, w16+OW_ug1, ug_b1, h16b, NV, 256, 256, 256, 1);
        ga = {(const float*)h16b, 0, 0, 0, 0, 0};
        mmgemm<M_A16,2,0,0>(ga, w16+OW_ug2, ug_b2, ws+O_VOUT, NV, 256, 256, 128, 0, statv);

        k_pn_scale<<<1, 128>>>((float)NV, statv);
        k_pn_apply<<<NV, 128>>>(ws+O_VOUT, statv, ws+O_VARS);

        k_co0<<<dim3(1, NC/128), 512, CO_SMEM>>>(ws+O_CDATA, ws+O_CLS, statc,
                                                 w16+OW_co0, co_b0, out, r, co_w1, co_b1);
    }
}

// round 13
// speedup vs baseline: 2.9475x; 1.2896x over previous
#include <cuda_runtime.h>
#include <cuda_fp16.h>
#include <math.h>
#include <stdint.h>

#define NV 24576
#define NC 98304
#define NE 294912
#define NL 49152
#define INV_M (1.0f/12582912.0f)
#define CSR_W 40

// ---------------- workspace layout (floats) ----------------
static constexpr size_t O_VARS   = 0;
static constexpr size_t O_CLS    = O_VARS  + (size_t)NV*128;
static constexpr size_t O_VQ     = O_CLS   + (size_t)NC*128;
static constexpr size_t O_CQ     = O_VQ    + (size_t)NV*128;
static constexpr size_t O_LOSS   = O_CQ    + (size_t)NC*128;
static constexpr size_t O_CDATA  = O_LOSS  + (size_t)NC*128;   // NC x 256
static constexpr size_t O_VOUT   = O_CDATA + (size_t)NC*256;   // NV x 128
static constexpr size_t O_SP     = O_VOUT  + (size_t)NV*128;   // NL x 128
static constexpr size_t O_DEGW   = O_SP    + (size_t)NL*128;   // NL
static constexpr size_t O_VDEGW  = O_DEGW  + NL;               // NV
static constexpr size_t O_STATC  = O_VDEGW + NV;               // 512
static constexpr size_t O_STATV  = O_STATC + 512;              // 512
static constexpr size_t O_WT     = O_STATV + 512;              // fp16 weights
static constexpr size_t O_H16    = O_WT + 240000;              // fp16 area base

// half offsets within H16 area
static constexpr size_t H_CLSCAT  = 0;                              // NC x 136
static constexpr size_t H_VARSCAT = H_CLSCAT  + (size_t)NC*136;     // NV x 136
static constexpr size_t H_CMIN    = H_VARSCAT + (size_t)NV*136;     // NC x 384
static constexpr size_t H_UNIT    = H_CMIN    + (size_t)NC*384;     // NV x 512
static constexpr size_t H_A       = H_UNIT    + (size_t)NV*512;     // NC x 256
static constexpr size_t H_B       = H_A       + (size_t)NC*256;     // NV x 256
static constexpr size_t H_END     = H_B       + (size_t)NV*256;
static constexpr size_t WS_TOTAL  = O_H16 + (H_END + 1)/2 + 64;

static constexpr size_t OW_vq0 = 0;
static constexpr size_t OW_vq1 = 17408;
static constexpr size_t OW_cq0 = 33792;
static constexpr size_t OW_cq1 = 51200;
static constexpr size_t OW_cm0 = 67584;
static constexpr size_t OW_cm1 = 165888;
static constexpr size_t OW_ug0 = 231424;
static constexpr size_t OW_ug1 = 362496;
static constexpr size_t OW_ug2 = 428032;
static constexpr size_t OW_co0 = 460800;
static constexpr int    OW_END = 477184;

__device__ float g_ws[WS_TOTAL];
__device__ int   g_deg[NL];
__device__ int   g_csr[(size_t)NL * CSR_W];

// ---------------- PTX helpers ----------------
__device__ __forceinline__ uint32_t smem_u32(const void* p){
    uint32_t a;
    asm("{ .reg .u64 t; cvta.to.shared.u64 t, %1; cvt.u32.u64 %0, t; }" : "=r"(a) : "l"(p));
    return a;
}
__device__ __forceinline__ void ldsm4(uint32_t* r, uint32_t addr){
    asm volatile("ldmatrix.sync.aligned.m8n8.x4.shared.b16 {%0,%1,%2,%3}, [%4];"
        : "=r"(r[0]), "=r"(r[1]), "=r"(r[2]), "=r"(r[3]) : "r"(addr));
}
__device__ __forceinline__ void mma_f16(float* c, const uint32_t* a, const uint32_t* b){
    asm volatile("mma.sync.aligned.m16n8k16.row.col.f32.f16.f16.f32 "
        "{%0,%1,%2,%3}, {%4,%5,%6,%7}, {%8,%9}, {%0,%1,%2,%3};"
        : "+f"(c[0]), "+f"(c[1]), "+f"(c[2]), "+f"(c[3])
        : "r"(a[0]), "r"(a[1]), "r"(a[2]), "r"(a[3]), "r"(b[0]), "r"(b[1]));
}
__device__ __forceinline__ void cp16(uint32_t dst, const void* src, bool pred){
    int sz = pred ? 16 : 0;
    asm volatile("cp.async.cg.shared.global [%0], [%1], 16, %2;"
                 :: "r"(dst), "l"(src), "r"(sz));
}
#define CP_COMMIT() asm volatile("cp.async.commit_group;" ::: "memory")
#define CP_WAIT2()  asm volatile("cp.async.wait_group 2;" ::: "memory")
#define CP_WAIT1()  asm volatile("cp.async.wait_group 1;" ::: "memory")

__device__ __forceinline__ float sigm(float x){ return 1.f/(1.f+expf(-x)); }
__device__ __forceinline__ float softplusf(float x){ return fmaxf(x,0.f)+log1pf(expf(-fabsf(x))); }
__device__ __forceinline__ float fsigm(float x){ return __fdividef(1.f, 1.f+__expf(-x)); }
__device__ __forceinline__ float fsoftplus(float x){ return fmaxf(x,0.f)+__logf(1.f+__expf(-fabsf(x))); }

__device__ __forceinline__ uint2 pack_h4(float a, float b, float c, float d){
    __half2 h0 = __floats2half2_rn(a, b);
    __half2 h1 = __floats2half2_rn(c, d);
    uint2 r;
    r.x = *reinterpret_cast<uint32_t*>(&h0);
    r.y = *reinterpret_cast<uint32_t*>(&h1);
    return r;
}

// ---------------- unified fp16 A16 GEMM: tile 128x64, 256 thr, 2 CTAs/SM ----------------
// 4-buffer depth-3 cp.async pipeline for both A and B; one barrier per chunk.
static constexpr int G64_SMEM = 61440;   // A 4x10240 + B 4x5120

template<int STATS, int CH, int SPE>
__global__ void __launch_bounds__(256, 2)
k_mma64(const __half* __restrict__ A16, const __half* __restrict__ Bg,
        const float* __restrict__ bias, void* __restrict__ Cv,
        int KP, int Ntot, int relu, float* __restrict__ statp,
        float* __restrict__ spbuf)
{
    extern __shared__ __align__(16) char smem[];
    const uint32_t sbase = smem_u32(smem);
    const int t = threadIdx.x;
    const int lane = t & 31, wid = t >> 5;
    const int warp_m = wid & 3, warp_n = wid >> 2;
    const int bm = blockIdx.y * 128, bn = blockIdx.x * 64;

    constexpr int LDH = 40, APLANE = 10240, BPLANE = 5120;
    constexpr int A0 = 0, B0 = 40960;

    float acc[2][4][4];
    #pragma unroll
    for (int i=0;i<2;i++)
        #pragma unroll
        for(int j=0;j<4;j++)
            #pragma unroll
            for(int q=0;q<4;q++) acc[i][j][q]=0.f;

    const int nch = (KP + 31) >> 5;

    auto cpAB = [&](int c){
        const int k0 = c << 5;
        const uint32_t ab = sbase + A0 + (uint32_t)(c & 3)*APLANE;
        #pragma unroll
        for (int i = 0; i < 2; i++) {
            int idx = t + i*256;
            int row = idx >> 2, q = idx & 3;
            int gk = k0 + q*8;
            bool ok = (gk + 8 <= KP);
            size_t off = ok ? ((size_t)(bm+row)*KP + gk) : 0;
            cp16(ab + (uint32_t)(row*LDH + q*8)*2, A16 + off, ok);
        }
        const uint32_t bb = sbase + B0 + (uint32_t)(c & 3)*BPLANE;
        {
            int row = t >> 2, q = t & 3;
            int gk = k0 + q*8;
            bool ok = (gk + 8 <= KP);
            size_t off = ok ? ((size_t)(bn+row)*KP + gk) : 0;
            cp16(bb + (uint32_t)(row*LDH + q*8)*2, Bg + off, ok);
        }
    };
    auto compute = [&](int c){
        const uint32_t sa = sbase + A0 + (uint32_t)(c & 3)*APLANE;
        const uint32_t sb = sbase + B0 + (uint32_t)(c & 3)*BPLANE;
        const int grp = lane >> 3, r = lane & 7;
        #pragma unroll
        for (int ks = 0; ks < 32; ks += 16) {
            uint32_t aH[2][4], bX[4][2];
            #pragma unroll
            for (int mt = 0; mt < 2; mt++) {
                int arow = warp_m*32 + mt*16 + (grp & 1)*8 + r;
                int acol = ks + (grp >> 1)*8;
                ldsm4(aH[mt], sa + (uint32_t)(arow*LDH + acol)*2);
            }
            #pragma unroll
            for (int p = 0; p < 2; p++) {
                int brow = warp_n*32 + p*16 + (grp >> 1)*8 + r;
                int bcol = ks + (grp & 1)*8;
                uint32_t tmp[4];
                ldsm4(tmp, sb + (uint32_t)(brow*LDH + bcol)*2);
                bX[2*p][0]=tmp[0]; bX[2*p][1]=tmp[1]; bX[2*p+1][0]=tmp[2]; bX[2*p+1][1]=tmp[3];
            }
            #pragma unroll
            for (int mt = 0; mt < 2; mt++)
                #pragma unroll
                for (int nt = 0; nt < 4; nt++)
                    mma_f16(acc[mt][nt], aH[mt], bX[nt]);
        }
    };

    // depth-3 prologue
    cpAB(0);
    CP_COMMIT();
    if (nch > 1) cpAB(1);
    CP_COMMIT();
    if (nch > 2) cpAB(2);
    CP_COMMIT();

    for (int c = 0; c < nch; c++) {
        CP_WAIT2();
        __syncthreads();
        compute(c);
        if (c+3 < nch) cpAB(c+3);
        CP_COMMIT();
    }

    // ---- C store (+SPE) ----
    #pragma unroll
    for (int mt = 0; mt < 2; mt++) {
        int row0 = bm + warp_m*32 + mt*16 + (lane >> 2);
        #pragma unroll
        for (int nt = 0; nt < 4; nt++) {
            int col = bn + warp_n*32 + nt*8 + (lane & 3)*2;
            float2 bv = *reinterpret_cast<const float2*>(&bias[col]);
            float v0 = acc[mt][nt][0] + bv.x, v1 = acc[mt][nt][1] + bv.y;
            float v2 = acc[mt][nt][2] + bv.x, v3 = acc[mt][nt][3] + bv.y;
            if (relu) { v0=fmaxf(v0,0.f); v1=fmaxf(v1,0.f); v2=fmaxf(v2,0.f); v3=fmaxf(v3,0.f); }
            if (CH) {
                __half* C16 = reinterpret_cast<__half*>(Cv);
                __half2 h01 = __floats2half2_rn(v0, v1);
                __half2 h23 = __floats2half2_rn(v2, v3);
                *reinterpret_cast<__half2*>(&C16[(size_t)row0*Ntot + col])     = h01;
                *reinterpret_cast<__half2*>(&C16[(size_t)(row0+8)*Ntot + col]) = h23;
            } else {
                float* C = reinterpret_cast<float*>(Cv);
                *reinterpret_cast<float2*>(&C[(size_t)row0*Ntot + col])     = make_float2(v0,v1);
                *reinterpret_cast<float2*>(&C[(size_t)(row0+8)*Ntot + col]) = make_float2(v2,v3);
            }
            if (SPE) {
                *reinterpret_cast<float2*>(&spbuf[(size_t)row0*128 + col]) =
                    make_float2(fsoftplus(v0), fsoftplus(v1));
                *reinterpret_cast<float2*>(&spbuf[(size_t)(row0+NV)*128 + col]) =
                    make_float2(fsoftplus(-v0), fsoftplus(-v1));
                *reinterpret_cast<float2*>(&spbuf[(size_t)(row0+8)*128 + col]) =
                    make_float2(fsoftplus(v2), fsoftplus(v3));
                *reinterpret_cast<float2*>(&spbuf[(size_t)(row0+8+NV)*128 + col]) =
                    make_float2(fsoftplus(-v2), fsoftplus(-v3));
            }
        }
    }

    if (STATS) {
        bool active = (STATS == 2) || (bn >= 128);
        if (active) {
            __syncthreads();
            float* red = reinterpret_cast<float*>(smem);
            if (t < 128) red[t] = 0.f;
            __syncthreads();
            #pragma unroll
            for (int nt = 0; nt < 4; nt++) {
                int c0 = warp_n*32 + nt*8 + (lane & 3)*2;
                float b0 = __ldg(&bias[bn + c0]), b1 = __ldg(&bias[bn + c0 + 1]);
                float s0=0.f, s1=0.f, q0=0.f, q1=0.f;
                #pragma unroll
                for (int mt = 0; mt < 2; mt++) {
                    float v0 = acc[mt][nt][0] + b0, v1 = acc[mt][nt][1] + b1;
                    float v2 = acc[mt][nt][2] + b0, v3 = acc[mt][nt][3] + b1;
                    s0 += v0 + v2; s1 += v1 + v3;
                    q0 += v0*v0 + v2*v2; q1 += v1*v1 + v3*v3;
                }
                #pragma unroll
                for (int o = 4; o < 32; o <<= 1) {
                    s0 += __shfl_xor_sync(0xffffffffu, s0, o);
                    s1 += __shfl_xor_sync(0xffffffffu, s1, o);
                    q0 += __shfl_xor_sync(0xffffffffu, q0, o);
                    q1 += __shfl_xor_sync(0xffffffffu, q1, o);
                }
                if (lane < 4) {
                    atomicAdd(&red[c0],      s0);
                    atomicAdd(&red[c0+1],    s1);
                    atomicAdd(&red[64+c0],   q0);
                    atomicAdd(&red[64+c0+1], q1);
                }
            }
            __syncthreads();
            int cb = (STATS == 1) ? (bn - 128) : bn;
            if (t < 64) {
                atomicAdd(&statp[cb + t],       red[t]);
                atomicAdd(&statp[128 + cb + t], red[64 + t]);
            }
        }
    }
}

// ---------------- co0: pn-apply loader (+fp16 state writes) + logits ----------------
static constexpr int CO_SMEM = 51200;

__global__ void __launch_bounds__(512, 1)
k_co0(const float* __restrict__ cdata, float* __restrict__ cls,
      const float* __restrict__ statc,
      const __half* __restrict__ Bg, const float* __restrict__ bias,
      float* __restrict__ out, int round,
      const float* __restrict__ w1, const float* __restrict__ b1,
      __half* __restrict__ clscat, __half* __restrict__ cmin16)
{
    extern __shared__ __align__(16) char smem[];
    const uint32_t sbase = smem_u32(smem);
    const int t = threadIdx.x;
    const int lane = t & 31, wid = t >> 5;
    const int warp_m = wid & 3, warp_n = wid >> 2;
    const int bm = blockIdx.y * 128;

    constexpr int LDH = 40, PLANE = 10240, A0 = 0, B0 = 20480;
    constexpr int K = 128, nch = 4;

    float acc[2][4][4];
    #pragma unroll
    for (int i=0;i<2;i++)
        #pragma unroll
        for(int j=0;j<4;j++)
            #pragma unroll
            for(int q=0;q<4;q++) acc[i][j][q]=0.f;

    float4 aReg[2];
    const float scale = statc[384];

    auto loadA = [&](int c){
        const int k0 = c << 5;
        #pragma unroll
        for (int i = 0; i < 2; i++) {
            int idx = t + i*512;
            int row = idx >> 3, col4 = (idx & 7) << 2;
            int gk = k0 + col4;
            int r = bm + row;
            float4 v = *reinterpret_cast<const float4*>(&cdata[(size_t)r*256 + 128 + gk]);
            float4 m = *reinterpret_cast<const float4*>(&statc[256 + gk]);
            float4 o = *reinterpret_cast<const float4*>(&cls[(size_t)r*128 + gk]);
            v.x = (v.x - m.x)*scale*0.25f + 0.1f*o.x;
            v.y = (v.y - m.y)*scale*0.25f + 0.1f*o.y;
            v.z = (v.z - m.z)*scale*0.25f + 0.1f*o.z;
            v.w = (v.w - m.w)*scale*0.25f + 0.1f*o.w;
            *reinterpret_cast<float4*>(&cls[(size_t)r*128 + gk]) = v;
            uint2 h4 = pack_h4(v.x, v.y, v.z, v.w);
            *reinterpret_cast<uint2*>(&clscat[(size_t)r*136 + gk]) = h4;
            *reinterpret_cast<uint2*>(&cmin16[(size_t)r*384 + gk]) = h4;
            aReg[i] = v;
        }
    };
    auto cpB = [&](int c){
        const int k0 = c << 5;
        const uint32_t bb = sbase + B0 + (uint32_t)(c % 3)*PLANE;
        int row = t >> 2, q = t & 3;
        int gk = k0 + q*8;
        cp16(bb + (uint32_t)(row*LDH + q*8)*2, Bg + (size_t)row*K + gk, true);
    };
    auto storeA = [&](int s){
        char* sc = smem + A0 + s*PLANE;
        #pragma unroll
        for (int i = 0; i < 2; i++) {
            int idx = t + i*512;
            int row = idx >> 3, col4 = (idx & 7) << 2;
            uint2 pk = pack_h4(aReg[i].x, aReg[i].y, aReg[i].z, aReg[i].w);
            *reinterpret_cast<uint2*>(sc + (row*LDH + col4)*2) = pk;
        }
    };
    auto compute = [&](int c){
        const uint32_t sa = sbase + A0 + (uint32_t)(c & 1)*PLANE;
        const uint32_t sb = sbase + B0 + (uint32_t)(c % 3)*PLANE;
        const int grp = lane >> 3, r = lane & 7;
        #pragma unroll
        for (int ks = 0; ks < 32; ks += 16) {
            uint32_t aH[2][4], bX[4][2];
            #pragma unroll
            for (int mt = 0; mt < 2; mt++) {
                int arow = warp_m*32 + mt*16 + (grp & 1)*8 + r;
                int acol = ks + (grp >> 1)*8;
                ldsm4(aH[mt], sa + (uint32_t)(arow*LDH + acol)*2);
            }
            #pragma unroll
            for (int p = 0; p < 2; p++) {
                int brow = warp_n*32 + p*16 + (grp >> 1)*8 + r;
                int bcol = ks + (grp & 1)*8;
                uint32_t tmp[4];
                ldsm4(tmp, sb + (uint32_t)(brow*LDH + bcol)*2);
                bX[2*p][0]=tmp[0]; bX[2*p][1]=tmp[1]; bX[2*p+1][0]=tmp[2]; bX[2*p+1][1]=tmp[3];
            }
            #pragma unroll
            for (int mt = 0; mt < 2; mt++)
                #pragma unroll
                for (int nt = 0; nt < 4; nt++)
                    mma_f16(acc[mt][nt], aH[mt], bX[nt]);
        }
    };

    loadA(0);
    cpB(0);
    CP_COMMIT();
    storeA(0);
    loadA(1); cpB(1);
    CP_COMMIT();
    CP_WAIT1();
    __syncthreads();

    for (int c = 0; c < nch; c++) {
        compute(c);
        if (c+1 < nch) storeA((c+1) & 1);
        if (c+2 < nch) cpB(c+2);
        CP_COMMIT();
        if (c+2 < nch) loadA(c+2);
        CP_WAIT1();
        __syncthreads();
    }

    float* red = reinterpret_cast<float*>(smem);
    if (t < 128) red[t] = 0.f;
    __syncthreads();
    #pragma unroll
    for (int mt = 0; mt < 2; mt++) {
        int rl = warp_m*32 + mt*16 + (lane >> 2);
        float p0 = 0.f, p1 = 0.f;
        #pragma unroll
        for (int nt = 0; nt < 4; nt++) {
            int col = warp_n*32 + nt*8 + (lane & 3)*2;
            float2 bv = *reinterpret_cast<const float2*>(&bias[col]);
            float wa = __ldg(&w1[col]), wb = __ldg(&w1[col+1]);
            float v0 = fmaxf(acc[mt][nt][0] + bv.x, 0.f);
            float v1 = fmaxf(acc[mt][nt][1] + bv.y, 0.f);
            float v2 = fmaxf(acc[mt][nt][2] + bv.x, 0.f);
            float v3 = fmaxf(acc[mt][nt][3] + bv.y, 0.f);
            p0 += v0*wa + v1*wb;
            p1 += v2*wa + v3*wb;
        }
        atomicAdd(&red[rl], p0);
        atomicAdd(&red[rl+8], p1);
    }
    __syncthreads();
    if (t < 128) {
        float x = red[t] + __ldg(&b1[0]);
        int row = bm + t;
        out[(size_t)round*NC + row] = sigm(x);
        out[(size_t)4*NC + (size_t)round*NC + row] = softplusf(x);
    }
}

// ---------------- setup kernels ----------------
__global__ void k_init(float* p, __half* clscat, __half* varscat, __half* cmin16){
    size_t i = (size_t)blockIdx.x*blockDim.x + threadIdx.x;
    size_t n = (size_t)(NV+NC)*128;
    if (i < n) {
        p[i] = 1.f;
        __half one = __float2half(1.f);
        if (i < (size_t)NV*128) {
            varscat[(i>>7)*136 + (i&127)] = one;
        } else {
            size_t j = i - (size_t)NV*128;
            size_t row = j >> 7, col = j & 127;
            clscat[row*136 + col] = one;
            cmin16[row*384 + col] = one;
        }
    }
    if (i < NL) g_deg[i] = 0;
    if (i < 256) { g_ws[O_STATC + i] = 0.f; g_ws[O_STATV + i] = 0.f; }
}
__global__ void k_count_csr(const int* __restrict__ lit, const int* __restrict__ cls){
    int e = blockIdx.x*blockDim.x + threadIdx.x;
    if (e >= NE) return;
    int l = lit[e];
    int pos = atomicAdd(&g_deg[l], 1);
    if (pos < CSR_W) g_csr[(size_t)l*CSR_W + pos] = cls[e];
}
struct WSrc { const float* w[10]; };
__global__ void k_weights_wsplit(WSrc ws, __half* __restrict__ w16){
    const int offs[11] = {0, 17408, 33792, 51200, 67584, 165888, 231424,
                          362496, 428032, 460800, 477184};
    const int Ks[10]  = {132,128,132,128,384,256,512,256,256,128};
    const int KPs[10] = {136,128,136,128,384,256,512,256,256,128};
    const int Ns[10]  = {128,128,128,128,256,256,256,256,128,128};
    int idx = blockIdx.x*blockDim.x + threadIdx.x;
    if (idx < NL) g_ws[O_DEGW + idx] = rsqrtf(fmaxf((float)g_deg[idx], 1.f));
    if (idx < NV) g_ws[O_VDEGW + idx] = 4.f*rsqrtf(fmaxf((float)(g_deg[idx] + g_deg[idx+NV]), 1.f));
    if (idx >= offs[10]) return;
    int seg = 0;
    #pragma unroll
    for (int s = 1; s < 10; s++) if (idx >= offs[s]) seg = s;
    int local = idx - offs[seg];
    int K = Ks[seg], KP = KPs[seg], N = Ns[seg];
    int n = local / KP, k = local % KP;
    float v = (k < K) ? ws.w[seg][(size_t)k*N + n] : 0.f;
    w16[idx] = __float2half_rn(v);
}

// ---------------- per-round small kernels ----------------
// write noise cols (128..135: 4 noise + 4 zeros) into cat buffers
__global__ void k_noise16(const float* __restrict__ nv, const float* __restrict__ nc,
                          __half* __restrict__ clscat, __half* __restrict__ varscat){
    int r = blockIdx.x*blockDim.x + threadIdx.x;
    if (r < NC) {
        float4 z = *reinterpret_cast<const float4*>(&nc[(size_t)r*4]);
        uint2 h = pack_h4(z.x, z.y, z.z, z.w);
        uint4 w = make_uint4(h.x, h.y, 0u, 0u);
        *reinterpret_cast<uint4*>(&clscat[(size_t)r*136 + 128]) = w;
    }
    if (r < NV) {
        float4 z = *reinterpret_cast<const float4*>(&nv[(size_t)r*4]);
        uint2 h = pack_h4(z.x, z.y, z.z, z.w);
        uint4 w = make_uint4(h.x, h.y, 0u, 0u);
        *reinterpret_cast<uint4*>(&varscat[(size_t)r*136 + 128]) = w;
    }
}
// csum (sorted gather) + loss fp32 + cmin16 loss/cgrad halves
__global__ void k_csum_loss(const int* __restrict__ lit, const int* __restrict__ cls,
                            const float* __restrict__ sp, __half* __restrict__ cmin16){
    const int warp = threadIdx.x >> 5, lane = threadIdx.x & 31;
    const int c = blockIdx.x*4 + warp;
    int s01 = 0;
    if (lane < 2) {
        int key = c + lane;
        int lo = 0, hi = NE;
        while (lo < hi) { int mid = (lo+hi) >> 1; if (cls[mid] < key) lo = mid+1; else hi = mid; }
        s01 = lo;
    }
    int s0 = __shfl_sync(0xffffffffu, s01, 0);
    int s1 = __shfl_sync(0xffffffffu, s01, 1);
    int f4 = lane << 2;
    float4 csum = make_float4(0.f,0.f,0.f,0.f);
    for (int e = s0; e < s1; e++) {
        int l = __ldg(&lit[e]);
        float4 v = *reinterpret_cast<const float4*>(&sp[(size_t)l*128 + f4]);
        csum.x += v.x; csum.y += v.y; csum.z += v.z; csum.w += v.w;
    }
    size_t i = (size_t)c*128 + f4;
    float4 cq = *reinterpret_cast<const float4*>(&g_ws[O_CQ + i]);
    float4 lo4, cg4;
    float sg;
    sg = fsigm(cq.x); lo4.x = __expf(-csum.x)*sg; cg4.x = lo4.x*(1.f-sg)*INV_M;
    sg = fsigm(cq.y); lo4.y = __expf(-csum.y)*sg; cg4.y = lo4.y*(1.f-sg)*INV_M;
    sg = fsigm(cq.z); lo4.z = __expf(-csum.z)*sg; cg4.z = lo4.z*(1.f-sg)*INV_M;
    sg = fsigm(cq.w); lo4.w = __expf(-csum.w)*sg; cg4.w = lo4.w*(1.f-sg)*INV_M;
    *reinterpret_cast<float4*>(&g_ws[O_LOSS + i]) = lo4;
    size_t b = (size_t)c*384;
    *reinterpret_cast<uint2*>(&cmin16[b + 128 + f4]) =
        pack_h4(4.f*lo4.x, 4.f*lo4.y, 4.f*lo4.z, 4.f*lo4.w);
    *reinterpret_cast<uint2*>(&cmin16[b + 256 + f4]) =
        pack_h4(cg4.x, cg4.y, cg4.z, cg4.w);
}
// fused: dlits+vl gathers + unit build -> unit16 fp16 (warp per variable)
__global__ void k_unit_build(const float* __restrict__ loss, const float* __restrict__ cdata,
                             const float* __restrict__ vq, const float* __restrict__ vars,
                             __half* __restrict__ unit16){
    const int warp = threadIdx.x >> 5, lane = threadIdx.x & 31;
    const int v = blockIdx.x*4 + warp;
    const int f4 = lane << 2;
    int dp = g_deg[v];       if (dp > CSR_W) dp = CSR_W;
    int dn = g_deg[v + NV];  if (dn > CSR_W) dn = CSR_W;
    float4 dlp = make_float4(0,0,0,0), vlp = dlp, dln = dlp, vln = dlp;
    for (int j = 0; j < dp; j++) {
        int c = g_csr[(size_t)v*CSR_W + j];
        float4 a = *reinterpret_cast<const float4*>(&loss[(size_t)c*128 + f4]);
        float4 b = *reinterpret_cast<const float4*>(&cdata[(size_t)c*256 + f4]);
        dlp.x+=a.x; dlp.y+=a.y; dlp.z+=a.z; dlp.w+=a.w;
        vlp.x+=b.x; vlp.y+=b.y; vlp.z+=b.z; vlp.w+=b.w;
    }
    for (int j = 0; j < dn; j++) {
        int c = g_csr[(size_t)(v+NV)*CSR_W + j];
        float4 a = *reinterpret_cast<const float4*>(&loss[(size_t)c*128 + f4]);
        float4 b = *reinterpret_cast<const float4*>(&cdata[(size_t)c*256 + f4]);
        dln.x+=a.x; dln.y+=a.y; dln.z+=a.z; dln.w+=a.w;
        vln.x+=b.x; vln.y+=b.y; vln.z+=b.z; vln.w+=b.w;
    }
    float4 q  = *reinterpret_cast<const float4*>(&vq[(size_t)v*128 + f4]);
    float4 va = *reinterpret_cast<const float4*>(&vars[(size_t)v*128 + f4]);
    float wv = g_ws[O_VDEGW + v];
    float wp = g_ws[O_DEGW + v];
    float wn = g_ws[O_DEGW + NV + v];
    float sp;
    float4 g;
    sp = fsigm(q.x); g.x = -INV_M*(dlp.x*sp - dln.x*(1.f-sp))*wv;
    sp = fsigm(q.y); g.y = -INV_M*(dlp.y*sp - dln.y*(1.f-sp))*wv;
    sp = fsigm(q.z); g.z = -INV_M*(dlp.z*sp - dln.z*(1.f-sp))*wv;
    sp = fsigm(q.w); g.w = -INV_M*(dlp.w*sp - dln.w*(1.f-sp))*wv;
    size_t b = (size_t)v*512;
    *reinterpret_cast<uint2*>(&unit16[b + f4])        = pack_h4(g.x, g.y, g.z, g.w);
    *reinterpret_cast<uint2*>(&unit16[b + 128 + f4])  = pack_h4(va.x, va.y, va.z, va.w);
    *reinterpret_cast<uint2*>(&unit16[b + 256 + f4])  = pack_h4(vlp.x*wp, vlp.y*wp, vlp.z*wp, vlp.w*wp);
    *reinterpret_cast<uint2*>(&unit16[b + 384 + f4])  = pack_h4(vln.x*wn, vln.y*wn, vln.z*wn, vln.w*wn);
}
__global__ void k_pn_scale(float n, float* stat){
    int f = threadIdx.x;
    float mean = stat[f] / n;
    float var  = stat[128 + f] / n - mean*mean;
    __shared__ float sh[128];
    sh[f] = var; __syncthreads();
    for (int s = 64; s > 0; s >>= 1) { if (f < s) sh[f] += sh[f+s]; __syncthreads(); }
    stat[256 + f] = mean;
    if (f == 0) stat[384] = rsqrtf(sh[0]*(1.f/128.f) + 1e-6f);
    stat[f] = 0.f;
    stat[128 + f] = 0.f;
}
__global__ void k_pn_apply(const float* __restrict__ x, const float* __restrict__ stat,
                           float* __restrict__ dst, __half* __restrict__ varscat){
    int r = blockIdx.x, f = threadIdx.x;
    float v = (x[(size_t)r*128 + f] - stat[256 + f]) * stat[384];
    size_t i = (size_t)r*128 + f;
    float o = v*0.25f + 0.1f*dst[i];
    dst[i] = o;
    varscat[(size_t)r*136 + f] = __float2half_rn(o);
}

// ---------------- host ----------------
template<int STATS, int CH, int SPE>
static void mmgemm(const __half* A16, const __half* Bg, const float* bias, void* C,
                   int M, int KP, int Ntot, int relu,
                   float* statp = nullptr, float* spbuf = nullptr){
    cudaFuncSetAttribute(k_mma64<STATS,CH,SPE>,
                         cudaFuncAttributeMaxDynamicSharedMemorySize, G64_SMEM);
    dim3 grid(Ntot/64, M/128);
    k_mma64<STATS,CH,SPE><<<grid, 256, G64_SMEM>>>(A16, Bg, bias, C, KP, Ntot, relu,
                                                   statp, spbuf);
}

extern "C" void kernel_launch(void* const* d_in, const int* in_sizes, int n_in,
                              void* d_out, int out_size)
{
    (void)in_sizes; (void)n_in; (void)out_size;
    const int*   edge_lit    = (const int*)d_in[0];
    const int*   edge_clause = (const int*)d_in[1];
    const float* noise_v = (const float*)d_in[2];
    const float* noise_c = (const float*)d_in[3];
    const float* vq_w0 = (const float*)d_in[4];  const float* vq_b0 = (const float*)d_in[5];
    const float* vq_w1 = (const float*)d_in[6];  const float* vq_b1 = (const float*)d_in[7];
    const float* cq_w0 = (const float*)d_in[8];  const float* cq_b0 = (const float*)d_in[9];
    const float* cq_w1 = (const float*)d_in[10]; const float* cq_b1 = (const float*)d_in[11];
    const float* cm_w0 = (const float*)d_in[12]; const float* cm_b0 = (const float*)d_in[13];
    const float* cm_w1 = (const float*)d_in[14]; const float* cm_b1 = (const float*)d_in[15];
    const float* ug_w0 = (const float*)d_in[16]; const float* ug_b0 = (const float*)d_in[17];
    const float* ug_w1 = (const float*)d_in[18]; const float* ug_b1 = (const float*)d_in[19];
    const float* ug_w2 = (const float*)d_in[20]; const float* ug_b2 = (const float*)d_in[21];
    const float* co_w0 = (const float*)d_in[22]; const float* co_b0 = (const float*)d_in[23];
    const float* co_w1 = (const float*)d_in[24]; const float* co_b1 = (const float*)d_in[25];
    float* out = (float*)d_out;

    float* ws; cudaGetSymbolAddress((void**)&ws, g_ws);
    __half* w16   = reinterpret_cast<__half*>(ws + O_WT);
    __half* h16   = reinterpret_cast<__half*>(ws + O_H16);
    __half* clscat  = h16 + H_CLSCAT;
    __half* varscat = h16 + H_VARSCAT;
    __half* cmin16  = h16 + H_CMIN;
    __half* unit16  = h16 + H_UNIT;
    __half* h16a    = h16 + H_A;
    __half* h16b    = h16 + H_B;
    float* statc = ws + O_STATC;
    float* statv = ws + O_STATV;
    float* sp    = ws + O_SP;

    cudaFuncSetAttribute(k_co0, cudaFuncAttributeMaxDynamicSharedMemorySize, CO_SMEM);

    {
        size_t n = (size_t)(NV+NC)*128;
        k_init<<<(unsigned)((n+255)/256), 256>>>(ws + O_VARS, clscat, varscat, cmin16);
    }
    k_count_csr<<<(NE+255)/256, 256>>>(edge_lit, edge_clause);
    {
        WSrc s;
        s.w[0]=vq_w0; s.w[1]=vq_w1; s.w[2]=cq_w0; s.w[3]=cq_w1; s.w[4]=cm_w0;
        s.w[5]=cm_w1; s.w[6]=ug_w0; s.w[7]=ug_w1; s.w[8]=ug_w2; s.w[9]=co_w0;
        k_weights_wsplit<<<(OW_END+255)/256, 256>>>(s, w16);
    }

    for (int r = 0; r < 4; r++) {
        const float* nv_r = noise_v + (size_t)r*NV*4;
        const float* nc_r = noise_c + (size_t)r*NC*4;

        k_noise16<<<(NC+255)/256, 256>>>(nv_r, nc_r, clscat, varscat);

        mmgemm<0,1,0>(clscat,  w16+OW_cq0, cq_b0, h16a,     NC, 136, 128, 1);
        mmgemm<0,0,0>(h16a,    w16+OW_cq1, cq_b1, ws+O_CQ,  NC, 128, 128, 0);
        mmgemm<0,1,0>(varscat, w16+OW_vq0, vq_b0, h16a,     NV, 136, 128, 1);
        mmgemm<0,0,1>(h16a,    w16+OW_vq1, vq_b1, ws+O_VQ,  NV, 128, 128, 0, nullptr, sp);

        k_csum_loss<<<NC/4, 128>>>(edge_lit, edge_clause, sp, cmin16);

        mmgemm<0,1,0>(cmin16, w16+OW_cm0, cm_b0, h16a,       NC, 384, 256, 1);
        mmgemm<1,0,0>(h16a,   w16+OW_cm1, cm_b1, ws+O_CDATA, NC, 256, 256, 0, statc);

        k_unit_build<<<NV/4, 128>>>(ws+O_LOSS, ws+O_CDATA, ws+O_VQ, ws+O_VARS, unit16);
        k_pn_scale<<<1, 128>>>((float)NC, statc);

        mmgemm<0,1,0>(unit16, w16+OW_ug0, ug_b0, h16a,      NV, 512, 256, 1);
        mmgemm<0,1,0>(h16a,   w16+OW_ug1, ug_b1, h16b,      NV, 256, 256, 1);
        mmgemm<2,0,0>(h16b,   w16+OW_ug2, ug_b2, ws+O_VOUT, NV, 256, 128, 0, statv);

        k_pn_scale<<<1, 128>>>((float)NV, statv);
        k_pn_apply<<<NV, 128>>>(ws+O_VOUT, statv, ws+O_VARS, varscat);

        k_co0<<<dim3(1, NC/128), 512, CO_SMEM>>>(ws+O_CDATA, ws+O_CLS, statc,
                                                 w16+OW_co0, co_b0, out, r, co_w1, co_b1,
                                                 clscat, cmin16);
    }
}

// round 14
// speedup vs baseline: 3.0096x; 1.0211x over previous
#include <cuda_runtime.h>
#include <cuda_fp16.h>
#include <math.h>
#include <stdint.h>

#define NV 24576
#define NC 98304
#define NE 294912
#define NL 49152
#define INV_M (1.0f/12582912.0f)
#define CSR_W 40

// ---------------- workspace layout (floats) ----------------
static constexpr size_t O_VARS   = 0;
static constexpr size_t O_CLS    = O_VARS  + (size_t)NV*128;
static constexpr size_t O_CQ     = O_CLS   + (size_t)NC*128;   // NC x 128, VQ follows
static constexpr size_t O_VQ     = O_CQ    + (size_t)NC*128;   // NV x 128 (contiguous!)
static constexpr size_t O_LOSS   = O_VQ    + (size_t)NV*128;
static constexpr size_t O_CDATA  = O_LOSS  + (size_t)NC*128;   // NC x 256
static constexpr size_t O_VOUT   = O_CDATA + (size_t)NC*256;   // NV x 128
static constexpr size_t O_SP     = O_VOUT  + (size_t)NV*128;   // NL x 128
static constexpr size_t O_DEGW   = O_SP    + (size_t)NL*128;   // NL
static constexpr size_t O_VDEGW  = O_DEGW  + NL;               // NV
static constexpr size_t O_STATC  = O_VDEGW + NV;               // 512
static constexpr size_t O_STATV  = O_STATC + 512;              // 512
static constexpr size_t O_WT     = O_STATV + 512;              // fp16 weights
static constexpr size_t O_H16    = O_WT + 240000;              // fp16 area base

// half offsets within H16 area
static constexpr size_t H_CLSCAT  = 0;                              // NC x 136
static constexpr size_t H_VARSCAT = H_CLSCAT  + (size_t)NC*136;     // NV x 136 (contiguous!)
static constexpr size_t H_CMIN    = H_VARSCAT + (size_t)NV*136;     // NC x 384
static constexpr size_t H_UNIT    = H_CMIN    + (size_t)NC*384;     // NV x 512
static constexpr size_t H_A       = H_UNIT    + (size_t)NV*512;     // NC x 256 (also (NC+NV)x128)
static constexpr size_t H_B       = H_A       + (size_t)NC*256;     // NV x 256
static constexpr size_t H_END     = H_B       + (size_t)NV*256;
static constexpr size_t WS_TOTAL  = O_H16 + (H_END + 1)/2 + 64;

static constexpr size_t OW_vq0 = 0;
static constexpr size_t OW_vq1 = 17408;
static constexpr size_t OW_cq0 = 33792;
static constexpr size_t OW_cq1 = 51200;
static constexpr size_t OW_cm0 = 67584;
static constexpr size_t OW_cm1 = 165888;
static constexpr size_t OW_ug0 = 231424;
static constexpr size_t OW_ug1 = 362496;
static constexpr size_t OW_ug2 = 428032;
static constexpr size_t OW_co0 = 460800;
static constexpr int    OW_END = 477184;

__device__ float g_ws[WS_TOTAL];
__device__ int   g_deg[NL];
__device__ int   g_csr[(size_t)NL * CSR_W];

// ---------------- PTX helpers ----------------
__device__ __forceinline__ uint32_t smem_u32(const void* p){
    uint32_t a;
    asm("{ .reg .u64 t; cvta.to.shared.u64 t, %1; cvt.u32.u64 %0, t; }" : "=r"(a) : "l"(p));
    return a;
}
__device__ __forceinline__ void ldsm4(uint32_t* r, uint32_t addr){
    asm volatile("ldmatrix.sync.aligned.m8n8.x4.shared.b16 {%0,%1,%2,%3}, [%4];"
        : "=r"(r[0]), "=r"(r[1]), "=r"(r[2]), "=r"(r[3]) : "r"(addr));
}
__device__ __forceinline__ void mma_f16(float* c, const uint32_t* a, const uint32_t* b){
    asm volatile("mma.sync.aligned.m16n8k16.row.col.f32.f16.f16.f32 "
        "{%0,%1,%2,%3}, {%4,%5,%6,%7}, {%8,%9}, {%0,%1,%2,%3};"
        : "+f"(c[0]), "+f"(c[1]), "+f"(c[2]), "+f"(c[3])
        : "r"(a[0]), "r"(a[1]), "r"(a[2]), "r"(a[3]), "r"(b[0]), "r"(b[1]));
}
__device__ __forceinline__ void cp16(uint32_t dst, const void* src, bool pred){
    int sz = pred ? 16 : 0;
    asm volatile("cp.async.cg.shared.global [%0], [%1], 16, %2;"
                 :: "r"(dst), "l"(src), "r"(sz));
}
#define CP_COMMIT() asm volatile("cp.async.commit_group;" ::: "memory")
#define CP_WAIT2()  asm volatile("cp.async.wait_group 2;" ::: "memory")
#define CP_WAIT1()  asm volatile("cp.async.wait_group 1;" ::: "memory")

__device__ __forceinline__ float sigm(float x){ return 1.f/(1.f+expf(-x)); }
__device__ __forceinline__ float softplusf(float x){ return fmaxf(x,0.f)+log1pf(expf(-fabsf(x))); }
__device__ __forceinline__ float fsigm(float x){ return __fdividef(1.f, 1.f+__expf(-x)); }
__device__ __forceinline__ float fsoftplus(float x){ return fmaxf(x,0.f)+__logf(1.f+__expf(-fabsf(x))); }

__device__ __forceinline__ uint2 pack_h4(float a, float b, float c, float d){
    __half2 h0 = __floats2half2_rn(a, b);
    __half2 h1 = __floats2half2_rn(c, d);
    uint2 r;
    r.x = *reinterpret_cast<uint32_t*>(&h0);
    r.y = *reinterpret_cast<uint32_t*>(&h1);
    return r;
}

// ---------------- unified fp16 A16 GEMM, early-prefetch depth-3 pipeline ----------------
// tile 128x64, 256 thr, 2 CTAs/SM. Dual weight sets selected by bm >= rowSplit.
static constexpr int G64_SMEM = 61440;   // A 4x10240 + B 4x5120

template<int STATS, int CH, int SPE>
__global__ void __launch_bounds__(256, 2)
k_mma64(const __half* __restrict__ A16,
        const __half* __restrict__ Bg1, const __half* __restrict__ Bg2,
        const float* __restrict__ bias1, const float* __restrict__ bias2,
        void* __restrict__ Cv, int KP, int Ntot, int relu, int rowSplit,
        float* __restrict__ statp, float* __restrict__ spbuf)
{
    extern __shared__ __align__(16) char smem[];
    const uint32_t sbase = smem_u32(smem);
    const int t = threadIdx.x;
    const int lane = t & 31, wid = t >> 5;
    const int warp_m = wid & 3, warp_n = wid >> 2;
    const int bm = blockIdx.y * 128, bn = blockIdx.x * 64;
    const bool part2 = (bm >= rowSplit);
    const __half* Bg  = part2 ? Bg2 : Bg1;
    const float* bias = part2 ? bias2 : bias1;

    constexpr int LDH = 40, APLANE = 10240, BPLANE = 5120;
    constexpr int A0 = 0, B0 = 40960;

    float acc[2][4][4];
    #pragma unroll
    for (int i=0;i<2;i++)
        #pragma unroll
        for(int j=0;j<4;j++)
            #pragma unroll
            for(int q=0;q<4;q++) acc[i][j][q]=0.f;

    const int nch = (KP + 31) >> 5;

    auto cpAB = [&](int c){
        const int k0 = c << 5;
        const uint32_t ab = sbase + A0 + (uint32_t)(c & 3)*APLANE;
        #pragma unroll
        for (int i = 0; i < 2; i++) {
            int idx = t + i*256;
            int row = idx >> 2, q = idx & 3;
            int gk = k0 + q*8;
            bool ok = (gk + 8 <= KP);
            size_t off = ok ? ((size_t)(bm+row)*KP + gk) : 0;
            cp16(ab + (uint32_t)(row*LDH + q*8)*2, A16 + off, ok);
        }
        const uint32_t bb = sbase + B0 + (uint32_t)(c & 3)*BPLANE;
        {
            int row = t >> 2, q = t & 3;
            int gk = k0 + q*8;
            bool ok = (gk + 8 <= KP);
            size_t off = ok ? ((size_t)(bn+row)*KP + gk) : 0;
            cp16(bb + (uint32_t)(row*LDH + q*8)*2, Bg + off, ok);
        }
    };
    auto compute = [&](int c){
        const uint32_t sa = sbase + A0 + (uint32_t)(c & 3)*APLANE;
        const uint32_t sb = sbase + B0 + (uint32_t)(c & 3)*BPLANE;
        const int grp = lane >> 3, r = lane & 7;
        #pragma unroll
        for (int ks = 0; ks < 32; ks += 16) {
            uint32_t aH[2][4], bX[4][2];
            #pragma unroll
            for (int mt = 0; mt < 2; mt++) {
                int arow = warp_m*32 + mt*16 + (grp & 1)*8 + r;
                int acol = ks + (grp >> 1)*8;
                ldsm4(aH[mt], sa + (uint32_t)(arow*LDH + acol)*2);
            }
            #pragma unroll
            for (int p = 0; p < 2; p++) {
                int brow = warp_n*32 + p*16 + (grp >> 1)*8 + r;
                int bcol = ks + (grp & 1)*8;
                uint32_t tmp[4];
                ldsm4(tmp, sb + (uint32_t)(brow*LDH + bcol)*2);
                bX[2*p][0]=tmp[0]; bX[2*p][1]=tmp[1]; bX[2*p+1][0]=tmp[2]; bX[2*p+1][1]=tmp[3];
            }
            #pragma unroll
            for (int mt = 0; mt < 2; mt++)
                #pragma unroll
                for (int nt = 0; nt < 4; nt++)
                    mma_f16(acc[mt][nt], aH[mt], bX[nt]);
        }
    };

    // depth-3 prologue
    cpAB(0);
    CP_COMMIT();
    if (nch > 1) cpAB(1);
    CP_COMMIT();
    if (nch > 2) cpAB(2);
    CP_COMMIT();

    // early-prefetch mainloop: memory for c+3 is in flight during compute(c)
    for (int c = 0; c < nch; c++) {
        CP_WAIT2();
        __syncthreads();
        if (c+3 < nch) cpAB(c+3);
        CP_COMMIT();
        compute(c);
    }

    // ---- C store (+SPE) ----
    #pragma unroll
    for (int mt = 0; mt < 2; mt++) {
        int row0 = bm + warp_m*32 + mt*16 + (lane >> 2);
        #pragma unroll
        for (int nt = 0; nt < 4; nt++) {
            int col = bn + warp_n*32 + nt*8 + (lane & 3)*2;
            float2 bv = *reinterpret_cast<const float2*>(&bias[col]);
            float v0 = acc[mt][nt][0] + bv.x, v1 = acc[mt][nt][1] + bv.y;
            float v2 = acc[mt][nt][2] + bv.x, v3 = acc[mt][nt][3] + bv.y;
            if (relu) { v0=fmaxf(v0,0.f); v1=fmaxf(v1,0.f); v2=fmaxf(v2,0.f); v3=fmaxf(v3,0.f); }
            if (CH) {
                __half* C16 = reinterpret_cast<__half*>(Cv);
                __half2 h01 = __floats2half2_rn(v0, v1);
                __half2 h23 = __floats2half2_rn(v2, v3);
                *reinterpret_cast<__half2*>(&C16[(size_t)row0*Ntot + col])     = h01;
                *reinterpret_cast<__half2*>(&C16[(size_t)(row0+8)*Ntot + col]) = h23;
            } else {
                float* C = reinterpret_cast<float*>(Cv);
                *reinterpret_cast<float2*>(&C[(size_t)row0*Ntot + col])     = make_float2(v0,v1);
                *reinterpret_cast<float2*>(&C[(size_t)(row0+8)*Ntot + col]) = make_float2(v2,v3);
            }
            if (SPE) {
                if (part2) {
                    int rv = row0 - rowSplit;
                    *reinterpret_cast<float2*>(&spbuf[(size_t)rv*128 + col]) =
                        make_float2(fsoftplus(v0), fsoftplus(v1));
                    *reinterpret_cast<float2*>(&spbuf[(size_t)(rv+NV)*128 + col]) =
                        make_float2(fsoftplus(-v0), fsoftplus(-v1));
                    *reinterpret_cast<float2*>(&spbuf[(size_t)(rv+8)*128 + col]) =
                        make_float2(fsoftplus(v2), fsoftplus(v3));
                    *reinterpret_cast<float2*>(&spbuf[(size_t)(rv+8+NV)*128 + col]) =
                        make_float2(fsoftplus(-v2), fsoftplus(-v3));
                }
            }
        }
    }

    if (STATS) {
        bool active = (STATS == 2) || (bn >= 128);
        if (active) {
            __syncthreads();
            float* red = reinterpret_cast<float*>(smem);
            if (t < 128) red[t] = 0.f;
            __syncthreads();
            #pragma unroll
            for (int nt = 0; nt < 4; nt++) {
                int c0 = warp_n*32 + nt*8 + (lane & 3)*2;
                float b0 = __ldg(&bias[bn + c0]), b1 = __ldg(&bias[bn + c0 + 1]);
                float s0=0.f, s1=0.f, q0=0.f, q1=0.f;
                #pragma unroll
                for (int mt = 0; mt < 2; mt++) {
                    float v0 = acc[mt][nt][0] + b0, v1 = acc[mt][nt][1] + b1;
                    float v2 = acc[mt][nt][2] + b0, v3 = acc[mt][nt][3] + b1;
                    s0 += v0 + v2; s1 += v1 + v3;
                    q0 += v0*v0 + v2*v2; q1 += v1*v1 + v3*v3;
                }
                #pragma unroll
                for (int o = 4; o < 32; o <<= 1) {
                    s0 += __shfl_xor_sync(0xffffffffu, s0, o);
                    s1 += __shfl_xor_sync(0xffffffffu, s1, o);
                    q0 += __shfl_xor_sync(0xffffffffu, q0, o);
                    q1 += __shfl_xor_sync(0xffffffffu, q1, o);
                }
                if (lane < 4) {
                    atomicAdd(&red[c0],      s0);
                    atomicAdd(&red[c0+1],    s1);
                    atomicAdd(&red[64+c0],   q0);
                    atomicAdd(&red[64+c0+1], q1);
                }
            }
            __syncthreads();
            int cb = (STATS == 1) ? (bn - 128) : bn;
            if (t < 64) {
                atomicAdd(&statp[cb + t],       red[t]);
                atomicAdd(&statp[128 + cb + t], red[64 + t]);
            }
        }
    }
}

// ---------------- co0: pn-apply loader (+fp16 state writes) + logits ----------------
static constexpr int CO_SMEM = 51200;

__global__ void __launch_bounds__(512, 1)
k_co0(const float* __restrict__ cdata, float* __restrict__ cls,
      const float* __restrict__ statc,
      const __half* __restrict__ Bg, const float* __restrict__ bias,
      float* __restrict__ out, int round,
      const float* __restrict__ w1, const float* __restrict__ b1,
      __half* __restrict__ clscat, __half* __restrict__ cmin16)
{
    extern __shared__ __align__(16) char smem[];
    const uint32_t sbase = smem_u32(smem);
    const int t = threadIdx.x;
    const int lane = t & 31, wid = t >> 5;
    const int warp_m = wid & 3, warp_n = wid >> 2;
    const int bm = blockIdx.y * 128;

    constexpr int LDH = 40, PLANE = 10240, A0 = 0, B0 = 20480;
    constexpr int K = 128, nch = 4;

    float acc[2][4][4];
    #pragma unroll
    for (int i=0;i<2;i++)
        #pragma unroll
        for(int j=0;j<4;j++)
            #pragma unroll
            for(int q=0;q<4;q++) acc[i][j][q]=0.f;

    float4 aReg[2];
    const float scale = statc[384];

    auto loadA = [&](int c){
        const int k0 = c << 5;
        #pragma unroll
        for (int i = 0; i < 2; i++) {
            int idx = t + i*512;
            int row = idx >> 3, col4 = (idx & 7) << 2;
            int gk = k0 + col4;
            int r = bm + row;
            float4 v = *reinterpret_cast<const float4*>(&cdata[(size_t)r*256 + 128 + gk]);
            float4 m = *reinterpret_cast<const float4*>(&statc[256 + gk]);
            float4 o = *reinterpret_cast<const float4*>(&cls[(size_t)r*128 + gk]);
            v.x = (v.x - m.x)*scale*0.25f + 0.1f*o.x;
            v.y = (v.y - m.y)*scale*0.25f + 0.1f*o.y;
            v.z = (v.z - m.z)*scale*0.25f + 0.1f*o.z;
            v.w = (v.w - m.w)*scale*0.25f + 0.1f*o.w;
            *reinterpret_cast<float4*>(&cls[(size_t)r*128 + gk]) = v;
            uint2 h4 = pack_h4(v.x, v.y, v.z, v.w);
            *reinterpret_cast<uint2*>(&clscat[(size_t)r*136 + gk]) = h4;
            *reinterpret_cast<uint2*>(&cmin16[(size_t)r*384 + gk]) = h4;
            aReg[i] = v;
        }
    };
    auto cpB = [&](int c){
        const int k0 = c << 5;
        const uint32_t bb = sbase + B0 + (uint32_t)(c % 3)*PLANE;
        int row = t >> 2, q = t & 3;
        int gk = k0 + q*8;
        cp16(bb + (uint32_t)(row*LDH + q*8)*2, Bg + (size_t)row*K + gk, true);
    };
    auto storeA = [&](int s){
        char* sc = smem + A0 + s*PLANE;
        #pragma unroll
        for (int i = 0; i < 2; i++) {
            int idx = t + i*512;
            int row = idx >> 3, col4 = (idx & 7) << 2;
            uint2 pk = pack_h4(aReg[i].x, aReg[i].y, aReg[i].z, aReg[i].w);
            *reinterpret_cast<uint2*>(sc + (row*LDH + col4)*2) = pk;
        }
    };
    auto compute = [&](int c){
        const uint32_t sa = sbase + A0 + (uint32_t)(c & 1)*PLANE;
        const uint32_t sb = sbase + B0 + (uint32_t)(c % 3)*PLANE;
        const int grp = lane >> 3, r = lane & 7;
        #pragma unroll
        for (int ks = 0; ks < 32; ks += 16) {
            uint32_t aH[2][4], bX[4][2];
            #pragma unroll
            for (int mt = 0; mt < 2; mt++) {
                int arow = warp_m*32 + mt*16 + (grp & 1)*8 + r;
                int acol = ks + (grp >> 1)*8;
                ldsm4(aH[mt], sa + (uint32_t)(arow*LDH + acol)*2);
            }
            #pragma unroll
            for (int p = 0; p < 2; p++) {
                int brow = warp_n*32 + p*16 + (grp >> 1)*8 + r;
                int bcol = ks + (grp & 1)*8;
                uint32_t tmp[4];
                ldsm4(tmp, sb + (uint32_t)(brow*LDH + bcol)*2);
                bX[2*p][0]=tmp[0]; bX[2*p][1]=tmp[1]; bX[2*p+1][0]=tmp[2]; bX[2*p+1][1]=tmp[3];
            }
            #pragma unroll
            for (int mt = 0; mt < 2; mt++)
                #pragma unroll
                for (int nt = 0; nt < 4; nt++)
                    mma_f16(acc[mt][nt], aH[mt], bX[nt]);
        }
    };

    loadA(0);
    cpB(0);
    CP_COMMIT();
    storeA(0);
    loadA(1); cpB(1);
    CP_COMMIT();
    CP_WAIT1();
    __syncthreads();

    for (int c = 0; c < nch; c++) {
        compute(c);
        if (c+1 < nch) storeA((c+1) & 1);
        if (c+2 < nch) cpB(c+2);
        CP_COMMIT();
        if (c+2 < nch) loadA(c+2);
        CP_WAIT1();
        __syncthreads();
    }

    float* red = reinterpret_cast<float*>(smem);
    if (t < 128) red[t] = 0.f;
    __syncthreads();
    #pragma unroll
    for (int mt = 0; mt < 2; mt++) {
        int rl = warp_m*32 + mt*16 + (lane >> 2);
        float p0 = 0.f, p1 = 0.f;
        #pragma unroll
        for (int nt = 0; nt < 4; nt++) {
            int col = warp_n*32 + nt*8 + (lane & 3)*2;
            float2 bv = *reinterpret_cast<const float2*>(&bias[col]);
            float wa = __ldg(&w1[col]), wb = __ldg(&w1[col+1]);
            float v0 = fmaxf(acc[mt][nt][0] + bv.x, 0.f);
            float v1 = fmaxf(acc[mt][nt][1] + bv.y, 0.f);
            float v2 = fmaxf(acc[mt][nt][2] + bv.x, 0.f);
            float v3 = fmaxf(acc[mt][nt][3] + bv.y, 0.f);
            p0 += v0*wa + v1*wb;
            p1 += v2*wa + v3*wb;
        }
        atomicAdd(&red[rl], p0);
        atomicAdd(&red[rl+8], p1);
    }
    __syncthreads();
    if (t < 128) {
        float x = red[t] + __ldg(&b1[0]);
        int row = bm + t;
        out[(size_t)round*NC + row] = sigm(x);
        out[(size_t)4*NC + (size_t)round*NC + row] = softplusf(x);
    }
}

// ---------------- setup kernels ----------------
__global__ void k_init(float* p, __half* clscat, __half* varscat, __half* cmin16){
    size_t i = (size_t)blockIdx.x*blockDim.x + threadIdx.x;
    size_t n = (size_t)(NV+NC)*128;
    if (i < n) {
        p[i] = 1.f;
        __half one = __float2half(1.f);
        if (i < (size_t)NV*128) {
            varscat[(i>>7)*136 + (i&127)] = one;
        } else {
            size_t j = i - (size_t)NV*128;
            size_t row = j >> 7, col = j & 127;
            clscat[row*136 + col] = one;
            cmin16[row*384 + col] = one;
        }
    }
    if (i < NL) g_deg[i] = 0;
    if (i < 256) { g_ws[O_STATC + i] = 0.f; g_ws[O_STATV + i] = 0.f; }
}
__global__ void k_count_csr(const int* __restrict__ lit, const int* __restrict__ cls){
    int e = blockIdx.x*blockDim.x + threadIdx.x;
    if (e >= NE) return;
    int l = lit[e];
    int pos = atomicAdd(&g_deg[l], 1);
    if (pos < CSR_W) g_csr[(size_t)l*CSR_W + pos] = cls[e];
}
struct WSrc { const float* w[10]; };
// weights split + degree weights + round-0 noise
__global__ void k_weights_wsplit(WSrc ws, __half* __restrict__ w16,
                                 const float* __restrict__ nv0, const float* __restrict__ nc0,
                                 __half* __restrict__ clscat, __half* __restrict__ varscat){
    const int offs[11] = {0, 17408, 33792, 51200, 67584, 165888, 231424,
                          362496, 428032, 460800, 477184};
    const int Ks[10]  = {132,128,132,128,384,256,512,256,256,128};
    const int KPs[10] = {136,128,136,128,384,256,512,256,256,128};
    const int Ns[10]  = {128,128,128,128,256,256,256,256,128,128};
    int idx = blockIdx.x*blockDim.x + threadIdx.x;
    if (idx < NL) g_ws[O_DEGW + idx] = rsqrtf(fmaxf((float)g_deg[idx], 1.f));
    if (idx < NV) g_ws[O_VDEGW + idx] = 4.f*rsqrtf(fmaxf((float)(g_deg[idx] + g_deg[idx+NV]), 1.f));
    if (idx < NC) {
        float4 z = *reinterpret_cast<const float4*>(&nc0[(size_t)idx*4]);
        uint2 h = pack_h4(z.x, z.y, z.z, z.w);
        *reinterpret_cast<uint4*>(&clscat[(size_t)idx*136 + 128]) = make_uint4(h.x, h.y, 0u, 0u);
    }
    if (idx < NV) {
        float4 z = *reinterpret_cast<const float4*>(&nv0[(size_t)idx*4]);
        uint2 h = pack_h4(z.x, z.y, z.z, z.w);
        *reinterpret_cast<uint4*>(&varscat[(size_t)idx*136 + 128]) = make_uint4(h.x, h.y, 0u, 0u);
    }
    if (idx >= offs[10]) return;
    int seg = 0;
    #pragma unroll
    for (int s = 1; s < 10; s++) if (idx >= offs[s]) seg = s;
    int local = idx - offs[seg];
    int K = Ks[seg], KP = KPs[seg], N = Ns[seg];
    int n = local / KP, k = local % KP;
    float v = (k < K) ? ws.w[seg][(size_t)k*N + n] : 0.f;
    w16[idx] = __float2half_rn(v);
}

// ---------------- per-round small kernels ----------------
__global__ void k_noise16(const float* __restrict__ nv, const float* __restrict__ nc,
                          __half* __restrict__ clscat, __half* __restrict__ varscat){
    int r = blockIdx.x*blockDim.x + threadIdx.x;
    if (r < NC) {
        float4 z = *reinterpret_cast<const float4*>(&nc[(size_t)r*4]);
        uint2 h = pack_h4(z.x, z.y, z.z, z.w);
        *reinterpret_cast<uint4*>(&clscat[(size_t)r*136 + 128]) = make_uint4(h.x, h.y, 0u, 0u);
    }
    if (r < NV) {
        float4 z = *reinterpret_cast<const float4*>(&nv[(size_t)r*4]);
        uint2 h = pack_h4(z.x, z.y, z.z, z.w);
        *reinterpret_cast<uint4*>(&varscat[(size_t)r*136 + 128]) = make_uint4(h.x, h.y, 0u, 0u);
    }
}
__global__ void k_csum_loss(const int* __restrict__ lit, const int* __restrict__ cls,
                            const float* __restrict__ sp, __half* __restrict__ cmin16){
    const int warp = threadIdx.x >> 5, lane = threadIdx.x & 31;
    const int c = blockIdx.x*4 + warp;
    int s01 = 0;
    if (lane < 2) {
        int key = c + lane;
        int lo = 0, hi = NE;
        while (lo < hi) { int mid = (lo+hi) >> 1; if (cls[mid] < key) lo = mid+1; else hi = mid; }
        s01 = lo;
    }
    int s0 = __shfl_sync(0xffffffffu, s01, 0);
    int s1 = __shfl_sync(0xffffffffu, s01, 1);
    int f4 = lane << 2;
    float4 csum = make_float4(0.f,0.f,0.f,0.f);
    for (int e = s0; e < s1; e++) {
        int l = __ldg(&lit[e]);
        float4 v = *reinterpret_cast<const float4*>(&sp[(size_t)l*128 + f4]);
        csum.x += v.x; csum.y += v.y; csum.z += v.z; csum.w += v.w;
    }
    size_t i = (size_t)c*128 + f4;
    float4 cq = *reinterpret_cast<const float4*>(&g_ws[O_CQ + i]);
    float4 lo4, cg4;
    float sg;
    sg = fsigm(cq.x); lo4.x = __expf(-csum.x)*sg; cg4.x = lo4.x*(1.f-sg)*INV_M;
    sg = fsigm(cq.y); lo4.y = __expf(-csum.y)*sg; cg4.y = lo4.y*(1.f-sg)*INV_M;
    sg = fsigm(cq.z); lo4.z = __expf(-csum.z)*sg; cg4.z = lo4.z*(1.f-sg)*INV_M;
    sg = fsigm(cq.w); lo4.w = __expf(-csum.w)*sg; cg4.w = lo4.w*(1.f-sg)*INV_M;
    *reinterpret_cast<float4*>(&g_ws[O_LOSS + i]) = lo4;
    size_t b = (size_t)c*384;
    *reinterpret_cast<uint2*>(&cmin16[b + 128 + f4]) =
        pack_h4(4.f*lo4.x, 4.f*lo4.y, 4.f*lo4.z, 4.f*lo4.w);
    *reinterpret_cast<uint2*>(&cmin16[b + 256 + f4]) =
        pack_h4(cg4.x, cg4.y, cg4.z, cg4.w);
}
__global__ void k_unit_build(const float* __restrict__ loss, const float* __restrict__ cdata,
                             const float* __restrict__ vq, const float* __restrict__ vars,
                             __half* __restrict__ unit16){
    const int warp = threadIdx.x >> 5, lane = threadIdx.x & 31;
    const int v = blockIdx.x*4 + warp;
    const int f4 = lane << 2;
    int dp = g_deg[v];       if (dp > CSR_W) dp = CSR_W;
    int dn = g_deg[v + NV];  if (dn > CSR_W) dn = CSR_W;
    float4 dlp = make_float4(0,0,0,0), vlp = dlp, dln = dlp, vln = dlp;
    for (int j = 0; j < dp; j++) {
        int c = g_csr[(size_t)v*CSR_W + j];
        float4 a = *reinterpret_cast<const float4*>(&loss[(size_t)c*128 + f4]);
        float4 b = *reinterpret_cast<const float4*>(&cdata[(size_t)c*256 + f4]);
        dlp.x+=a.x; dlp.y+=a.y; dlp.z+=a.z; dlp.w+=a.w;
        vlp.x+=b.x; vlp.y+=b.y; vlp.z+=b.z; vlp.w+=b.w;
    }
    for (int j = 0; j < dn; j++) {
        int c = g_csr[(size_t)(v+NV)*CSR_W + j];
        float4 a = *reinterpret_cast<const float4*>(&loss[(size_t)c*128 + f4]);
        float4 b = *reinterpret_cast<const float4*>(&cdata[(size_t)c*256 + f4]);
        dln.x+=a.x; dln.y+=a.y; dln.z+=a.z; dln.w+=a.w;
        vln.x+=b.x; vln.y+=b.y; vln.z+=b.z; vln.w+=b.w;
    }
    float4 q  = *reinterpret_cast<const float4*>(&vq[(size_t)v*128 + f4]);
    float4 va = *reinterpret_cast<const float4*>(&vars[(size_t)v*128 + f4]);
    float wv = g_ws[O_VDEGW + v];
    float wp = g_ws[O_DEGW + v];
    float wn = g_ws[O_DEGW + NV + v];
    float sp;
    float4 g;
    sp = fsigm(q.x); g.x = -INV_M*(dlp.x*sp - dln.x*(1.f-sp))*wv;
    sp = fsigm(q.y); g.y = -INV_M*(dlp.y*sp - dln.y*(1.f-sp))*wv;
    sp = fsigm(q.z); g.z = -INV_M*(dlp.z*sp - dln.z*(1.f-sp))*wv;
    sp = fsigm(q.w); g.w = -INV_M*(dlp.w*sp - dln.w*(1.f-sp))*wv;
    size_t b = (size_t)v*512;
    *reinterpret_cast<uint2*>(&unit16[b + f4])        = pack_h4(g.x, g.y, g.z, g.w);
    *reinterpret_cast<uint2*>(&unit16[b + 128 + f4])  = pack_h4(va.x, va.y, va.z, va.w);
    *reinterpret_cast<uint2*>(&unit16[b + 256 + f4])  = pack_h4(vlp.x*wp, vlp.y*wp, vlp.z*wp, vlp.w*wp);
    *reinterpret_cast<uint2*>(&unit16[b + 384 + f4])  = pack_h4(vln.x*wn, vln.y*wn, vln.z*wn, vln.w*wn);
}
__global__ void k_pn_scale(float n, float* stat){
    int f = threadIdx.x;
    float mean = stat[f] / n;
    float var  = stat[128 + f] / n - mean*mean;
    __shared__ float sh[128];
    sh[f] = var; __syncthreads();
    for (int s = 64; s > 0; s >>= 1) { if (f < s) sh[f] += sh[f+s]; __syncthreads(); }
    stat[256 + f] = mean;
    if (f == 0) stat[384] = rsqrtf(sh[0]*(1.f/128.f) + 1e-6f);
    stat[f] = 0.f;
    stat[128 + f] = 0.f;
}
__global__ void k_pn_apply(const float* __restrict__ x, const float* __restrict__ stat,
                           float* __restrict__ dst, __half* __restrict__ varscat){
    int r = blockIdx.x, f = threadIdx.x;
    float v = (x[(size_t)r*128 + f] - stat[256 + f]) * stat[384];
    size_t i = (size_t)r*128 + f;
    float o = v*0.25f + 0.1f*dst[i];
    dst[i] = o;
    varscat[(size_t)r*136 + f] = __float2half_rn(o);
}

// ---------------- host ----------------
template<int STATS, int CH, int SPE>
static void mmgemm(const __half* A16, const __half* Bg1, const __half* Bg2,
                   const float* b1, const float* b2, void* C,
                   int M, int KP, int Ntot, int relu, int rowSplit,
                   float* statp = nullptr, float* spbuf = nullptr){
    cudaFuncSetAttribute(k_mma64<STATS,CH,SPE>,
                         cudaFuncAttributeMaxDynamicSharedMemorySize, G64_SMEM);
    dim3 grid(Ntot/64, M/128);
    k_mma64<STATS,CH,SPE><<<grid, 256, G64_SMEM>>>(A16, Bg1, Bg2, b1, b2, C,
                                                   KP, Ntot, relu, rowSplit, statp, spbuf);
}

extern "C" void kernel_launch(void* const* d_in, const int* in_sizes, int n_in,
                              void* d_out, int out_size)
{
    (void)in_sizes; (void)n_in; (void)out_size;
    const int*   edge_lit    = (const int*)d_in[0];
    const int*   edge_clause = (const int*)d_in[1];
    const float* noise_v = (const float*)d_in[2];
    const float* noise_c = (const float*)d_in[3];
    const float* vq_w0 = (const float*)d_in[4];  const float* vq_b0 = (const float*)d_in[5];
    const float* vq_w1 = (const float*)d_in[6];  const float* vq_b1 = (const float*)d_in[7];
    const float* cq_w0 = (const float*)d_in[8];  const float* cq_b0 = (const float*)d_in[9];
    const float* cq_w1 = (const float*)d_in[10]; const float* cq_b1 = (const float*)d_in[11];
    const float* cm_w0 = (const float*)d_in[12]; const float* cm_b0 = (const float*)d_in[13];
    const float* cm_w1 = (const float*)d_in[14]; const float* cm_b1 = (const float*)d_in[15];
    const float* ug_w0 = (const float*)d_in[16]; const float* ug_b0 = (const float*)d_in[17];
    const float* ug_w1 = (const float*)d_in[18]; const float* ug_b1 = (const float*)d_in[19];
    const float* ug_w2 = (const float*)d_in[20]; const float* ug_b2 = (const float*)d_in[21];
    const float* co_w0 = (const float*)d_in[22]; const float* co_b0 = (const float*)d_in[23];
    const float* co_w1 = (const float*)d_in[24]; const float* co_b1 = (const float*)d_in[25];
    float* out = (float*)d_out;

    float* ws; cudaGetSymbolAddress((void**)&ws, g_ws);
    __half* w16   = reinterpret_cast<__half*>(ws + O_WT);
    __half* h16   = reinterpret_cast<__half*>(ws + O_H16);
    __half* clscat  = h16 + H_CLSCAT;
    __half* varscat = h16 + H_VARSCAT;
    __half* cmin16  = h16 + H_CMIN;
    __half* unit16  = h16 + H_UNIT;
    __half* h16a    = h16 + H_A;
    __half* h16b    = h16 + H_B;
    float* statc = ws + O_STATC;
    float* statv = ws + O_STATV;
    float* sp    = ws + O_SP;

    cudaFuncSetAttribute(k_co0, cudaFuncAttributeMaxDynamicSharedMemorySize, CO_SMEM);

    {
        size_t n = (size_t)(NV+NC)*128;
        k_init<<<(unsigned)((n+255)/256), 256>>>(ws + O_VARS, clscat, varscat, cmin16);
    }
    k_count_csr<<<(NE+255)/256, 256>>>(edge_lit, edge_clause);
    {
        WSrc s;
        s.w[0]=vq_w0; s.w[1]=vq_w1; s.w[2]=cq_w0; s.w[3]=cq_w1; s.w[4]=cm_w0;
        s.w[5]=cm_w1; s.w[6]=ug_w0; s.w[7]=ug_w1; s.w[8]=ug_w2; s.w[9]=co_w0;
        k_weights_wsplit<<<(OW_END+255)/256, 256>>>(s, w16, noise_v, noise_c,
                                                    clscat, varscat);
    }

    for (int r = 0; r < 4; r++) {
        // merged cq0+vq0: clscat||varscat -> h16a (NC+NV rows, fp16)
        mmgemm<0,1,0>(clscat, w16+OW_cq0, w16+OW_vq0, cq_b0, vq_b0, h16a,
                      NC+NV, 136, 128, 1, NC);
        // merged cq1+vq1: h16a -> CQ||VQ fp32 + softplus table (vq part)
        mmgemm<0,0,1>(h16a, w16+OW_cq1, w16+OW_vq1, cq_b1, vq_b1, ws+O_CQ,
                      NC+NV, 128, 128, 0, NC, nullptr, sp);

        k_csum_loss<<<NC/4, 128>>>(edge_lit, edge_clause, sp, cmin16);

        mmgemm<0,1,0>(cmin16, w16+OW_cm0, w16+OW_cm0, cm_b0, cm_b0, h16a,
                      NC, 384, 256, 1, NC);
        mmgemm<1,0,0>(h16a, w16+OW_cm1, w16+OW_cm1, cm_b1, cm_b1, ws+O_CDATA,
                      NC, 256, 256, 0, NC, statc);

        k_unit_build<<<NV/4, 128>>>(ws+O_LOSS, ws+O_CDATA, ws+O_VQ, ws+O_VARS, unit16);
        k_pn_scale<<<1, 128>>>((float)NC, statc);

        mmgemm<0,1,0>(unit16, w16+OW_ug0, w16+OW_ug0, ug_b0, ug_b0, h16a,
                      NV, 512, 256, 1, NV);
        mmgemm<0,1,0>(h16a, w16+OW_ug1, w16+OW_ug1, ug_b1, ug_b1, h16b,
                      NV, 256, 256, 1, NV);
        mmgemm<2,0,0>(h16b, w16+OW_ug2, w16+OW_ug2, ug_b2, ug_b2, ws+O_VOUT,
                      NV, 256, 128, 0, NV, statv);

        k_pn_scale<<<1, 128>>>((float)NV, statv);
        k_pn_apply<<<NV, 128>>>(ws+O_VOUT, statv, ws+O_VARS, varscat);

        k_co0<<<dim3(1, NC/128), 512, CO_SMEM>>>(ws+O_CDATA, ws+O_CLS, statc,
                                                 w16+OW_co0, co_b0, out, r, co_w1, co_b1,
                                                 clscat, cmin16);

        // noise for next round (cols 128..135 are disjoint from state cols)
        if (r < 3) {
            k_noise16<<<(NC+255)/256, 256>>>(noise_v + (size_t)(r+1)*NV*4,
                                             noise_c + (size_t)(r+1)*NC*4,
                                             clscat, varscat);
        }
    }
}

// round 15
// speedup vs baseline: 3.2865x; 1.0920x over previous
#include <cuda_runtime.h>
#include <cuda_fp16.h>
#include <math.h>
#include <stdint.h>

#define NV 24576
#define NC 98304
#define NE 294912
#define NL 49152
#define INV_M (1.0f/12582912.0f)
#define CSR_W 40

// ---------------- workspace layout (floats) ----------------
static constexpr size_t O_VARS   = 0;
static constexpr size_t O_CLS    = O_VARS  + (size_t)NV*128;
static constexpr size_t O_CQ     = O_CLS   + (size_t)NC*128;   // NC x 128, VQ follows
static constexpr size_t O_VQ     = O_CQ    + (size_t)NC*128;   // NV x 128 (contiguous!)
static constexpr size_t O_LOSS   = O_VQ    + (size_t)NV*128;
static constexpr size_t O_CDATA  = O_LOSS  + (size_t)NC*128;   // NC x 256
static constexpr size_t O_VOUT   = O_CDATA + (size_t)NC*256;   // NV x 128
static constexpr size_t O_SP     = O_VOUT  + (size_t)NV*128;   // NL x 128
static constexpr size_t O_DEGW   = O_SP    + (size_t)NL*128;   // NL
static constexpr size_t O_VDEGW  = O_DEGW  + NL;               // NV
static constexpr size_t O_STATC  = O_VDEGW + NV;               // 512
static constexpr size_t O_STATV  = O_STATC + 512;              // 512
static constexpr size_t O_WT     = O_STATV + 512;              // fp16 weights
static constexpr size_t O_H16    = O_WT + 240000;              // fp16 area base

// half offsets within H16 area
static constexpr size_t H_CLSCAT  = 0;                              // NC x 136
static constexpr size_t H_VARSCAT = H_CLSCAT  + (size_t)NC*136;     // NV x 136 (contiguous!)
static constexpr size_t H_CMIN    = H_VARSCAT + (size_t)NV*136;     // NC x 384
static constexpr size_t H_UNIT    = H_CMIN    + (size_t)NC*384;     // NV x 512
static constexpr size_t H_A       = H_UNIT    + (size_t)NV*512;     // NC x 256 (also (NC+NV)x128)
static constexpr size_t H_B       = H_A       + (size_t)NC*256;     // NV x 256
static constexpr size_t H_END     = H_B       + (size_t)NV*256;
static constexpr size_t WS_TOTAL  = O_H16 + (H_END + 1)/2 + 64;

static constexpr size_t OW_vq0 = 0;
static constexpr size_t OW_vq1 = 17408;
static constexpr size_t OW_cq0 = 33792;
static constexpr size_t OW_cq1 = 51200;
static constexpr size_t OW_cm0 = 67584;
static constexpr size_t OW_cm1 = 165888;
static constexpr size_t OW_ug0 = 231424;
static constexpr size_t OW_ug1 = 362496;
static constexpr size_t OW_ug2 = 428032;
static constexpr size_t OW_co0 = 460800;
static constexpr int    OW_END = 477184;

__device__ float g_ws[WS_TOTAL];
__device__ int   g_deg[NL];
__device__ int   g_csr[(size_t)NL * CSR_W];

// ---------------- PTX helpers ----------------
__device__ __forceinline__ uint32_t smem_u32(const void* p){
    uint32_t a;
    asm("{ .reg .u64 t; cvta.to.shared.u64 t, %1; cvt.u32.u64 %0, t; }" : "=r"(a) : "l"(p));
    return a;
}
__device__ __forceinline__ void ldsm4(uint32_t* r, uint32_t addr){
    asm volatile("ldmatrix.sync.aligned.m8n8.x4.shared.b16 {%0,%1,%2,%3}, [%4];"
        : "=r"(r[0]), "=r"(r[1]), "=r"(r[2]), "=r"(r[3]) : "r"(addr));
}
__device__ __forceinline__ void mma_f16(float* c, const uint32_t* a, const uint32_t* b){
    asm volatile("mma.sync.aligned.m16n8k16.row.col.f32.f16.f16.f32 "
        "{%0,%1,%2,%3}, {%4,%5,%6,%7}, {%8,%9}, {%0,%1,%2,%3};"
        : "+f"(c[0]), "+f"(c[1]), "+f"(c[2]), "+f"(c[3])
        : "r"(a[0]), "r"(a[1]), "r"(a[2]), "r"(a[3]), "r"(b[0]), "r"(b[1]));
}
__device__ __forceinline__ void cp16(uint32_t dst, const void* src, bool pred){
    int sz = pred ? 16 : 0;
    asm volatile("cp.async.cg.shared.global [%0], [%1], 16, %2;"
                 :: "r"(dst), "l"(src), "r"(sz));
}
#define CP_COMMIT() asm volatile("cp.async.commit_group;" ::: "memory")
#define CP_WAIT2()  asm volatile("cp.async.wait_group 2;" ::: "memory")
#define CP_WAIT1()  asm volatile("cp.async.wait_group 1;" ::: "memory")

__device__ __forceinline__ float sigm(float x){ return 1.f/(1.f+expf(-x)); }
__device__ __forceinline__ float softplusf(float x){ return fmaxf(x,0.f)+log1pf(expf(-fabsf(x))); }
__device__ __forceinline__ float fsigm(float x){ return __fdividef(1.f, 1.f+__expf(-x)); }
__device__ __forceinline__ float fsoftplus(float x){ return fmaxf(x,0.f)+__logf(1.f+__expf(-fabsf(x))); }

__device__ __forceinline__ uint2 pack_h4(float a, float b, float c, float d){
    __half2 h0 = __floats2half2_rn(a, b);
    __half2 h1 = __floats2half2_rn(c, d);
    uint2 r;
    r.x = *reinterpret_cast<uint32_t*>(&h0);
    r.y = *reinterpret_cast<uint32_t*>(&h1);
    return r;
}

// ---------------- unified fp16 A16 GEMM, tile 128x128, early-prefetch depth-3 ----------------
// 256 thr, 2 CTAs/SM. Dual weight sets selected by bm >= rowSplit.
static constexpr int G64_SMEM = 81920;   // A 4x10240 + B 4x10240

template<int STATS, int CH, int SPE>
__global__ void __launch_bounds__(256, 2)
k_mma64(const __half* __restrict__ A16,
        const __half* __restrict__ Bg1, const __half* __restrict__ Bg2,
        const float* __restrict__ bias1, const float* __restrict__ bias2,
        void* __restrict__ Cv, int KP, int Ntot, int relu, int rowSplit,
        float* __restrict__ statp, float* __restrict__ spbuf)
{
    extern __shared__ __align__(16) char smem[];
    const uint32_t sbase = smem_u32(smem);
    const int t = threadIdx.x;
    const int lane = t & 31, wid = t >> 5;
    const int warp_m = wid & 3;        // 4 x 32 rows
    const int warp_n = wid >> 2;       // 2 x 64 cols
    const int bm = blockIdx.y * 128, bn = blockIdx.x * 128;
    const bool part2 = (bm >= rowSplit);
    const __half* Bg  = part2 ? Bg2 : Bg1;
    const float* bias = part2 ? bias2 : bias1;

    constexpr int LDH = 40, APLANE = 10240, BPLANE = 10240;
    constexpr int A0 = 0, B0 = 40960;

    float acc[2][8][4];
    #pragma unroll
    for (int i=0;i<2;i++)
        #pragma unroll
        for(int j=0;j<8;j++)
            #pragma unroll
            for(int q=0;q<4;q++) acc[i][j][q]=0.f;

    const int nch = (KP + 31) >> 5;

    auto cpAB = [&](int c){
        const int k0 = c << 5;
        const uint32_t ab = sbase + A0 + (uint32_t)(c & 3)*APLANE;
        const uint32_t bb = sbase + B0 + (uint32_t)(c & 3)*BPLANE;
        #pragma unroll
        for (int i = 0; i < 2; i++) {
            int idx = t + i*256;
            int row = idx >> 2, q = idx & 3;
            int gk = k0 + q*8;
            bool ok = (gk + 8 <= KP);
            size_t aoff = ok ? ((size_t)(bm+row)*KP + gk) : 0;
            size_t boff = ok ? ((size_t)(bn+row)*KP + gk) : 0;
            uint32_t so = (uint32_t)(row*LDH + q*8)*2;
            cp16(ab + so, A16 + aoff, ok);
            cp16(bb + so, Bg + boff, ok);
        }
    };
    auto compute = [&](int c){
        const uint32_t sa = sbase + A0 + (uint32_t)(c & 3)*APLANE;
        const uint32_t sb = sbase + B0 + (uint32_t)(c & 3)*BPLANE;
        const int grp = lane >> 3, r = lane & 7;
        #pragma unroll
        for (int ks = 0; ks < 32; ks += 16) {
            uint32_t aH[2][4], bX[8][2];
            #pragma unroll
            for (int mt = 0; mt < 2; mt++) {
                int arow = warp_m*32 + mt*16 + (grp & 1)*8 + r;
                int acol = ks + (grp >> 1)*8;
                ldsm4(aH[mt], sa + (uint32_t)(arow*LDH + acol)*2);
            }
            #pragma unroll
            for (int p = 0; p < 4; p++) {
                int brow = warp_n*64 + p*16 + (grp >> 1)*8 + r;
                int bcol = ks + (grp & 1)*8;
                uint32_t tmp[4];
                ldsm4(tmp, sb + (uint32_t)(brow*LDH + bcol)*2);
                bX[2*p][0]=tmp[0]; bX[2*p][1]=tmp[1]; bX[2*p+1][0]=tmp[2]; bX[2*p+1][1]=tmp[3];
            }
            #pragma unroll
            for (int mt = 0; mt < 2; mt++)
                #pragma unroll
                for (int nt = 0; nt < 8; nt++)
                    mma_f16(acc[mt][nt], aH[mt], bX[nt]);
        }
    };

    // depth-3 prologue
    cpAB(0);
    CP_COMMIT();
    if (nch > 1) cpAB(1);
    CP_COMMIT();
    if (nch > 2) cpAB(2);
    CP_COMMIT();

    // early-prefetch mainloop
    for (int c = 0; c < nch; c++) {
        CP_WAIT2();
        __syncthreads();
        if (c+3 < nch) cpAB(c+3);
        CP_COMMIT();
        compute(c);
    }

    // ---- C store (+SPE) ----
    #pragma unroll
    for (int mt = 0; mt < 2; mt++) {
        int row0 = bm + warp_m*32 + mt*16 + (lane >> 2);
        #pragma unroll
        for (int nt = 0; nt < 8; nt++) {
            int col = bn + warp_n*64 + nt*8 + (lane & 3)*2;
            float2 bv = *reinterpret_cast<const float2*>(&bias[col - bn]);
            float v0 = acc[mt][nt][0] + bv.x, v1 = acc[mt][nt][1] + bv.y;
            float v2 = acc[mt][nt][2] + bv.x, v3 = acc[mt][nt][3] + bv.y;
            if (relu) { v0=fmaxf(v0,0.f); v1=fmaxf(v1,0.f); v2=fmaxf(v2,0.f); v3=fmaxf(v3,0.f); }
            if (CH) {
                __half* C16 = reinterpret_cast<__half*>(Cv);
                __half2 h01 = __floats2half2_rn(v0, v1);
                __half2 h23 = __floats2half2_rn(v2, v3);
                *reinterpret_cast<__half2*>(&C16[(size_t)row0*Ntot + col])     = h01;
                *reinterpret_cast<__half2*>(&C16[(size_t)(row0+8)*Ntot + col]) = h23;
            } else {
                float* C = reinterpret_cast<float*>(Cv);
                *reinterpret_cast<float2*>(&C[(size_t)row0*Ntot + col])     = make_float2(v0,v1);
                *reinterpret_cast<float2*>(&C[(size_t)(row0+8)*Ntot + col]) = make_float2(v2,v3);
            }
            if (SPE) {
                if (part2) {
                    int rv = row0 - rowSplit;
                    *reinterpret_cast<float2*>(&spbuf[(size_t)rv*128 + col]) =
                        make_float2(fsoftplus(v0), fsoftplus(v1));
                    *reinterpret_cast<float2*>(&spbuf[(size_t)(rv+NV)*128 + col]) =
                        make_float2(fsoftplus(-v0), fsoftplus(-v1));
                    *reinterpret_cast<float2*>(&spbuf[(size_t)(rv+8)*128 + col]) =
                        make_float2(fsoftplus(v2), fsoftplus(v3));
                    *reinterpret_cast<float2*>(&spbuf[(size_t)(rv+8+NV)*128 + col]) =
                        make_float2(fsoftplus(-v2), fsoftplus(-v3));
                }
            }
        }
    }

    if (STATS) {
        // STATS==1: only cols 128..255 of Ntot=256 (bn==128 block)
        // STATS==2: all 128 cols (Ntot=128, bn==0)
        bool active = (STATS == 2) || (bn >= 128);
        if (active) {
            __syncthreads();
            float* red = reinterpret_cast<float*>(smem);
            if (t < 256) red[t] = 0.f;
            __syncthreads();
            #pragma unroll
            for (int nt = 0; nt < 8; nt++) {
                int c0 = warp_n*64 + nt*8 + (lane & 3)*2;
                float b0 = __ldg(&bias[c0]), b1 = __ldg(&bias[c0 + 1]);
                float s0=0.f, s1=0.f, q0=0.f, q1=0.f;
                #pragma unroll
                for (int mt = 0; mt < 2; mt++) {
                    float v0 = acc[mt][nt][0] + b0, v1 = acc[mt][nt][1] + b1;
                    float v2 = acc[mt][nt][2] + b0, v3 = acc[mt][nt][3] + b1;
                    s0 += v0 + v2; s1 += v1 + v3;
                    q0 += v0*v0 + v2*v2; q1 += v1*v1 + v3*v3;
                }
                #pragma unroll
                for (int o = 4; o < 32; o <<= 1) {
                    s0 += __shfl_xor_sync(0xffffffffu, s0, o);
                    s1 += __shfl_xor_sync(0xffffffffu, s1, o);
                    q0 += __shfl_xor_sync(0xffffffffu, q0, o);
                    q1 += __shfl_xor_sync(0xffffffffu, q1, o);
                }
                if (lane < 4) {
                    atomicAdd(&red[c0],        s0);
                    atomicAdd(&red[c0+1],      s1);
                    atomicAdd(&red[128+c0],    q0);
                    atomicAdd(&red[128+c0+1],  q1);
                }
            }
            __syncthreads();
            if (t < 128) {
                atomicAdd(&statp[t],       red[t]);
                atomicAdd(&statp[128 + t], red[128 + t]);
            }
        }
    }
}

// ---------------- co0: pn-apply loader (+fp16 state writes) + logits ----------------
static constexpr int CO_SMEM = 51200;

__global__ void __launch_bounds__(512, 1)
k_co0(const float* __restrict__ cdata, float* __restrict__ cls,
      const float* __restrict__ statc,
      const __half* __restrict__ Bg, const float* __restrict__ bias,
      float* __restrict__ out, int round,
      const float* __restrict__ w1, const float* __restrict__ b1,
      __half* __restrict__ clscat, __half* __restrict__ cmin16)
{
    extern __shared__ __align__(16) char smem[];
    const uint32_t sbase = smem_u32(smem);
    const int t = threadIdx.x;
    const int lane = t & 31, wid = t >> 5;
    const int warp_m = wid & 3, warp_n = wid >> 2;
    const int bm = blockIdx.y * 128;

    constexpr int LDH = 40, PLANE = 10240, A0 = 0, B0 = 20480;
    constexpr int K = 128, nch = 4;

    float acc[2][4][4];
    #pragma unroll
    for (int i=0;i<2;i++)
        #pragma unroll
        for(int j=0;j<4;j++)
            #pragma unroll
            for(int q=0;q<4;q++) acc[i][j][q]=0.f;

    float4 aReg[2];
    const float scale = statc[384];

    auto loadA = [&](int c){
        const int k0 = c << 5;
        #pragma unroll
        for (int i = 0; i < 2; i++) {
            int idx = t + i*512;
            int row = idx >> 3, col4 = (idx & 7) << 2;
            int gk = k0 + col4;
            int r = bm + row;
            float4 v = *reinterpret_cast<const float4*>(&cdata[(size_t)r*256 + 128 + gk]);
            float4 m = *reinterpret_cast<const float4*>(&statc[256 + gk]);
            float4 o = *reinterpret_cast<const float4*>(&cls[(size_t)r*128 + gk]);
            v.x = (v.x - m.x)*scale*0.25f + 0.1f*o.x;
            v.y = (v.y - m.y)*scale*0.25f + 0.1f*o.y;
            v.z = (v.z - m.z)*scale*0.25f + 0.1f*o.z;
            v.w = (v.w - m.w)*scale*0.25f + 0.1f*o.w;
            *reinterpret_cast<float4*>(&cls[(size_t)r*128 + gk]) = v;
            uint2 h4 = pack_h4(v.x, v.y, v.z, v.w);
            *reinterpret_cast<uint2*>(&clscat[(size_t)r*136 + gk]) = h4;
            *reinterpret_cast<uint2*>(&cmin16[(size_t)r*384 + gk]) = h4;
            aReg[i] = v;
        }
    };
    auto cpB = [&](int c){
        const int k0 = c << 5;
        const uint32_t bb = sbase + B0 + (uint32_t)(c % 3)*PLANE;
        int row = t >> 2, q = t & 3;
        int gk = k0 + q*8;
        cp16(bb + (uint32_t)(row*LDH + q*8)*2, Bg + (size_t)row*K + gk, true);
    };
    auto storeA = [&](int s){
        char* sc = smem + A0 + s*PLANE;
        #pragma unroll
        for (int i = 0; i < 2; i++) {
            int idx = t + i*512;
            int row = idx >> 3, col4 = (idx & 7) << 2;
            uint2 pk = pack_h4(aReg[i].x, aReg[i].y, aReg[i].z, aReg[i].w);
            *reinterpret_cast<uint2*>(sc + (row*LDH + col4)*2) = pk;
        }
    };
    auto compute = [&](int c){
        const uint32_t sa = sbase + A0 + (uint32_t)(c & 1)*PLANE;
        const uint32_t sb = sbase + B0 + (uint32_t)(c % 3)*PLANE;
        const int grp = lane >> 3, r = lane & 7;
        #pragma unroll
        for (int ks = 0; ks < 32; ks += 16) {
            uint32_t aH[2][4], bX[4][2];
            #pragma unroll
            for (int mt = 0; mt < 2; mt++) {
                int arow = warp_m*32 + mt*16 + (grp & 1)*8 + r;
                int acol = ks + (grp >> 1)*8;
                ldsm4(aH[mt], sa + (uint32_t)(arow*LDH + acol)*2);
            }
            #pragma unroll
            for (int p = 0; p < 2; p++) {
                int brow = warp_n*32 + p*16 + (grp >> 1)*8 + r;
                int bcol = ks + (grp & 1)*8;
                uint32_t tmp[4];
                ldsm4(tmp, sb + (uint32_t)(brow*LDH + bcol)*2);
                bX[2*p][0]=tmp[0]; bX[2*p][1]=tmp[1]; bX[2*p+1][0]=tmp[2]; bX[2*p+1][1]=tmp[3];
            }
            #pragma unroll
            for (int mt = 0; mt < 2; mt++)
                #pragma unroll
                for (int nt = 0; nt < 4; nt++)
                    mma_f16(acc[mt][nt], aH[mt], bX[nt]);
        }
    };

    loadA(0);
    cpB(0);
    CP_COMMIT();
    storeA(0);
    loadA(1); cpB(1);
    CP_COMMIT();
    CP_WAIT1();
    __syncthreads();

    for (int c = 0; c < nch; c++) {
        compute(c);
        if (c+1 < nch) storeA((c+1) & 1);
        if (c+2 < nch) cpB(c+2);
        CP_COMMIT();
        if (c+2 < nch) loadA(c+2);
        CP_WAIT1();
        __syncthreads();
    }

    float* red = reinterpret_cast<float*>(smem);
    if (t < 128) red[t] = 0.f;
    __syncthreads();
    #pragma unroll
    for (int mt = 0; mt < 2; mt++) {
        int rl = warp_m*32 + mt*16 + (lane >> 2);
        float p0 = 0.f, p1 = 0.f;
        #pragma unroll
        for (int nt = 0; nt < 4; nt++) {
            int col = warp_n*32 + nt*8 + (lane & 3)*2;
            float2 bv = *reinterpret_cast<const float2*>(&bias[col]);
            float wa = __ldg(&w1[col]), wb = __ldg(&w1[col+1]);
            float v0 = fmaxf(acc[mt][nt][0] + bv.x, 0.f);
            float v1 = fmaxf(acc[mt][nt][1] + bv.y, 0.f);
            float v2 = fmaxf(acc[mt][nt][2] + bv.x, 0.f);
            float v3 = fmaxf(acc[mt][nt][3] + bv.y, 0.f);
            p0 += v0*wa + v1*wb;
            p1 += v2*wa + v3*wb;
        }
        atomicAdd(&red[rl], p0);
        atomicAdd(&red[rl+8], p1);
    }
    __syncthreads();
    if (t < 128) {
        float x = red[t] + __ldg(&b1[0]);
        int row = bm + t;
        out[(size_t)round*NC + row] = sigm(x);
        out[(size_t)4*NC + (size_t)round*NC + row] = softplusf(x);
    }
}

// ---------------- setup kernels ----------------
__global__ void k_init(float* p, __half* clscat, __half* varscat, __half* cmin16){
    size_t i = (size_t)blockIdx.x*blockDim.x + threadIdx.x;
    size_t n = (size_t)(NV+NC)*128;
    if (i < n) {
        p[i] = 1.f;
        __half one = __float2half(1.f);
        if (i < (size_t)NV*128) {
            varscat[(i>>7)*136 + (i&127)] = one;
        } else {
            size_t j = i - (size_t)NV*128;
            size_t row = j >> 7, col = j & 127;
            clscat[row*136 + col] = one;
            cmin16[row*384 + col] = one;
        }
    }
    if (i < NL) g_deg[i] = 0;
    if (i < 256) { g_ws[O_STATC + i] = 0.f; g_ws[O_STATV + i] = 0.f; }
}
__global__ void k_count_csr(const int* __restrict__ lit, const int* __restrict__ cls){
    int e = blockIdx.x*blockDim.x + threadIdx.x;
    if (e >= NE) return;
    int l = lit[e];
    int pos = atomicAdd(&g_deg[l], 1);
    if (pos < CSR_W) g_csr[(size_t)l*CSR_W + pos] = cls[e];
}
struct WSrc { const float* w[10]; };
__global__ void k_weights_wsplit(WSrc ws, __half* __restrict__ w16,
                                 const float* __restrict__ nv0, const float* __restrict__ nc0,
                                 __half* __restrict__ clscat, __half* __restrict__ varscat){
    const int offs[11] = {0, 17408, 33792, 51200, 67584, 165888, 231424,
                          362496, 428032, 460800, 477184};
    const int Ks[10]  = {132,128,132,128,384,256,512,256,256,128};
    const int KPs[10] = {136,128,136,128,384,256,512,256,256,128};
    const int Ns[10]  = {128,128,128,128,256,256,256,256,128,128};
    int idx = blockIdx.x*blockDim.x + threadIdx.x;
    if (idx < NL) g_ws[O_DEGW + idx] = rsqrtf(fmaxf((float)g_deg[idx], 1.f));
    if (idx < NV) g_ws[O_VDEGW + idx] = 4.f*rsqrtf(fmaxf((float)(g_deg[idx] + g_deg[idx+NV]), 1.f));
    if (idx < NC) {
        float4 z = *reinterpret_cast<const float4*>(&nc0[(size_t)idx*4]);
        uint2 h = pack_h4(z.x, z.y, z.z, z.w);
        *reinterpret_cast<uint4*>(&clscat[(size_t)idx*136 + 128]) = make_uint4(h.x, h.y, 0u, 0u);
    }
    if (idx < NV) {
        float4 z = *reinterpret_cast<const float4*>(&nv0[(size_t)idx*4]);
        uint2 h = pack_h4(z.x, z.y, z.z, z.w);
        *reinterpret_cast<uint4*>(&varscat[(size_t)idx*136 + 128]) = make_uint4(h.x, h.y, 0u, 0u);
    }
    if (idx >= offs[10]) return;
    int seg = 0;
    #pragma unroll
    for (int s = 1; s < 10; s++) if (idx >= offs[s]) seg = s;
    int local = idx - offs[seg];
    int K = Ks[seg], KP = KPs[seg], N = Ns[seg];
    int n = local / KP, k = local % KP;
    float v = (k < K) ? ws.w[seg][(size_t)k*N + n] : 0.f;
    w16[idx] = __float2half_rn(v);
}

// ---------------- per-round small kernels ----------------
__global__ void k_noise16(const float* __restrict__ nv, const float* __restrict__ nc,
                          __half* __restrict__ clscat, __half* __restrict__ varscat){
    int r = blockIdx.x*blockDim.x + threadIdx.x;
    if (r < NC) {
        float4 z = *reinterpret_cast<const float4*>(&nc[(size_t)r*4]);
        uint2 h = pack_h4(z.x, z.y, z.z, z.w);
        *reinterpret_cast<uint4*>(&clscat[(size_t)r*136 + 128]) = make_uint4(h.x, h.y, 0u, 0u);
    }
    if (r < NV) {
        float4 z = *reinterpret_cast<const float4*>(&nv[(size_t)r*4]);
        uint2 h = pack_h4(z.x, z.y, z.z, z.w);
        *reinterpret_cast<uint4*>(&varscat[(size_t)r*136 + 128]) = make_uint4(h.x, h.y, 0u, 0u);
    }
}
__global__ void k_csum_loss(const int* __restrict__ lit, const int* __restrict__ cls,
                            const float* __restrict__ sp, __half* __restrict__ cmin16){
    const int warp = threadIdx.x >> 5, lane = threadIdx.x & 31;
    const int c = blockIdx.x*4 + warp;
    int s01 = 0;
    if (lane < 2) {
        int key = c + lane;
        int lo = 0, hi = NE;
        while (lo < hi) { int mid = (lo+hi) >> 1; if (cls[mid] < key) lo = mid+1; else hi = mid; }
        s01 = lo;
    }
    int s0 = __shfl_sync(0xffffffffu, s01, 0);
    int s1 = __shfl_sync(0xffffffffu, s01, 1);
    int f4 = lane << 2;
    float4 csum = make_float4(0.f,0.f,0.f,0.f);
    for (int e = s0; e < s1; e++) {
        int l = __ldg(&lit[e]);
        float4 v = *reinterpret_cast<const float4*>(&sp[(size_t)l*128 + f4]);
        csum.x += v.x; csum.y += v.y; csum.z += v.z; csum.w += v.w;
    }
    size_t i = (size_t)c*128 + f4;
    float4 cq = *reinterpret_cast<const float4*>(&g_ws[O_CQ + i]);
    float4 lo4, cg4;
    float sg;
    sg = fsigm(cq.x); lo4.x = __expf(-csum.x)*sg; cg4.x = lo4.x*(1.f-sg)*INV_M;
    sg = fsigm(cq.y); lo4.y = __expf(-csum.y)*sg; cg4.y = lo4.y*(1.f-sg)*INV_M;
    sg = fsigm(cq.z); lo4.z = __expf(-csum.z)*sg; cg4.z = lo4.z*(1.f-sg)*INV_M;
    sg = fsigm(cq.w); lo4.w = __expf(-csum.w)*sg; cg4.w = lo4.w*(1.f-sg)*INV_M;
    *reinterpret_cast<float4*>(&g_ws[O_LOSS + i]) = lo4;
    size_t b = (size_t)c*384;
    *reinterpret_cast<uint2*>(&cmin16[b + 128 + f4]) =
        pack_h4(4.f*lo4.x, 4.f*lo4.y, 4.f*lo4.z, 4.f*lo4.w);
    *reinterpret_cast<uint2*>(&cmin16[b + 256 + f4]) =
        pack_h4(cg4.x, cg4.y, cg4.z, cg4.w);
}
__global__ void k_unit_build(const float* __restrict__ loss, const float* __restrict__ cdata,
                             const float* __restrict__ vq, const float* __restrict__ vars,
                             __half* __restrict__ unit16){
    const int warp = threadIdx.x >> 5, lane = threadIdx.x & 31;
    const int v = blockIdx.x*4 + warp;
    const int f4 = lane << 2;
    int dp = g_deg[v];       if (dp > CSR_W) dp = CSR_W;
    int dn = g_deg[v + NV];  if (dn > CSR_W) dn = CSR_W;
    float4 dlp = make_float4(0,0,0,0), vlp = dlp, dln = dlp, vln = dlp;
    for (int j = 0; j < dp; j++) {
        int c = g_csr[(size_t)v*CSR_W + j];
        float4 a = *reinterpret_cast<const float4*>(&loss[(size_t)c*128 + f4]);
        float4 b = *reinterpret_cast<const float4*>(&cdata[(size_t)c*256 + f4]);
        dlp.x+=a.x; dlp.y+=a.y; dlp.z+=a.z; dlp.w+=a.w;
        vlp.x+=b.x; vlp.y+=b.y; vlp.z+=b.z; vlp.w+=b.w;
    }
    for (int j = 0; j < dn; j++) {
        int c = g_csr[(size_t)(v+NV)*CSR_W + j];
        float4 a = *reinterpret_cast<const float4*>(&loss[(size_t)c*128 + f4]);
        float4 b = *reinterpret_cast<const float4*>(&cdata[(size_t)c*256 + f4]);
        dln.x+=a.x; dln.y+=a.y; dln.z+=a.z; dln.w+=a.w;
        vln.x+=b.x; vln.y+=b.y; vln.z+=b.z; vln.w+=b.w;
    }
    float4 q  = *reinterpret_cast<const float4*>(&vq[(size_t)v*128 + f4]);
    float4 va = *reinterpret_cast<const float4*>(&vars[(size_t)v*128 + f4]);
    float wv = g_ws[O_VDEGW + v];
    float wp = g_ws[O_DEGW + v];
    float wn = g_ws[O_DEGW + NV + v];
    float sp;
    float4 g;
    sp = fsigm(q.x); g.x = -INV_M*(dlp.x*sp - dln.x*(1.f-sp))*wv;
    sp = fsigm(q.y); g.y = -INV_M*(dlp.y*sp - dln.y*(1.f-sp))*wv;
    sp = fsigm(q.z); g.z = -INV_M*(dlp.z*sp - dln.z*(1.f-sp))*wv;
    sp = fsigm(q.w); g.w = -INV_M*(dlp.w*sp - dln.w*(1.f-sp))*wv;
    size_t b = (size_t)v*512;
    *reinterpret_cast<uint2*>(&unit16[b + f4])        = pack_h4(g.x, g.y, g.z, g.w);
    *reinterpret_cast<uint2*>(&unit16[b + 128 + f4])  = pack_h4(va.x, va.y, va.z, va.w);
    *reinterpret_cast<uint2*>(&unit16[b + 256 + f4])  = pack_h4(vlp.x*wp, vlp.y*wp, vlp.z*wp, vlp.w*wp);
    *reinterpret_cast<uint2*>(&unit16[b + 384 + f4])  = pack_h4(vln.x*wn, vln.y*wn, vln.z*wn, vln.w*wn);
}
__global__ void k_pn_scale(float n, float* stat){
    int f = threadIdx.x;
    float mean = stat[f] / n;
    float var  = stat[128 + f] / n - mean*mean;
    __shared__ float sh[128];
    sh[f] = var; __syncthreads();
    for (int s = 64; s > 0; s >>= 1) { if (f < s) sh[f] += sh[f+s]; __syncthreads(); }
    stat[256 + f] = mean;
    if (f == 0) stat[384] = rsqrtf(sh[0]*(1.f/128.f) + 1e-6f);
    stat[f] = 0.f;
    stat[128 + f] = 0.f;
}
__global__ void k_pn_apply(const float* __restrict__ x, const float* __restrict__ stat,
                           float* __restrict__ dst, __half* __restrict__ varscat){
    int r = blockIdx.x, f = threadIdx.x;
    float v = (x[(size_t)r*128 + f] - stat[256 + f]) * stat[384];
    size_t i = (size_t)r*128 + f;
    float o = v*0.25f + 0.1f*dst[i];
    dst[i] = o;
    varscat[(size_t)r*136 + f] = __float2half_rn(o);
}

// ---------------- host ----------------
template<int STATS, int CH, int SPE>
static void mmgemm(const __half* A16, const __half* Bg1, const __half* Bg2,
                   const float* b1, const float* b2, void* C,
                   int M, int KP, int Ntot, int relu, int rowSplit,
                   float* statp = nullptr, float* spbuf = nullptr){
    cudaFuncSetAttribute(k_mma64<STATS,CH,SPE>,
                         cudaFuncAttributeMaxDynamicSharedMemorySize, G64_SMEM);
    dim3 grid(Ntot/128, M/128);
    k_mma64<STATS,CH,SPE><<<grid, 256, G64_SMEM>>>(A16, Bg1, Bg2, b1, b2, C,
                                                   KP, Ntot, relu, rowSplit, statp, spbuf);
}

extern "C" void kernel_launch(void* const* d_in, const int* in_sizes, int n_in,
                              void* d_out, int out_size)
{
    (void)in_sizes; (void)n_in; (void)out_size;
    const int*   edge_lit    = (const int*)d_in[0];
    const int*   edge_clause = (const int*)d_in[1];
    const float* noise_v = (const float*)d_in[2];
    const float* noise_c = (const float*)d_in[3];
    const float* vq_w0 = (const float*)d_in[4];  const float* vq_b0 = (const float*)d_in[5];
    const float* vq_w1 = (const float*)d_in[6];  const float* vq_b1 = (const float*)d_in[7];
    const float* cq_w0 = (const float*)d_in[8];  const float* cq_b0 = (const float*)d_in[9];
    const float* cq_w1 = (const float*)d_in[10]; const float* cq_b1 = (const float*)d_in[11];
    const float* cm_w0 = (const float*)d_in[12]; const float* cm_b0 = (const float*)d_in[13];
    const float* cm_w1 = (const float*)d_in[14]; const float* cm_b1 = (const float*)d_in[15];
    const float* ug_w0 = (const float*)d_in[16]; const float* ug_b0 = (const float*)d_in[17];
    const float* ug_w1 = (const float*)d_in[18]; const float* ug_b1 = (const float*)d_in[19];
    const float* ug_w2 = (const float*)d_in[20]; const float* ug_b2 = (const float*)d_in[21];
    const float* co_w0 = (const float*)d_in[22]; const float* co_b0 = (const float*)d_in[23];
    const float* co_w1 = (const float*)d_in[24]; const float* co_b1 = (const float*)d_in[25];
    float* out = (float*)d_out;

    float* ws; cudaGetSymbolAddress((void**)&ws, g_ws);
    __half* w16   = reinterpret_cast<__half*>(ws + O_WT);
    __half* h16   = reinterpret_cast<__half*>(ws + O_H16);
    __half* clscat  = h16 + H_CLSCAT;
    __half* varscat = h16 + H_VARSCAT;
    __half* cmin16  = h16 + H_CMIN;
    __half* unit16  = h16 + H_UNIT;
    __half* h16a    = h16 + H_A;
    __half* h16b    = h16 + H_B;
    float* statc = ws + O_STATC;
    float* statv = ws + O_STATV;
    float* sp    = ws + O_SP;

    cudaFuncSetAttribute(k_co0, cudaFuncAttributeMaxDynamicSharedMemorySize, CO_SMEM);

    {
        size_t n = (size_t)(NV+NC)*128;
        k_init<<<(unsigned)((n+255)/256), 256>>>(ws + O_VARS, clscat, varscat, cmin16);
    }
    k_count_csr<<<(NE+255)/256, 256>>>(edge_lit, edge_clause);
    {
        WSrc s;
        s.w[0]=vq_w0; s.w[1]=vq_w1; s.w[2]=cq_w0; s.w[3]=cq_w1; s.w[4]=cm_w0;
        s.w[5]=cm_w1; s.w[6]=ug_w0; s.w[7]=ug_w1; s.w[8]=ug_w2; s.w[9]=co_w0;
        k_weights_wsplit<<<(OW_END+255)/256, 256>>>(s, w16, noise_v, noise_c,
                                                    clscat, varscat);
    }

    for (int r = 0; r < 4; r++) {
        // merged cq0+vq0: clscat||varscat -> h16a (NC+NV rows, fp16)
        mmgemm<0,1,0>(clscat, w16+OW_cq0, w16+OW_vq0, cq_b0, vq_b0, h16a,
                      NC+NV, 136, 128, 1, NC);
        // merged cq1+vq1: h16a -> CQ||VQ fp32 + softplus table (vq part)
        mmgemm<0,0,1>(h16a, w16+OW_cq1, w16+OW_vq1, cq_b1, vq_b1, ws+O_CQ,
                      NC+NV, 128, 128, 0, NC, nullptr, sp);

        k_csum_loss<<<NC/4, 128>>>(edge_lit, edge_clause, sp, cmin16);

        mmgemm<0,1,0>(cmin16, w16+OW_cm0, w16+OW_cm0, cm_b0, cm_b0, h16a,
                      NC, 384, 256, 1, NC);
        mmgemm<1,0,0>(h16a, w16+OW_cm1, w16+OW_cm1, cm_b1, cm_b1, ws+O_CDATA,
                      NC, 256, 256, 0, NC, statc);

        k_unit_build<<<NV/4, 128>>>(ws+O_LOSS, ws+O_CDATA, ws+O_VQ, ws+O_VARS, unit16);
        k_pn_scale<<<1, 128>>>((float)NC, statc);

        mmgemm<0,1,0>(unit16, w16+OW_ug0, w16+OW_ug0, ug_b0, ug_b0, h16a,
                      NV, 512, 256, 1, NV);
        mmgemm<0,1,0>(h16a, w16+OW_ug1, w16+OW_ug1, ug_b1, ug_b1, h16b,
                      NV, 256, 256, 1, NV);
        mmgemm<2,0,0>(h16b, w16+OW_ug2, w16+OW_ug2, ug_b2, ug_b2, ws+O_VOUT,
                      NV, 256, 128, 0, NV, statv);

        k_pn_scale<<<1, 128>>>((float)NV, statv);
        k_pn_apply<<<NV, 128>>>(ws+O_VOUT, statv, ws+O_VARS, varscat);

        k_co0<<<dim3(1, NC/128), 512, CO_SMEM>>>(ws+O_CDATA, ws+O_CLS, statc,
                                                 w16+OW_co0, co_b0, out, r, co_w1, co_b1,
                                                 clscat, cmin16);

        if (r < 3) {
            k_noise16<<<(NC+255)/256, 256>>>(noise_v + (size_t)(r+1)*NV*4,
                                             noise_c + (size_t)(r+1)*NC*4,
                                             clscat, varscat);
        }
    }
}